// round 9
// baseline (speedup 1.0000x reference)
#include <cuda_runtime.h>
#include <cuda_bf16.h>
#include <cstdint>

#define D_MODEL 1024
#define NHEAD   16
#define DK      64
#define BATCH   2
#define SEQ     2048
#define MTOT    (BATCH * SEQ)   // 4096
#define BH      (BATCH * NHEAD) // 32

#define NEG_INF __int_as_float(0xff800000)

// ---------------------------------------------------------------------------
// Scratch (__device__ globals: allocations are forbidden)
// ---------------------------------------------------------------------------
__device__ __nv_bfloat16 g_x_hi[MTOT * D_MODEL];
__device__ __nv_bfloat16 g_x_lo[MTOT * D_MODEL];
__device__ __nv_bfloat16 g_o_hi[MTOT * D_MODEL];
__device__ __nv_bfloat16 g_o_lo[MTOT * D_MODEL];
__device__ __nv_bfloat16 g_w_hi[4][D_MODEL * D_MODEL];
__device__ __nv_bfloat16 g_w_lo[4][D_MODEL * D_MODEL];

// head-major bf16 hi/lo for attention
__device__ __nv_bfloat16 g_qh[BH * SEQ * DK];
__device__ __nv_bfloat16 g_ql[BH * SEQ * DK];
__device__ __nv_bfloat16 g_kh[BH * SEQ * DK];
__device__ __nv_bfloat16 g_kl[BH * SEQ * DK];
__device__ __nv_bfloat16 g_vth[BH * DK * SEQ];  // transposed: [bh][d][s]
__device__ __nv_bfloat16 g_vtl[BH * DK * SEQ];

// ---------------------------------------------------------------------------
// Base-ISA helpers (NO tcgen05 — harness ptxas targets plain sm_103)
// ---------------------------------------------------------------------------
__device__ __forceinline__ uint32_t smem_to_u32(const void* p) {
    uint32_t a;
    asm("{ .reg .u64 t; cvta.to.shared.u64 t, %1; cvt.u32.u64 %0, t; }" : "=r"(a) : "l"(p));
    return a;
}
#define SW128(o) ((o) ^ (((o) >> 3) & 0x70))

#define CP_ASYNC16(dst, src) \
    asm volatile("cp.async.cg.shared.global [%0], [%1], 16;" :: "r"(dst), "l"(src))
#define CP_COMMIT() asm volatile("cp.async.commit_group;" ::: "memory")
#define CP_WAIT(n)  asm volatile("cp.async.wait_group %0;" :: "n"(n) : "memory")

#define LDSM_X4(r0, r1, r2, r3, addr) \
    asm volatile("ldmatrix.sync.aligned.m8n8.x4.shared.b16 {%0,%1,%2,%3}, [%4];" \
                 : "=r"(r0), "=r"(r1), "=r"(r2), "=r"(r3) : "r"(addr))

#define MMA_BF16(c, a, b) \
    asm volatile("mma.sync.aligned.m16n8k16.row.col.f32.bf16.bf16.f32 " \
                 "{%0,%1,%2,%3}, {%4,%5,%6,%7}, {%8,%9}, {%0,%1,%2,%3};" \
                 : "+f"((c)[0]), "+f"((c)[1]), "+f"((c)[2]), "+f"((c)[3]) \
                 : "r"((a)[0]), "r"((a)[1]), "r"((a)[2]), "r"((a)[3]), \
                   "r"((b)[0]), "r"((b)[1]))

__device__ __forceinline__ void split2(float x, float y, uint32_t& hi, uint32_t& lo) {
    __nv_bfloat16 hx = __float2bfloat16(x), hy = __float2bfloat16(y);
    __nv_bfloat16 lx = __float2bfloat16(x - __bfloat162float(hx));
    __nv_bfloat16 ly = __float2bfloat16(y - __bfloat162float(hy));
    __nv_bfloat162 th(hx, hy), tl(lx, ly);
    hi = *(uint32_t*)&th;
    lo = *(uint32_t*)&tl;
}

// ---------------------------------------------------------------------------
// fp32 -> bf16 hi/lo split, one launch for x (4 slices) + 4 weights.
// grid = (D_MODEL*D_MODEL/4/256, 8); y<4 -> weight y, y>=4 -> x slice y-4
// ---------------------------------------------------------------------------
__global__ __launch_bounds__(256)
void cvt_all(const float* __restrict__ x,
             const float* __restrict__ w0, const float* __restrict__ w1,
             const float* __restrict__ w2, const float* __restrict__ w3,
             __nv_bfloat16* __restrict__ xhi, __nv_bfloat16* __restrict__ xlo,
             __nv_bfloat16* __restrict__ whi, __nv_bfloat16* __restrict__ wlo)
{
    const int y = blockIdx.y;
    const size_t WSZ4 = (size_t)D_MODEL * D_MODEL / 4;
    const float* src;
    __nv_bfloat16 *hi, *lo;
    if (y < 4) {
        src = (y == 0) ? w0 : (y == 1) ? w1 : (y == 2) ? w2 : w3;
        hi = whi + (size_t)y * D_MODEL * D_MODEL;
        lo = wlo + (size_t)y * D_MODEL * D_MODEL;
    } else {
        src = x + (size_t)(y - 4) * WSZ4 * 4;
        hi = xhi + (size_t)(y - 4) * WSZ4 * 4;
        lo = xlo + (size_t)(y - 4) * WSZ4 * 4;
    }
    int i = blockIdx.x * 256 + threadIdx.x;
    float4 v = ((const float4*)src)[i];
    uint32_t h0, l0, h1, l1;
    split2(v.x, v.y, h0, l0);
    split2(v.z, v.w, h1, l1);
    ((uint32_t*)hi)[2 * i] = h0;     ((uint32_t*)hi)[2 * i + 1] = h1;
    ((uint32_t*)lo)[2 * i] = l0;     ((uint32_t*)lo)[2 * i + 1] = l1;
}

// ---------------------------------------------------------------------------
// GEMM core: 128x128 CTA tile, 512 threads / 16 warps, warp tile 32x32,
// KC=64, 3-pass bf16 split, cp.async double buffering.
// ---------------------------------------------------------------------------
#define KC        64
#define NCHUNK    (D_MODEL / KC)      // 16
#define TILE_B    16384
#define BUF_B     (4 * TILE_B)
#define GEMM_SMEM (2 * BUF_B)         // 131072
#define GNT       512

__device__ __forceinline__ void cp_tile(uint32_t dst_base, const __nv_bfloat16* src, int tid)
{
#pragma unroll
    for (int u = tid; u < 1024; u += GNT) {
        int row = u >> 3, c = u & 7;
        uint32_t off = row * 128 + c * 16;
        CP_ASYNC16(dst_base + SW128(off), src + (size_t)row * D_MODEL + c * 8);
    }
}

// mainloop: leaves per-warp 32x32 result in acc[2][4][4]
__device__ __forceinline__ void gemm_mainloop(
    uint32_t sbase, int tid, int lane, int m0, int n0,
    const __nv_bfloat16* pAh, const __nv_bfloat16* pAl,
    const __nv_bfloat16* pBh, const __nv_bfloat16* pBl,
    float acc[2][4][4])
{
#pragma unroll
    for (int i = 0; i < 2; i++)
#pragma unroll
        for (int j = 0; j < 4; j++)
#pragma unroll
            for (int r = 0; r < 4; r++) acc[i][j][r] = 0.f;

    const int ra = lane & 15;
    const int ca = lane >> 4;
    const int qb = lane >> 3;
    const int l7 = lane & 7;

    cp_tile(sbase + 0 * TILE_B, pAh, tid);
    cp_tile(sbase + 1 * TILE_B, pAl, tid);
    cp_tile(sbase + 2 * TILE_B, pBh, tid);
    cp_tile(sbase + 3 * TILE_B, pBl, tid);
    CP_COMMIT();

    for (int ch = 0; ch < NCHUNK; ch++) {
        const int buf = ch & 1;
        if (ch + 1 < NCHUNK) {
            const uint32_t nb = sbase + (buf ^ 1) * BUF_B;
            const int kc = (ch + 1) * KC;
            cp_tile(nb + 0 * TILE_B, pAh + kc, tid);
            cp_tile(nb + 1 * TILE_B, pAl + kc, tid);
            cp_tile(nb + 2 * TILE_B, pBh + kc, tid);
            cp_tile(nb + 3 * TILE_B, pBl + kc, tid);
            CP_COMMIT();
            CP_WAIT(1);
        } else {
            CP_WAIT(0);
        }
        __syncthreads();

        const uint32_t aH = sbase + buf * BUF_B + 0 * TILE_B;
        const uint32_t aL = sbase + buf * BUF_B + 1 * TILE_B;
        const uint32_t bH = sbase + buf * BUF_B + 2 * TILE_B;
        const uint32_t bL = sbase + buf * BUF_B + 3 * TILE_B;

#pragma unroll
        for (int ks = 0; ks < 4; ks++) {
            uint32_t ah[8], al[8];
#pragma unroll
            for (int i = 0; i < 2; i++) {
                uint32_t off = (uint32_t)(m0 + i * 16 + ra) * 128 + (ks * 2 + ca) * 16;
                uint32_t sw = SW128(off);
                LDSM_X4(ah[4 * i], ah[4 * i + 1], ah[4 * i + 2], ah[4 * i + 3], aH + sw);
                LDSM_X4(al[4 * i], al[4 * i + 1], al[4 * i + 2], al[4 * i + 3], aL + sw);
            }
            uint32_t bh[8], bl[8];
#pragma unroll
            for (int jj = 0; jj < 2; jj++) {
                uint32_t off = (uint32_t)(n0 + (jj * 2 + (qb >> 1)) * 8 + l7) * 128
                             + (ks * 2 + (qb & 1)) * 16;
                uint32_t sw = SW128(off);
                LDSM_X4(bh[4 * jj], bh[4 * jj + 1], bh[4 * jj + 2], bh[4 * jj + 3], bH + sw);
                LDSM_X4(bl[4 * jj], bl[4 * jj + 1], bl[4 * jj + 2], bl[4 * jj + 3], bL + sw);
            }
#pragma unroll
            for (int i = 0; i < 2; i++)
#pragma unroll
                for (int j = 0; j < 4; j++) {
                    MMA_BF16(acc[i][j], &ah[4 * i], &bh[2 * j]);
                    MMA_BF16(acc[i][j], &ah[4 * i], &bl[2 * j]);
                    MMA_BF16(acc[i][j], &al[4 * i], &bh[2 * j]);
                }
        }
        __syncthreads();
    }
}

// ---------------------------------------------------------------------------
// QKV projections, one launch (grid.z = 0:Q, 1:K, 2:V).
// ---------------------------------------------------------------------------
__global__ __launch_bounds__(GNT, 1)
void gemm_qkv(const __nv_bfloat16* __restrict__ Ahi, const __nv_bfloat16* __restrict__ Alo,
              const __nv_bfloat16* __restrict__ Whi, const __nv_bfloat16* __restrict__ Wlo,
              __nv_bfloat16* __restrict__ qh, __nv_bfloat16* __restrict__ ql,
              __nv_bfloat16* __restrict__ kh, __nv_bfloat16* __restrict__ kl,
              __nv_bfloat16* __restrict__ vth, __nv_bfloat16* __restrict__ vtl)
{
    extern __shared__ char smem[];
    const uint32_t sbase = smem_to_u32(smem);
    const int tid = threadIdx.x;
    const int wid = tid >> 5, lane = tid & 31;
    const int bm = blockIdx.y * 128;
    const int bn = blockIdx.x * 128;
    const int z  = blockIdx.z;
    const int m0 = (wid & 3) * 32;
    const int n0 = (wid >> 2) * 32;

    float acc[2][4][4];
    gemm_mainloop(sbase, tid, lane, m0, n0,
                  Ahi + (size_t)bm * D_MODEL,
                  Alo + (size_t)bm * D_MODEL,
                  Whi + (size_t)z * D_MODEL * D_MODEL + (size_t)bn * D_MODEL,
                  Wlo + (size_t)z * D_MODEL * D_MODEL + (size_t)bn * D_MODEL,
                  acc);

    const int g = lane >> 2, t = lane & 3;

    if (z == 2) {
        // V: transposed scattered bf16 writes
#pragma unroll
        for (int i = 0; i < 2; i++) {
#pragma unroll
            for (int j = 0; j < 4; j++) {
                const int c  = bn + n0 + j * 8 + 2 * t;
                const int hh = c >> 6, d0 = c & 63;
#pragma unroll
                for (int rr = 0; rr < 4; rr++) {
                    const int row = bm + m0 + i * 16 + g + ((rr >> 1) * 8);
                    const int b = row >> 11, s = row & (SEQ - 1);
                    const int d = d0 + (rr & 1);
                    float v = acc[i][j][rr];
                    __nv_bfloat16 hv = __float2bfloat16(v);
                    __nv_bfloat16 lv = __float2bfloat16(v - __bfloat162float(hv));
                    const size_t dst = ((size_t)((b * NHEAD + hh) * DK + d)) * SEQ + s;
                    vth[dst] = hv;
                    vtl[dst] = lv;
                }
            }
        }
    } else {
        __nv_bfloat16* Hi = (z == 0) ? qh : kh;
        __nv_bfloat16* Lo = (z == 0) ? ql : kl;
        const float sc = (z == 0) ? 0.125f : 1.0f;
#pragma unroll
        for (int i = 0; i < 2; i++) {
#pragma unroll
            for (int j = 0; j < 4; j++) {
                const int c  = bn + n0 + j * 8 + 2 * t;
                const int hh = c >> 6, d = c & 63;
                const int row0 = bm + m0 + i * 16 + g;
                uint32_t hv, lv;
                {
                    const int b = row0 >> 11, s = row0 & (SEQ - 1);
                    split2(acc[i][j][0] * sc, acc[i][j][1] * sc, hv, lv);
                    const size_t dst = ((size_t)((b * NHEAD + hh) * SEQ + s)) * DK + d;
                    *(uint32_t*)(Hi + dst) = hv;
                    *(uint32_t*)(Lo + dst) = lv;
                }
                {
                    const int row1 = row0 + 8;
                    const int b = row1 >> 11, s = row1 & (SEQ - 1);
                    split2(acc[i][j][2] * sc, acc[i][j][3] * sc, hv, lv);
                    const size_t dst = ((size_t)((b * NHEAD + hh) * SEQ + s)) * DK + d;
                    *(uint32_t*)(Hi + dst) = hv;
                    *(uint32_t*)(Lo + dst) = lv;
                }
            }
        }
    }
}

// ---------------------------------------------------------------------------
// Output projection GEMM (fp32 result to d_out)
// ---------------------------------------------------------------------------
__global__ __launch_bounds__(GNT, 1)
void gemm_mma(const __nv_bfloat16* __restrict__ Ahi, const __nv_bfloat16* __restrict__ Alo,
              const __nv_bfloat16* __restrict__ Bhi, const __nv_bfloat16* __restrict__ Blo,
              float* __restrict__ C)
{
    extern __shared__ char smem[];
    const uint32_t sbase = smem_to_u32(smem);
    const int tid = threadIdx.x;
    const int wid = tid >> 5, lane = tid & 31;
    const int bm = blockIdx.y * 128;
    const int bn = blockIdx.x * 128;
    const int m0 = (wid & 3) * 32;
    const int n0 = (wid >> 2) * 32;

    float acc[2][4][4];
    gemm_mainloop(sbase, tid, lane, m0, n0,
                  Ahi + (size_t)bm * D_MODEL,
                  Alo + (size_t)bm * D_MODEL,
                  Bhi + (size_t)bn * D_MODEL,
                  Blo + (size_t)bn * D_MODEL,
                  acc);

    const int g = lane >> 2, t = lane & 3;
#pragma unroll
    for (int i = 0; i < 2; i++) {
#pragma unroll
        for (int j = 0; j < 4; j++) {
            float* cp0 = C + (size_t)(bm + m0 + i * 16 + g) * D_MODEL + bn + n0 + j * 8 + 2 * t;
            float* cp1 = cp0 + 8 * D_MODEL;
            *(float2*)cp0 = make_float2(acc[i][j][0], acc[i][j][1]);
            *(float2*)cp1 = make_float2(acc[i][j][2], acc[i][j][3]);
        }
    }
}

// ---------------------------------------------------------------------------
// Tensor-core causal flash attention (validated R7/R8, unchanged)
// ---------------------------------------------------------------------------
#define ATT_SMEM (32768 + 2 * 32768)

__global__ __launch_bounds__(256, 1)
void attn_mma(const __nv_bfloat16* __restrict__ Qh, const __nv_bfloat16* __restrict__ Ql,
              const __nv_bfloat16* __restrict__ Kh, const __nv_bfloat16* __restrict__ Kl,
              const __nv_bfloat16* __restrict__ Vh, const __nv_bfloat16* __restrict__ Vl,
              __nv_bfloat16* __restrict__ Ohi, __nv_bfloat16* __restrict__ Olo)
{
    extern __shared__ char smem[];
    const uint32_t sb = smem_to_u32(smem);
    const int tid = threadIdx.x, wid = tid >> 5, lane = tid & 31;
    const int qblk = gridDim.x - 1 - blockIdx.x;   // heavy CTAs first
    const int bh = blockIdx.y;
    const int b = bh >> 4, h = bh & 15;
    const int qr0 = qblk * 128 + wid * 16;
    const int g = lane >> 2, t = lane & 3;
    const int qb2 = lane >> 3, l7 = lane & 7;
    const int ra = lane & 15, ca = lane >> 4;

    const uint32_t QH = sb, QL = sb + 16384;
    const uint32_t BUF0 = sb + 32768;

    {
        const __nv_bfloat16* qh_g = Qh + ((size_t)bh * SEQ + qblk * 128) * DK;
        const __nv_bfloat16* ql_g = Ql + ((size_t)bh * SEQ + qblk * 128) * DK;
#pragma unroll
        for (int u = tid; u < 1024; u += 256) {
            int row = u >> 3, c = u & 7;
            uint32_t sw = SW128((uint32_t)(row * 128 + c * 16));
            CP_ASYNC16(QH + sw, qh_g + (size_t)row * DK + c * 8);
            CP_ASYNC16(QL + sw, ql_g + (size_t)row * DK + c * 8);
        }
        CP_COMMIT();
    }

    const int nkb = 2 * (qblk + 1);

    auto load_kv = [&](uint32_t dbuf, int k0) {
#pragma unroll
        for (int u = tid; u < 512; u += 256) {
            int r = u >> 3, c = u & 7;
            uint32_t sw = SW128((uint32_t)(r * 128 + c * 16));
            const size_t kg = ((size_t)bh * SEQ + k0 + r) * DK + c * 8;
            CP_ASYNC16(dbuf + sw,         Kh + kg);
            CP_ASYNC16(dbuf + 8192 + sw,  Kl + kg);
            const size_t vg = ((size_t)bh * DK + r) * SEQ + k0 + c * 8;
            CP_ASYNC16(dbuf + 16384 + sw, Vh + vg);
            CP_ASYNC16(dbuf + 24576 + sw, Vl + vg);
        }
    };

    load_kv(BUF0, 0);
    CP_COMMIT();

    CP_WAIT(1);
    __syncthreads();

    uint32_t qhf[16], qlf[16];
#pragma unroll
    for (int ks = 0; ks < 4; ks++) {
        uint32_t sw = SW128((uint32_t)((wid * 16 + ra) * 128 + (ks * 2 + ca) * 16));
        LDSM_X4(qhf[4 * ks], qhf[4 * ks + 1], qhf[4 * ks + 2], qhf[4 * ks + 3], QH + sw);
        LDSM_X4(qlf[4 * ks], qlf[4 * ks + 1], qlf[4 * ks + 2], qlf[4 * ks + 3], QL + sw);
    }

    float o[8][4];
#pragma unroll
    for (int j = 0; j < 8; j++)
#pragma unroll
        for (int r = 0; r < 4; r++) o[j][r] = 0.f;
    float m0 = NEG_INF, m1 = NEG_INF, l0 = 0.f, l1 = 0.f;

    for (int kb = 0; kb < nkb; kb++) {
        const int k0 = kb * 64;
        const int buf = kb & 1;
        if (kb + 1 < nkb) {
            load_kv(BUF0 + (buf ^ 1) * 32768, (kb + 1) * 64);
            CP_COMMIT();
            CP_WAIT(1);
        } else {
            CP_WAIT(0);
        }
        __syncthreads();

        if (k0 <= qr0 + 15) {
            const uint32_t KHs = BUF0 + buf * 32768;
            const uint32_t KLs = KHs + 8192;
            const uint32_t VHs = KHs + 16384;
            const uint32_t VLs = KHs + 24576;

            float sf[8][4];
#pragma unroll
            for (int j = 0; j < 8; j++)
#pragma unroll
                for (int r = 0; r < 4; r++) sf[j][r] = 0.f;

#pragma unroll
            for (int ks = 0; ks < 4; ks++) {
                uint32_t bhf[16], blf[16];
#pragma unroll
                for (int jj = 0; jj < 4; jj++) {
                    uint32_t sw = SW128((uint32_t)(((jj * 2 + (qb2 >> 1)) * 8 + l7) * 128
                                                   + (ks * 2 + (qb2 & 1)) * 16));
                    LDSM_X4(bhf[4 * jj], bhf[4 * jj + 1], bhf[4 * jj + 2], bhf[4 * jj + 3], KHs + sw);
                    LDSM_X4(blf[4 * jj], blf[4 * jj + 1], blf[4 * jj + 2], blf[4 * jj + 3], KLs + sw);
                }
#pragma unroll
                for (int j = 0; j < 8; j++) {
                    MMA_BF16(sf[j], &qhf[4 * ks], &bhf[2 * j]);
                    MMA_BF16(sf[j], &qhf[4 * ks], &blf[2 * j]);
                    MMA_BF16(sf[j], &qlf[4 * ks], &bhf[2 * j]);
                }
            }

            if (k0 + 63 > qr0) {
                const int row0 = qr0 + g, row1 = row0 + 8;
#pragma unroll
                for (int j = 0; j < 8; j++) {
                    const int key = k0 + 8 * j + 2 * t;
                    if (key     > row0) sf[j][0] = NEG_INF;
                    if (key + 1 > row0) sf[j][1] = NEG_INF;
                    if (key     > row1) sf[j][2] = NEG_INF;
                    if (key + 1 > row1) sf[j][3] = NEG_INF;
                }
            }

            float mx0 = NEG_INF, mx1 = NEG_INF;
#pragma unroll
            for (int j = 0; j < 8; j++) {
                mx0 = fmaxf(mx0, fmaxf(sf[j][0], sf[j][1]));
                mx1 = fmaxf(mx1, fmaxf(sf[j][2], sf[j][3]));
            }
            mx0 = fmaxf(mx0, __shfl_xor_sync(0xffffffffu, mx0, 1));
            mx0 = fmaxf(mx0, __shfl_xor_sync(0xffffffffu, mx0, 2));
            mx1 = fmaxf(mx1, __shfl_xor_sync(0xffffffffu, mx1, 1));
            mx1 = fmaxf(mx1, __shfl_xor_sync(0xffffffffu, mx1, 2));
            const float mn0 = fmaxf(m0, mx0), mn1 = fmaxf(m1, mx1);
            const float a0 = __expf(m0 - mn0), a1 = __expf(m1 - mn1);
            m0 = mn0; m1 = mn1;

            float rs0 = 0.f, rs1 = 0.f;
            uint32_t ph[16], pl[16];
#pragma unroll
            for (int j = 0; j < 8; j++) {
                float p0 = __expf(sf[j][0] - mn0);
                float p1 = __expf(sf[j][1] - mn0);
                float p2 = __expf(sf[j][2] - mn1);
                float p3 = __expf(sf[j][3] - mn1);
                rs0 += p0 + p1;
                rs1 += p2 + p3;
                const int ks2 = j >> 1, hf = j & 1;
                split2(p0, p1, ph[4 * ks2 + 2 * hf],     pl[4 * ks2 + 2 * hf]);
                split2(p2, p3, ph[4 * ks2 + 2 * hf + 1], pl[4 * ks2 + 2 * hf + 1]);
            }
            rs0 += __shfl_xor_sync(0xffffffffu, rs0, 1);
            rs0 += __shfl_xor_sync(0xffffffffu, rs0, 2);
            rs1 += __shfl_xor_sync(0xffffffffu, rs1, 1);
            rs1 += __shfl_xor_sync(0xffffffffu, rs1, 2);
            l0 = l0 * a0 + rs0;
            l1 = l1 * a1 + rs1;

#pragma unroll
            for (int j = 0; j < 8; j++) {
                o[j][0] *= a0; o[j][1] *= a0;
                o[j][2] *= a1; o[j][3] *= a1;
            }

#pragma unroll
            for (int ks = 0; ks < 4; ks++) {
                uint32_t vhf[16], vlf[16];
#pragma unroll
                for (int jj = 0; jj < 4; jj++) {
                    uint32_t sw = SW128((uint32_t)(((jj * 2 + (qb2 >> 1)) * 8 + l7) * 128
                                                   + (ks * 2 + (qb2 & 1)) * 16));
                    LDSM_X4(vhf[4 * jj], vhf[4 * jj + 1], vhf[4 * jj + 2], vhf[4 * jj + 3], VHs + sw);
                    LDSM_X4(vlf[4 * jj], vlf[4 * jj + 1], vlf[4 * jj + 2], vlf[4 * jj + 3], VLs + sw);
                }
#pragma unroll
                for (int j = 0; j < 8; j++) {
                    MMA_BF16(o[j], &ph[4 * ks], &vhf[2 * j]);
                    MMA_BF16(o[j], &ph[4 * ks], &vlf[2 * j]);
                    MMA_BF16(o[j], &pl[4 * ks], &vhf[2 * j]);
                }
            }
        }
        __syncthreads();
    }

    const float il0 = 1.f / l0, il1 = 1.f / l1;
    const size_t r0 = (size_t)(b * SEQ + qr0 + g) * D_MODEL + h * DK;
    const size_t r1 = r0 + (size_t)8 * D_MODEL;
#pragma unroll
    for (int j = 0; j < 8; j++) {
        const int c = 8 * j + 2 * t;
        uint32_t hv, lv;
        split2(o[j][0] * il0, o[j][1] * il0, hv, lv);
        *(uint32_t*)(Ohi + r0 + c) = hv;
        *(uint32_t*)(Olo + r0 + c) = lv;
        split2(o[j][2] * il1, o[j][3] * il1, hv, lv);
        *(uint32_t*)(Ohi + r1 + c) = hv;
        *(uint32_t*)(Olo + r1 + c) = lv;
    }
}

// ---------------------------------------------------------------------------
extern "C" void kernel_launch(void* const* d_in, const int* in_sizes, int n_in,
                              void* d_out, int out_size)
{
    (void)in_sizes; (void)n_in; (void)out_size;
    const float* x  = (const float*)d_in[0];
    const float* Wq = (const float*)d_in[1];
    const float* Wk = (const float*)d_in[2];
    const float* Wv = (const float*)d_in[3];
    const float* Wo = (const float*)d_in[4];
    float* out = (float*)d_out;

    __nv_bfloat16 *xhi, *xlo, *ohi, *olo, *whi, *wlo;
    cudaGetSymbolAddress((void**)&xhi, g_x_hi);
    cudaGetSymbolAddress((void**)&xlo, g_x_lo);
    cudaGetSymbolAddress((void**)&ohi, g_o_hi);
    cudaGetSymbolAddress((void**)&olo, g_o_lo);
    cudaGetSymbolAddress((void**)&whi, g_w_hi);
    cudaGetSymbolAddress((void**)&wlo, g_w_lo);
    __nv_bfloat16 *qh, *ql, *kh, *kl, *vth, *vtl;
    cudaGetSymbolAddress((void**)&qh,  g_qh);
    cudaGetSymbolAddress((void**)&ql,  g_ql);
    cudaGetSymbolAddress((void**)&kh,  g_kh);
    cudaGetSymbolAddress((void**)&kl,  g_kl);
    cudaGetSymbolAddress((void**)&vth, g_vth);
    cudaGetSymbolAddress((void**)&vtl, g_vtl);

    cudaFuncSetAttribute(gemm_qkv, cudaFuncAttributeMaxDynamicSharedMemorySize, GEMM_SMEM);
    cudaFuncSetAttribute(gemm_mma, cudaFuncAttributeMaxDynamicSharedMemorySize, GEMM_SMEM);
    cudaFuncSetAttribute(attn_mma, cudaFuncAttributeMaxDynamicSharedMemorySize, ATT_SMEM);

    const int NW4 = D_MODEL * D_MODEL / 4;   // 262,144
    const int WSZ = D_MODEL * D_MODEL;

    cvt_all<<<dim3(NW4 / 256, 8), 256>>>(x, Wq, Wk, Wv, Wo, xhi, xlo, whi, wlo);

    gemm_qkv<<<dim3(D_MODEL / 128, MTOT / 128, 3), GNT, GEMM_SMEM>>>(
        xhi, xlo, whi, wlo, qh, ql, kh, kl, vth, vtl);

    attn_mma<<<dim3(SEQ / 128, BH), 256, ATT_SMEM>>>(qh, ql, kh, kl, vth, vtl, ohi, olo);

    gemm_mma<<<dim3(D_MODEL / 128, MTOT / 128), GNT, GEMM_SMEM>>>(
        ohi, olo, whi + 3 * WSZ, wlo + 3 * WSZ, out);
}

// round 10
// speedup vs baseline: 1.6638x; 1.6638x over previous
#include <cuda_runtime.h>
#include <cuda_bf16.h>
#include <cstdint>

#define D_MODEL 1024
#define NHEAD   16
#define DK      64
#define BATCH   2
#define SEQ     2048
#define MTOT    (BATCH * SEQ)   // 4096
#define BH      (BATCH * NHEAD) // 32

#define NEG_INF __int_as_float(0xff800000)

// ---------------------------------------------------------------------------
// Scratch (__device__ globals: allocations are forbidden)
// ---------------------------------------------------------------------------
__device__ __nv_bfloat16 g_x_hi[MTOT * D_MODEL];
__device__ __nv_bfloat16 g_x_lo[MTOT * D_MODEL];
__device__ __nv_bfloat16 g_o_hi[MTOT * D_MODEL];
__device__ __nv_bfloat16 g_o_lo[MTOT * D_MODEL];
__device__ __nv_bfloat16 g_w_hi[4][D_MODEL * D_MODEL];
__device__ __nv_bfloat16 g_w_lo[4][D_MODEL * D_MODEL];

// head-major bf16 hi/lo for attention
__device__ __nv_bfloat16 g_qh[BH * SEQ * DK];
__device__ __nv_bfloat16 g_ql[BH * SEQ * DK];
__device__ __nv_bfloat16 g_kh[BH * SEQ * DK];
__device__ __nv_bfloat16 g_kl[BH * SEQ * DK];
__device__ __nv_bfloat16 g_vth[BH * DK * SEQ];  // transposed: [bh][d][s]
__device__ __nv_bfloat16 g_vtl[BH * DK * SEQ];

// ---------------------------------------------------------------------------
// Base-ISA helpers (NO tcgen05 — harness ptxas targets plain sm_103)
// ---------------------------------------------------------------------------
__device__ __forceinline__ uint32_t smem_to_u32(const void* p) {
    uint32_t a;
    asm("{ .reg .u64 t; cvta.to.shared.u64 t, %1; cvt.u32.u64 %0, t; }" : "=r"(a) : "l"(p));
    return a;
}
#define SW128(o) ((o) ^ (((o) >> 3) & 0x70))

#define CP_ASYNC16(dst, src) \
    asm volatile("cp.async.cg.shared.global [%0], [%1], 16;" :: "r"(dst), "l"(src))
#define CP_COMMIT() asm volatile("cp.async.commit_group;" ::: "memory")
#define CP_WAIT(n)  asm volatile("cp.async.wait_group %0;" :: "n"(n) : "memory")

#define LDSM_X4(r0, r1, r2, r3, addr) \
    asm volatile("ldmatrix.sync.aligned.m8n8.x4.shared.b16 {%0,%1,%2,%3}, [%4];" \
                 : "=r"(r0), "=r"(r1), "=r"(r2), "=r"(r3) : "r"(addr))

#define MMA_BF16(c, a, b) \
    asm volatile("mma.sync.aligned.m16n8k16.row.col.f32.bf16.bf16.f32 " \
                 "{%0,%1,%2,%3}, {%4,%5,%6,%7}, {%8,%9}, {%0,%1,%2,%3};" \
                 : "+f"((c)[0]), "+f"((c)[1]), "+f"((c)[2]), "+f"((c)[3]) \
                 : "r"((a)[0]), "r"((a)[1]), "r"((a)[2]), "r"((a)[3]), \
                   "r"((b)[0]), "r"((b)[1]))

__device__ __forceinline__ void split2(float x, float y, uint32_t& hi, uint32_t& lo) {
    __nv_bfloat16 hx = __float2bfloat16(x), hy = __float2bfloat16(y);
    __nv_bfloat16 lx = __float2bfloat16(x - __bfloat162float(hx));
    __nv_bfloat16 ly = __float2bfloat16(y - __bfloat162float(hy));
    __nv_bfloat162 th(hx, hy), tl(lx, ly);
    hi = *(uint32_t*)&th;
    lo = *(uint32_t*)&tl;
}

// ---------------------------------------------------------------------------
// fp32 -> bf16 hi/lo split, one launch for x (4 slices) + 4 weights.
// ---------------------------------------------------------------------------
__global__ __launch_bounds__(256)
void cvt_all(const float* __restrict__ x,
             const float* __restrict__ w0, const float* __restrict__ w1,
             const float* __restrict__ w2, const float* __restrict__ w3,
             __nv_bfloat16* __restrict__ xhi, __nv_bfloat16* __restrict__ xlo,
             __nv_bfloat16* __restrict__ whi, __nv_bfloat16* __restrict__ wlo)
{
    const int y = blockIdx.y;
    const size_t WSZ4 = (size_t)D_MODEL * D_MODEL / 4;
    const float* src;
    __nv_bfloat16 *hi, *lo;
    if (y < 4) {
        src = (y == 0) ? w0 : (y == 1) ? w1 : (y == 2) ? w2 : w3;
        hi = whi + (size_t)y * D_MODEL * D_MODEL;
        lo = wlo + (size_t)y * D_MODEL * D_MODEL;
    } else {
        src = x + (size_t)(y - 4) * WSZ4 * 4;
        hi = xhi + (size_t)(y - 4) * WSZ4 * 4;
        lo = xlo + (size_t)(y - 4) * WSZ4 * 4;
    }
    int i = blockIdx.x * 256 + threadIdx.x;
    float4 v = ((const float4*)src)[i];
    uint32_t h0, l0, h1, l1;
    split2(v.x, v.y, h0, l0);
    split2(v.z, v.w, h1, l1);
    ((uint32_t*)hi)[2 * i] = h0;     ((uint32_t*)hi)[2 * i + 1] = h1;
    ((uint32_t*)lo)[2 * i] = l0;     ((uint32_t*)lo)[2 * i + 1] = l1;
}

// ---------------------------------------------------------------------------
// GEMM core — EXACT R8 configuration (validated fastest): 128x128 CTA tile,
// 8 warps (2x4), warp tile 64x32, KC=64, cp.async double buffering.
// ---------------------------------------------------------------------------
#define KC        64
#define NCHUNK    (D_MODEL / KC)      // 16
#define TILE_B    16384
#define BUF_B     (4 * TILE_B)
#define GEMM_SMEM (2 * BUF_B)         // 131072

__device__ __forceinline__ void cp_tile(uint32_t dst_base, const __nv_bfloat16* src, int tid)
{
#pragma unroll
    for (int u = tid; u < 1024; u += 256) {
        int row = u >> 3, c = u & 7;
        uint32_t off = row * 128 + c * 16;
        CP_ASYNC16(dst_base + SW128(off), src + (size_t)row * D_MODEL + c * 8);
    }
}

__device__ __forceinline__ void gemm_mainloop(
    uint32_t sbase, int tid, int lane, int m0, int n0,
    const __nv_bfloat16* pAh, const __nv_bfloat16* pAl,
    const __nv_bfloat16* pBh, const __nv_bfloat16* pBl,
    float acc[4][4][4])
{
#pragma unroll
    for (int i = 0; i < 4; i++)
#pragma unroll
        for (int j = 0; j < 4; j++)
#pragma unroll
            for (int r = 0; r < 4; r++) acc[i][j][r] = 0.f;

    const int ra = lane & 15;
    const int ca = lane >> 4;
    const int qb = lane >> 3;
    const int l7 = lane & 7;

    cp_tile(sbase + 0 * TILE_B, pAh, tid);
    cp_tile(sbase + 1 * TILE_B, pAl, tid);
    cp_tile(sbase + 2 * TILE_B, pBh, tid);
    cp_tile(sbase + 3 * TILE_B, pBl, tid);
    CP_COMMIT();

    for (int ch = 0; ch < NCHUNK; ch++) {
        const int buf = ch & 1;
        if (ch + 1 < NCHUNK) {
            const uint32_t nb = sbase + (buf ^ 1) * BUF_B;
            const int kc = (ch + 1) * KC;
            cp_tile(nb + 0 * TILE_B, pAh + kc, tid);
            cp_tile(nb + 1 * TILE_B, pAl + kc, tid);
            cp_tile(nb + 2 * TILE_B, pBh + kc, tid);
            cp_tile(nb + 3 * TILE_B, pBl + kc, tid);
            CP_COMMIT();
            CP_WAIT(1);
        } else {
            CP_WAIT(0);
        }
        __syncthreads();

        const uint32_t aH = sbase + buf * BUF_B + 0 * TILE_B;
        const uint32_t aL = sbase + buf * BUF_B + 1 * TILE_B;
        const uint32_t bH = sbase + buf * BUF_B + 2 * TILE_B;
        const uint32_t bL = sbase + buf * BUF_B + 3 * TILE_B;

#pragma unroll
        for (int ks = 0; ks < 4; ks++) {
            uint32_t ah[16], al[16];
#pragma unroll
            for (int i = 0; i < 4; i++) {
                uint32_t off = (uint32_t)(m0 + i * 16 + ra) * 128 + (ks * 2 + ca) * 16;
                uint32_t sw = SW128(off);
                LDSM_X4(ah[4 * i], ah[4 * i + 1], ah[4 * i + 2], ah[4 * i + 3], aH + sw);
                LDSM_X4(al[4 * i], al[4 * i + 1], al[4 * i + 2], al[4 * i + 3], aL + sw);
            }
            uint32_t bh[8], bl[8];
#pragma unroll
            for (int jj = 0; jj < 2; jj++) {
                uint32_t off = (uint32_t)(n0 + (jj * 2 + (qb >> 1)) * 8 + l7) * 128
                             + (ks * 2 + (qb & 1)) * 16;
                uint32_t sw = SW128(off);
                LDSM_X4(bh[4 * jj], bh[4 * jj + 1], bh[4 * jj + 2], bh[4 * jj + 3], bH + sw);
                LDSM_X4(bl[4 * jj], bl[4 * jj + 1], bl[4 * jj + 2], bl[4 * jj + 3], bL + sw);
            }
#pragma unroll
            for (int i = 0; i < 4; i++)
#pragma unroll
                for (int j = 0; j < 4; j++) {
                    MMA_BF16(acc[i][j], &ah[4 * i], &bh[2 * j]);
                    MMA_BF16(acc[i][j], &ah[4 * i], &bl[2 * j]);
                    MMA_BF16(acc[i][j], &al[4 * i], &bh[2 * j]);
                }
        }
        __syncthreads();
    }
}

// ---------------------------------------------------------------------------
// QKV projections, one launch (grid.z = 0:Q, 1:K, 2:V).
// ---------------------------------------------------------------------------
__global__ __launch_bounds__(256, 1)
void gemm_qkv(const __nv_bfloat16* __restrict__ Ahi, const __nv_bfloat16* __restrict__ Alo,
              const __nv_bfloat16* __restrict__ Whi, const __nv_bfloat16* __restrict__ Wlo,
              __nv_bfloat16* __restrict__ qh, __nv_bfloat16* __restrict__ ql,
              __nv_bfloat16* __restrict__ kh, __nv_bfloat16* __restrict__ kl,
              __nv_bfloat16* __restrict__ vth, __nv_bfloat16* __restrict__ vtl)
{
    extern __shared__ char smem[];
    const uint32_t sbase = smem_to_u32(smem);
    const int tid = threadIdx.x;
    const int wid = tid >> 5, lane = tid & 31;
    const int bm = blockIdx.y * 128;
    const int bn = blockIdx.x * 128;
    const int z  = blockIdx.z;
    const int m0 = (wid & 1) * 64;
    const int n0 = (wid >> 1) * 32;

    float acc[4][4][4];
    gemm_mainloop(sbase, tid, lane, m0, n0,
                  Ahi + (size_t)bm * D_MODEL,
                  Alo + (size_t)bm * D_MODEL,
                  Whi + (size_t)z * D_MODEL * D_MODEL + (size_t)bn * D_MODEL,
                  Wlo + (size_t)z * D_MODEL * D_MODEL + (size_t)bn * D_MODEL,
                  acc);

    const int g = lane >> 2, t = lane & 3;

    if (z == 2) {
#pragma unroll
        for (int i = 0; i < 4; i++) {
#pragma unroll
            for (int j = 0; j < 4; j++) {
                const int c  = bn + n0 + j * 8 + 2 * t;
                const int hh = c >> 6, d0 = c & 63;
#pragma unroll
                for (int rr = 0; rr < 4; rr++) {
                    const int row = bm + m0 + i * 16 + g + ((rr >> 1) * 8);
                    const int b = row >> 11, s = row & (SEQ - 1);
                    const int d = d0 + (rr & 1);
                    float v = acc[i][j][rr];
                    __nv_bfloat16 hv = __float2bfloat16(v);
                    __nv_bfloat16 lv = __float2bfloat16(v - __bfloat162float(hv));
                    const size_t dst = ((size_t)((b * NHEAD + hh) * DK + d)) * SEQ + s;
                    vth[dst] = hv;
                    vtl[dst] = lv;
                }
            }
        }
    } else {
        __nv_bfloat16* Hi = (z == 0) ? qh : kh;
        __nv_bfloat16* Lo = (z == 0) ? ql : kl;
        const float sc = (z == 0) ? 0.125f : 1.0f;
#pragma unroll
        for (int i = 0; i < 4; i++) {
#pragma unroll
            for (int j = 0; j < 4; j++) {
                const int c  = bn + n0 + j * 8 + 2 * t;
                const int hh = c >> 6, d = c & 63;
                const int row0 = bm + m0 + i * 16 + g;
                uint32_t hv, lv;
                {
                    const int b = row0 >> 11, s = row0 & (SEQ - 1);
                    split2(acc[i][j][0] * sc, acc[i][j][1] * sc, hv, lv);
                    const size_t dst = ((size_t)((b * NHEAD + hh) * SEQ + s)) * DK + d;
                    *(uint32_t*)(Hi + dst) = hv;
                    *(uint32_t*)(Lo + dst) = lv;
                }
                {
                    const int row1 = row0 + 8;
                    const int b = row1 >> 11, s = row1 & (SEQ - 1);
                    split2(acc[i][j][2] * sc, acc[i][j][3] * sc, hv, lv);
                    const size_t dst = ((size_t)((b * NHEAD + hh) * SEQ + s)) * DK + d;
                    *(uint32_t*)(Hi + dst) = hv;
                    *(uint32_t*)(Lo + dst) = lv;
                }
            }
        }
    }
}

// ---------------------------------------------------------------------------
// Output projection GEMM (fp32 result to d_out)
// ---------------------------------------------------------------------------
__global__ __launch_bounds__(256, 1)
void gemm_mma(const __nv_bfloat16* __restrict__ Ahi, const __nv_bfloat16* __restrict__ Alo,
              const __nv_bfloat16* __restrict__ Bhi, const __nv_bfloat16* __restrict__ Blo,
              float* __restrict__ C)
{
    extern __shared__ char smem[];
    const uint32_t sbase = smem_to_u32(smem);
    const int tid = threadIdx.x;
    const int wid = tid >> 5, lane = tid & 31;
    const int bm = blockIdx.y * 128;
    const int bn = blockIdx.x * 128;
    const int m0 = (wid & 1) * 64;
    const int n0 = (wid >> 1) * 32;

    float acc[4][4][4];
    gemm_mainloop(sbase, tid, lane, m0, n0,
                  Ahi + (size_t)bm * D_MODEL,
                  Alo + (size_t)bm * D_MODEL,
                  Bhi + (size_t)bn * D_MODEL,
                  Blo + (size_t)bn * D_MODEL,
                  acc);

    const int g = lane >> 2, t = lane & 3;
#pragma unroll
    for (int i = 0; i < 4; i++) {
#pragma unroll
        for (int j = 0; j < 4; j++) {
            float* cp0 = C + (size_t)(bm + m0 + i * 16 + g) * D_MODEL + bn + n0 + j * 8 + 2 * t;
            float* cp1 = cp0 + 8 * D_MODEL;
            *(float2*)cp0 = make_float2(acc[i][j][0], acc[i][j][1]);
            *(float2*)cp1 = make_float2(acc[i][j][2], acc[i][j][3]);
        }
    }
}

// ---------------------------------------------------------------------------
// Tensor-core causal flash attention.
// NEW: 4 warps / 64 q-rows per CTA, single-buffered 64-key KV tile,
// 48KB smem -> 2 CTAs/SM so softmax of one CTA overlaps MMAs of the other.
// Per-warp math identical to the validated R7/R8 kernel (16 q-rows/warp).
// ---------------------------------------------------------------------------
#define ATT_NT   128
#define ATT_SMEM (16384 + 32768)   // Q(hi+lo, 64 rows) + one KV buffer

__global__ __launch_bounds__(ATT_NT, 2)
void attn_mma(const __nv_bfloat16* __restrict__ Qh, const __nv_bfloat16* __restrict__ Ql,
              const __nv_bfloat16* __restrict__ Kh, const __nv_bfloat16* __restrict__ Kl,
              const __nv_bfloat16* __restrict__ Vh, const __nv_bfloat16* __restrict__ Vl,
              __nv_bfloat16* __restrict__ Ohi, __nv_bfloat16* __restrict__ Olo)
{
    extern __shared__ char smem[];
    const uint32_t sb = smem_to_u32(smem);
    const int tid = threadIdx.x, wid = tid >> 5, lane = tid & 31;
    const int qblk = gridDim.x - 1 - blockIdx.x;   // heavy CTAs first
    const int bh = blockIdx.y;
    const int b = bh >> 4, h = bh & 15;
    const int qr0 = qblk * 64 + wid * 16;
    const int g = lane >> 2, t = lane & 3;
    const int qb2 = lane >> 3, l7 = lane & 7;
    const int ra = lane & 15, ca = lane >> 4;

    const uint32_t QH = sb, QL = sb + 8192;
    const uint32_t KVB = sb + 16384;   // KH +0, KL +8192, VH +16384, VL +24576

    // --- Q tile load (64 x 64 bf16, hi+lo) ---
    {
        const __nv_bfloat16* qh_g = Qh + ((size_t)bh * SEQ + qblk * 64) * DK;
        const __nv_bfloat16* ql_g = Ql + ((size_t)bh * SEQ + qblk * 64) * DK;
#pragma unroll
        for (int u = tid; u < 512; u += ATT_NT) {
            int row = u >> 3, c = u & 7;
            uint32_t sw = SW128((uint32_t)(row * 128 + c * 16));
            CP_ASYNC16(QH + sw, qh_g + (size_t)row * DK + c * 8);
            CP_ASYNC16(QL + sw, ql_g + (size_t)row * DK + c * 8);
        }
        CP_COMMIT();
        CP_WAIT(0);
        __syncthreads();
    }

    // --- Q fragments (persistent) ---
    uint32_t qhf[16], qlf[16];
#pragma unroll
    for (int ks = 0; ks < 4; ks++) {
        uint32_t sw = SW128((uint32_t)((wid * 16 + ra) * 128 + (ks * 2 + ca) * 16));
        LDSM_X4(qhf[4 * ks], qhf[4 * ks + 1], qhf[4 * ks + 2], qhf[4 * ks + 3], QH + sw);
        LDSM_X4(qlf[4 * ks], qlf[4 * ks + 1], qlf[4 * ks + 2], qlf[4 * ks + 3], QL + sw);
    }

    float o[8][4];
#pragma unroll
    for (int j = 0; j < 8; j++)
#pragma unroll
        for (int r = 0; r < 4; r++) o[j][r] = 0.f;
    float m0 = NEG_INF, m1 = NEG_INF, l0 = 0.f, l1 = 0.f;

    const int nkb = qblk + 1;

    for (int kb = 0; kb < nkb; kb++) {
        const int k0 = kb * 64;

        // single-buffered KV load (exposed latency hidden by the co-resident CTA)
#pragma unroll
        for (int u = tid; u < 512; u += ATT_NT) {
            int r = u >> 3, c = u & 7;
            uint32_t sw = SW128((uint32_t)(r * 128 + c * 16));
            const size_t kg = ((size_t)bh * SEQ + k0 + r) * DK + c * 8;
            CP_ASYNC16(KVB + sw,         Kh + kg);
            CP_ASYNC16(KVB + 8192 + sw,  Kl + kg);
            const size_t vg = ((size_t)bh * DK + r) * SEQ + k0 + c * 8;
            CP_ASYNC16(KVB + 16384 + sw, Vh + vg);
            CP_ASYNC16(KVB + 24576 + sw, Vl + vg);
        }
        CP_COMMIT();
        CP_WAIT(0);
        __syncthreads();

        const uint32_t KHs = KVB;
        const uint32_t KLs = KVB + 8192;
        const uint32_t VHs = KVB + 16384;
        const uint32_t VLs = KVB + 24576;

        // --- S = Q K^T ---
        float sf[8][4];
#pragma unroll
        for (int j = 0; j < 8; j++)
#pragma unroll
            for (int r = 0; r < 4; r++) sf[j][r] = 0.f;

#pragma unroll
        for (int ks = 0; ks < 4; ks++) {
            uint32_t bhf[16], blf[16];
#pragma unroll
            for (int jj = 0; jj < 4; jj++) {
                uint32_t sw = SW128((uint32_t)(((jj * 2 + (qb2 >> 1)) * 8 + l7) * 128
                                               + (ks * 2 + (qb2 & 1)) * 16));
                LDSM_X4(bhf[4 * jj], bhf[4 * jj + 1], bhf[4 * jj + 2], bhf[4 * jj + 3], KHs + sw);
                LDSM_X4(blf[4 * jj], blf[4 * jj + 1], blf[4 * jj + 2], blf[4 * jj + 3], KLs + sw);
            }
#pragma unroll
            for (int j = 0; j < 8; j++) {
                MMA_BF16(sf[j], &qhf[4 * ks], &bhf[2 * j]);
                MMA_BF16(sf[j], &qhf[4 * ks], &blf[2 * j]);
                MMA_BF16(sf[j], &qlf[4 * ks], &bhf[2 * j]);
            }
        }

        // --- causal mask (only needed on the diagonal block group) ---
        if (k0 + 63 > qr0) {
            const int row0 = qr0 + g, row1 = row0 + 8;
#pragma unroll
            for (int j = 0; j < 8; j++) {
                const int key = k0 + 8 * j + 2 * t;
                if (key     > row0) sf[j][0] = NEG_INF;
                if (key + 1 > row0) sf[j][1] = NEG_INF;
                if (key     > row1) sf[j][2] = NEG_INF;
                if (key + 1 > row1) sf[j][3] = NEG_INF;
            }
        }

        // --- online softmax ---
        float mx0 = NEG_INF, mx1 = NEG_INF;
#pragma unroll
        for (int j = 0; j < 8; j++) {
            mx0 = fmaxf(mx0, fmaxf(sf[j][0], sf[j][1]));
            mx1 = fmaxf(mx1, fmaxf(sf[j][2], sf[j][3]));
        }
        mx0 = fmaxf(mx0, __shfl_xor_sync(0xffffffffu, mx0, 1));
        mx0 = fmaxf(mx0, __shfl_xor_sync(0xffffffffu, mx0, 2));
        mx1 = fmaxf(mx1, __shfl_xor_sync(0xffffffffu, mx1, 1));
        mx1 = fmaxf(mx1, __shfl_xor_sync(0xffffffffu, mx1, 2));
        const float mn0 = fmaxf(m0, mx0), mn1 = fmaxf(m1, mx1);
        const float a0 = __expf(m0 - mn0), a1 = __expf(m1 - mn1);
        m0 = mn0; m1 = mn1;

        float rs0 = 0.f, rs1 = 0.f;
        uint32_t ph[16], pl[16];
#pragma unroll
        for (int j = 0; j < 8; j++) {
            float p0 = __expf(sf[j][0] - mn0);
            float p1 = __expf(sf[j][1] - mn0);
            float p2 = __expf(sf[j][2] - mn1);
            float p3 = __expf(sf[j][3] - mn1);
            rs0 += p0 + p1;
            rs1 += p2 + p3;
            const int ks2 = j >> 1, hf = j & 1;
            split2(p0, p1, ph[4 * ks2 + 2 * hf],     pl[4 * ks2 + 2 * hf]);
            split2(p2, p3, ph[4 * ks2 + 2 * hf + 1], pl[4 * ks2 + 2 * hf + 1]);
        }
        rs0 += __shfl_xor_sync(0xffffffffu, rs0, 1);
        rs0 += __shfl_xor_sync(0xffffffffu, rs0, 2);
        rs1 += __shfl_xor_sync(0xffffffffu, rs1, 1);
        rs1 += __shfl_xor_sync(0xffffffffu, rs1, 2);
        l0 = l0 * a0 + rs0;
        l1 = l1 * a1 + rs1;

#pragma unroll
        for (int j = 0; j < 8; j++) {
            o[j][0] *= a0; o[j][1] *= a0;
            o[j][2] *= a1; o[j][3] *= a1;
        }

        // --- O += P V ---
#pragma unroll
        for (int ks = 0; ks < 4; ks++) {
            uint32_t vhf[16], vlf[16];
#pragma unroll
            for (int jj = 0; jj < 4; jj++) {
                uint32_t sw = SW128((uint32_t)(((jj * 2 + (qb2 >> 1)) * 8 + l7) * 128
                                               + (ks * 2 + (qb2 & 1)) * 16));
                LDSM_X4(vhf[4 * jj], vhf[4 * jj + 1], vhf[4 * jj + 2], vhf[4 * jj + 3], VHs + sw);
                LDSM_X4(vlf[4 * jj], vlf[4 * jj + 1], vlf[4 * jj + 2], vlf[4 * jj + 3], VLs + sw);
            }
#pragma unroll
            for (int j = 0; j < 8; j++) {
                MMA_BF16(o[j], &ph[4 * ks], &vhf[2 * j]);
                MMA_BF16(o[j], &ph[4 * ks], &vlf[2 * j]);
                MMA_BF16(o[j], &pl[4 * ks], &vhf[2 * j]);
            }
        }

        __syncthreads();   // all reads done before next load overwrites
    }

    const float il0 = 1.f / l0, il1 = 1.f / l1;
    const size_t r0 = (size_t)(b * SEQ + qr0 + g) * D_MODEL + h * DK;
    const size_t r1 = r0 + (size_t)8 * D_MODEL;
#pragma unroll
    for (int j = 0; j < 8; j++) {
        const int c = 8 * j + 2 * t;
        uint32_t hv, lv;
        split2(o[j][0] * il0, o[j][1] * il0, hv, lv);
        *(uint32_t*)(Ohi + r0 + c) = hv;
        *(uint32_t*)(Olo + r0 + c) = lv;
        split2(o[j][2] * il1, o[j][3] * il1, hv, lv);
        *(uint32_t*)(Ohi + r1 + c) = hv;
        *(uint32_t*)(Olo + r1 + c) = lv;
    }
}

// ---------------------------------------------------------------------------
extern "C" void kernel_launch(void* const* d_in, const int* in_sizes, int n_in,
                              void* d_out, int out_size)
{
    (void)in_sizes; (void)n_in; (void)out_size;
    const float* x  = (const float*)d_in[0];
    const float* Wq = (const float*)d_in[1];
    const float* Wk = (const float*)d_in[2];
    const float* Wv = (const float*)d_in[3];
    const float* Wo = (const float*)d_in[4];
    float* out = (float*)d_out;

    __nv_bfloat16 *xhi, *xlo, *ohi, *olo, *whi, *wlo;
    cudaGetSymbolAddress((void**)&xhi, g_x_hi);
    cudaGetSymbolAddress((void**)&xlo, g_x_lo);
    cudaGetSymbolAddress((void**)&ohi, g_o_hi);
    cudaGetSymbolAddress((void**)&olo, g_o_lo);
    cudaGetSymbolAddress((void**)&whi, g_w_hi);
    cudaGetSymbolAddress((void**)&wlo, g_w_lo);
    __nv_bfloat16 *qh, *ql, *kh, *kl, *vth, *vtl;
    cudaGetSymbolAddress((void**)&qh,  g_qh);
    cudaGetSymbolAddress((void**)&ql,  g_ql);
    cudaGetSymbolAddress((void**)&kh,  g_kh);
    cudaGetSymbolAddress((void**)&kl,  g_kl);
    cudaGetSymbolAddress((void**)&vth, g_vth);
    cudaGetSymbolAddress((void**)&vtl, g_vtl);

    cudaFuncSetAttribute(gemm_qkv, cudaFuncAttributeMaxDynamicSharedMemorySize, GEMM_SMEM);
    cudaFuncSetAttribute(gemm_mma, cudaFuncAttributeMaxDynamicSharedMemorySize, GEMM_SMEM);
    cudaFuncSetAttribute(attn_mma, cudaFuncAttributeMaxDynamicSharedMemorySize, ATT_SMEM);

    const int NW4 = D_MODEL * D_MODEL / 4;   // 262,144
    const int WSZ = D_MODEL * D_MODEL;

    cvt_all<<<dim3(NW4 / 256, 8), 256>>>(x, Wq, Wk, Wv, Wo, xhi, xlo, whi, wlo);

    gemm_qkv<<<dim3(D_MODEL / 128, MTOT / 128, 3), 256, GEMM_SMEM>>>(
        xhi, xlo, whi, wlo, qh, ql, kh, kl, vth, vtl);

    attn_mma<<<dim3(SEQ / 64, BH), ATT_NT, ATT_SMEM>>>(qh, ql, kh, kl, vth, vtl, ohi, olo);

    gemm_mma<<<dim3(D_MODEL / 128, MTOT / 128), 256, GEMM_SMEM>>>(
        ohi, olo, whi + 3 * WSZ, wlo + 3 * WSZ, out);
}

// round 11
// speedup vs baseline: 1.9836x; 1.1923x over previous
#include <cuda_runtime.h>
#include <cuda_bf16.h>
#include <cuda_fp16.h>
#include <cstdint>

#define D_MODEL 1024
#define NHEAD   16
#define DK      64
#define BATCH   2
#define SEQ     2048
#define MTOT    (BATCH * SEQ)   // 4096
#define BH      (BATCH * NHEAD) // 32

#define NEG_INF __int_as_float(0xff800000)

// ---------------------------------------------------------------------------
// Scratch (__device__ globals: allocations are forbidden)
// ---------------------------------------------------------------------------
__device__ __half g_x_hi[MTOT * D_MODEL];
__device__ __half g_x_lo[MTOT * D_MODEL];
__device__ __half g_o_hi[MTOT * D_MODEL];
__device__ __half g_o_lo[MTOT * D_MODEL];
__device__ __half g_w_hi[4][D_MODEL * D_MODEL];   // fp16 hi only (2-pass scheme)

// head-major bf16 hi/lo for attention (unchanged, validated)
__device__ __nv_bfloat16 g_qh[BH * SEQ * DK];
__device__ __nv_bfloat16 g_ql[BH * SEQ * DK];
__device__ __nv_bfloat16 g_kh[BH * SEQ * DK];
__device__ __nv_bfloat16 g_kl[BH * SEQ * DK];
__device__ __nv_bfloat16 g_vth[BH * DK * SEQ];  // transposed: [bh][d][s]
__device__ __nv_bfloat16 g_vtl[BH * DK * SEQ];

// ---------------------------------------------------------------------------
// Base-ISA helpers (NO tcgen05 — harness ptxas targets plain sm_103)
// ---------------------------------------------------------------------------
__device__ __forceinline__ uint32_t smem_to_u32(const void* p) {
    uint32_t a;
    asm("{ .reg .u64 t; cvta.to.shared.u64 t, %1; cvt.u32.u64 %0, t; }" : "=r"(a) : "l"(p));
    return a;
}
#define SW128(o) ((o) ^ (((o) >> 3) & 0x70))

#define CP_ASYNC16(dst, src) \
    asm volatile("cp.async.cg.shared.global [%0], [%1], 16;" :: "r"(dst), "l"(src))
#define CP_COMMIT() asm volatile("cp.async.commit_group;" ::: "memory")
#define CP_WAIT(n)  asm volatile("cp.async.wait_group %0;" :: "n"(n) : "memory")

#define LDSM_X4(r0, r1, r2, r3, addr) \
    asm volatile("ldmatrix.sync.aligned.m8n8.x4.shared.b16 {%0,%1,%2,%3}, [%4];" \
                 : "=r"(r0), "=r"(r1), "=r"(r2), "=r"(r3) : "r"(addr))

#define MMA_BF16(c, a, b) \
    asm volatile("mma.sync.aligned.m16n8k16.row.col.f32.bf16.bf16.f32 " \
                 "{%0,%1,%2,%3}, {%4,%5,%6,%7}, {%8,%9}, {%0,%1,%2,%3};" \
                 : "+f"((c)[0]), "+f"((c)[1]), "+f"((c)[2]), "+f"((c)[3]) \
                 : "r"((a)[0]), "r"((a)[1]), "r"((a)[2]), "r"((a)[3]), \
                   "r"((b)[0]), "r"((b)[1]))

#define MMA_F16(c, a, b) \
    asm volatile("mma.sync.aligned.m16n8k16.row.col.f32.f16.f16.f32 " \
                 "{%0,%1,%2,%3}, {%4,%5,%6,%7}, {%8,%9}, {%0,%1,%2,%3};" \
                 : "+f"((c)[0]), "+f"((c)[1]), "+f"((c)[2]), "+f"((c)[3]) \
                 : "r"((a)[0]), "r"((a)[1]), "r"((a)[2]), "r"((a)[3]), \
                   "r"((b)[0]), "r"((b)[1]))

__device__ __forceinline__ void split2(float x, float y, uint32_t& hi, uint32_t& lo) {
    __nv_bfloat16 hx = __float2bfloat16(x), hy = __float2bfloat16(y);
    __nv_bfloat16 lx = __float2bfloat16(x - __bfloat162float(hx));
    __nv_bfloat16 ly = __float2bfloat16(y - __bfloat162float(hy));
    __nv_bfloat162 th(hx, hy), tl(lx, ly);
    hi = *(uint32_t*)&th;
    lo = *(uint32_t*)&tl;
}

__device__ __forceinline__ void split2h(float x, float y, uint32_t& hi, uint32_t& lo) {
    __half hx = __float2half_rn(x), hy = __float2half_rn(y);
    __half lx = __float2half_rn(x - __half2float(hx));
    __half ly = __float2half_rn(y - __half2float(hy));
    __half2 th(hx, hy), tl(lx, ly);
    hi = *(uint32_t*)&th;
    lo = *(uint32_t*)&tl;
}

// ---------------------------------------------------------------------------
// fp32 -> fp16 conversion, one launch: weights (hi only) + x (hi/lo split)
// grid = (D_MODEL*D_MODEL/4/256, 8); y<4 -> weight y, y>=4 -> x slice y-4
// ---------------------------------------------------------------------------
__global__ __launch_bounds__(256)
void cvt_all(const float* __restrict__ x,
             const float* __restrict__ w0, const float* __restrict__ w1,
             const float* __restrict__ w2, const float* __restrict__ w3,
             __half* __restrict__ xhi, __half* __restrict__ xlo,
             __half* __restrict__ whi)
{
    const int y = blockIdx.y;
    const size_t WSZ4 = (size_t)D_MODEL * D_MODEL / 4;
    int i = blockIdx.x * 256 + threadIdx.x;
    if (y < 4) {
        const float* src = (y == 0) ? w0 : (y == 1) ? w1 : (y == 2) ? w2 : w3;
        __half* hi = whi + (size_t)y * D_MODEL * D_MODEL;
        float4 v = ((const float4*)src)[i];
        __half2 a(__float2half_rn(v.x), __float2half_rn(v.y));
        __half2 b(__float2half_rn(v.z), __float2half_rn(v.w));
        ((uint32_t*)hi)[2 * i]     = *(uint32_t*)&a;
        ((uint32_t*)hi)[2 * i + 1] = *(uint32_t*)&b;
    } else {
        const float* src = x + (size_t)(y - 4) * WSZ4 * 4;
        __half* hi = xhi + (size_t)(y - 4) * WSZ4 * 4;
        __half* lo = xlo + (size_t)(y - 4) * WSZ4 * 4;
        float4 v = ((const float4*)src)[i];
        uint32_t h0, l0, h1, l1;
        split2h(v.x, v.y, h0, l0);
        split2h(v.z, v.w, h1, l1);
        ((uint32_t*)hi)[2 * i] = h0;     ((uint32_t*)hi)[2 * i + 1] = h1;
        ((uint32_t*)lo)[2 * i] = l0;     ((uint32_t*)lo)[2 * i + 1] = l1;
    }
}

// ---------------------------------------------------------------------------
// GEMM core — R8 tile config (validated fastest), now fp16 2-pass:
//   C = (Ahi + Alo) * Bhi   (missing A*Blo ~ 2^-12 relative)
// 128x128 CTA tile, 8 warps (2x4), warp tile 64x32, KC=64, double buffering.
// Tiles per chunk: Ahi, Alo, Bhi (3 x 16KB).
// ---------------------------------------------------------------------------
#define KC        64
#define NCHUNK    (D_MODEL / KC)      // 16
#define TILE_B    16384
#define BUF_B     (3 * TILE_B)
#define GEMM_SMEM (2 * BUF_B)         // 98304

__device__ __forceinline__ void cp_tile(uint32_t dst_base, const __half* src, int tid)
{
#pragma unroll
    for (int u = tid; u < 1024; u += 256) {
        int row = u >> 3, c = u & 7;
        uint32_t off = row * 128 + c * 16;
        CP_ASYNC16(dst_base + SW128(off), src + (size_t)row * D_MODEL + c * 8);
    }
}

__device__ __forceinline__ void gemm_mainloop(
    uint32_t sbase, int tid, int lane, int m0, int n0,
    const __half* pAh, const __half* pAl, const __half* pBh,
    float acc[4][4][4])
{
#pragma unroll
    for (int i = 0; i < 4; i++)
#pragma unroll
        for (int j = 0; j < 4; j++)
#pragma unroll
            for (int r = 0; r < 4; r++) acc[i][j][r] = 0.f;

    const int ra = lane & 15;
    const int ca = lane >> 4;
    const int qb = lane >> 3;
    const int l7 = lane & 7;

    cp_tile(sbase + 0 * TILE_B, pAh, tid);
    cp_tile(sbase + 1 * TILE_B, pAl, tid);
    cp_tile(sbase + 2 * TILE_B, pBh, tid);
    CP_COMMIT();

    for (int ch = 0; ch < NCHUNK; ch++) {
        const int buf = ch & 1;
        if (ch + 1 < NCHUNK) {
            const uint32_t nb = sbase + (buf ^ 1) * BUF_B;
            const int kc = (ch + 1) * KC;
            cp_tile(nb + 0 * TILE_B, pAh + kc, tid);
            cp_tile(nb + 1 * TILE_B, pAl + kc, tid);
            cp_tile(nb + 2 * TILE_B, pBh + kc, tid);
            CP_COMMIT();
            CP_WAIT(1);
        } else {
            CP_WAIT(0);
        }
        __syncthreads();

        const uint32_t aH = sbase + buf * BUF_B + 0 * TILE_B;
        const uint32_t aL = sbase + buf * BUF_B + 1 * TILE_B;
        const uint32_t bH = sbase + buf * BUF_B + 2 * TILE_B;

#pragma unroll
        for (int ks = 0; ks < 4; ks++) {
            uint32_t ah[16], al[16];
#pragma unroll
            for (int i = 0; i < 4; i++) {
                uint32_t off = (uint32_t)(m0 + i * 16 + ra) * 128 + (ks * 2 + ca) * 16;
                uint32_t sw = SW128(off);
                LDSM_X4(ah[4 * i], ah[4 * i + 1], ah[4 * i + 2], ah[4 * i + 3], aH + sw);
                LDSM_X4(al[4 * i], al[4 * i + 1], al[4 * i + 2], al[4 * i + 3], aL + sw);
            }
            uint32_t bh[8];
#pragma unroll
            for (int jj = 0; jj < 2; jj++) {
                uint32_t off = (uint32_t)(n0 + (jj * 2 + (qb >> 1)) * 8 + l7) * 128
                             + (ks * 2 + (qb & 1)) * 16;
                uint32_t sw = SW128(off);
                LDSM_X4(bh[4 * jj], bh[4 * jj + 1], bh[4 * jj + 2], bh[4 * jj + 3], bH + sw);
            }
#pragma unroll
            for (int i = 0; i < 4; i++)
#pragma unroll
                for (int j = 0; j < 4; j++) {
                    MMA_F16(acc[i][j], &ah[4 * i], &bh[2 * j]);
                    MMA_F16(acc[i][j], &al[4 * i], &bh[2 * j]);
                }
        }
        __syncthreads();
    }
}

// ---------------------------------------------------------------------------
// QKV projections, one launch (grid.z = 0:Q, 1:K, 2:V).
// Epilogue writes attention-ready bf16 hi/lo layouts (unchanged).
// ---------------------------------------------------------------------------
__global__ __launch_bounds__(256, 1)
void gemm_qkv(const __half* __restrict__ Ahi, const __half* __restrict__ Alo,
              const __half* __restrict__ Whi,
              __nv_bfloat16* __restrict__ qh, __nv_bfloat16* __restrict__ ql,
              __nv_bfloat16* __restrict__ kh, __nv_bfloat16* __restrict__ kl,
              __nv_bfloat16* __restrict__ vth, __nv_bfloat16* __restrict__ vtl)
{
    extern __shared__ char smem[];
    const uint32_t sbase = smem_to_u32(smem);
    const int tid = threadIdx.x;
    const int wid = tid >> 5, lane = tid & 31;
    const int bm = blockIdx.y * 128;
    const int bn = blockIdx.x * 128;
    const int z  = blockIdx.z;
    const int m0 = (wid & 1) * 64;
    const int n0 = (wid >> 1) * 32;

    float acc[4][4][4];
    gemm_mainloop(sbase, tid, lane, m0, n0,
                  Ahi + (size_t)bm * D_MODEL,
                  Alo + (size_t)bm * D_MODEL,
                  Whi + (size_t)z * D_MODEL * D_MODEL + (size_t)bn * D_MODEL,
                  acc);

    const int g = lane >> 2, t = lane & 3;

    if (z == 2) {
#pragma unroll
        for (int i = 0; i < 4; i++) {
#pragma unroll
            for (int j = 0; j < 4; j++) {
                const int c  = bn + n0 + j * 8 + 2 * t;
                const int hh = c >> 6, d0 = c & 63;
#pragma unroll
                for (int rr = 0; rr < 4; rr++) {
                    const int row = bm + m0 + i * 16 + g + ((rr >> 1) * 8);
                    const int b = row >> 11, s = row & (SEQ - 1);
                    const int d = d0 + (rr & 1);
                    float v = acc[i][j][rr];
                    __nv_bfloat16 hv = __float2bfloat16(v);
                    __nv_bfloat16 lv = __float2bfloat16(v - __bfloat162float(hv));
                    const size_t dst = ((size_t)((b * NHEAD + hh) * DK + d)) * SEQ + s;
                    vth[dst] = hv;
                    vtl[dst] = lv;
                }
            }
        }
    } else {
        __nv_bfloat16* Hi = (z == 0) ? qh : kh;
        __nv_bfloat16* Lo = (z == 0) ? ql : kl;
        const float sc = (z == 0) ? 0.125f : 1.0f;
#pragma unroll
        for (int i = 0; i < 4; i++) {
#pragma unroll
            for (int j = 0; j < 4; j++) {
                const int c  = bn + n0 + j * 8 + 2 * t;
                const int hh = c >> 6, d = c & 63;
                const int row0 = bm + m0 + i * 16 + g;
                uint32_t hv, lv;
                {
                    const int b = row0 >> 11, s = row0 & (SEQ - 1);
                    split2(acc[i][j][0] * sc, acc[i][j][1] * sc, hv, lv);
                    const size_t dst = ((size_t)((b * NHEAD + hh) * SEQ + s)) * DK + d;
                    *(uint32_t*)(Hi + dst) = hv;
                    *(uint32_t*)(Lo + dst) = lv;
                }
                {
                    const int row1 = row0 + 8;
                    const int b = row1 >> 11, s = row1 & (SEQ - 1);
                    split2(acc[i][j][2] * sc, acc[i][j][3] * sc, hv, lv);
                    const size_t dst = ((size_t)((b * NHEAD + hh) * SEQ + s)) * DK + d;
                    *(uint32_t*)(Hi + dst) = hv;
                    *(uint32_t*)(Lo + dst) = lv;
                }
            }
        }
    }
}

// ---------------------------------------------------------------------------
// Output projection GEMM (fp32 result to d_out)
// ---------------------------------------------------------------------------
__global__ __launch_bounds__(256, 1)
void gemm_mma(const __half* __restrict__ Ahi, const __half* __restrict__ Alo,
              const __half* __restrict__ Bhi, float* __restrict__ C)
{
    extern __shared__ char smem[];
    const uint32_t sbase = smem_to_u32(smem);
    const int tid = threadIdx.x;
    const int wid = tid >> 5, lane = tid & 31;
    const int bm = blockIdx.y * 128;
    const int bn = blockIdx.x * 128;
    const int m0 = (wid & 1) * 64;
    const int n0 = (wid >> 1) * 32;

    float acc[4][4][4];
    gemm_mainloop(sbase, tid, lane, m0, n0,
                  Ahi + (size_t)bm * D_MODEL,
                  Alo + (size_t)bm * D_MODEL,
                  Bhi + (size_t)bn * D_MODEL,
                  acc);

    const int g = lane >> 2, t = lane & 3;
#pragma unroll
    for (int i = 0; i < 4; i++) {
#pragma unroll
        for (int j = 0; j < 4; j++) {
            float* cp0 = C + (size_t)(bm + m0 + i * 16 + g) * D_MODEL + bn + n0 + j * 8 + 2 * t;
            float* cp1 = cp0 + 8 * D_MODEL;
            *(float2*)cp0 = make_float2(acc[i][j][0], acc[i][j][1]);
            *(float2*)cp1 = make_float2(acc[i][j][2], acc[i][j][3]);
        }
    }
}

// ---------------------------------------------------------------------------
// Tensor-core causal flash attention (validated R10: 4 warps / 64 q-rows,
// 2 CTAs/SM). Internals bf16 3-pass; output now written as fp16 hi/lo.
// ---------------------------------------------------------------------------
#define ATT_NT   128
#define ATT_SMEM (16384 + 32768)   // Q(hi+lo, 64 rows) + one KV buffer

__global__ __launch_bounds__(ATT_NT, 2)
void attn_mma(const __nv_bfloat16* __restrict__ Qh, const __nv_bfloat16* __restrict__ Ql,
              const __nv_bfloat16* __restrict__ Kh, const __nv_bfloat16* __restrict__ Kl,
              const __nv_bfloat16* __restrict__ Vh, const __nv_bfloat16* __restrict__ Vl,
              __half* __restrict__ Ohi, __half* __restrict__ Olo)
{
    extern __shared__ char smem[];
    const uint32_t sb = smem_to_u32(smem);
    const int tid = threadIdx.x, wid = tid >> 5, lane = tid & 31;
    const int qblk = gridDim.x - 1 - blockIdx.x;   // heavy CTAs first
    const int bh = blockIdx.y;
    const int b = bh >> 4, h = bh & 15;
    const int qr0 = qblk * 64 + wid * 16;
    const int g = lane >> 2, t = lane & 3;
    const int qb2 = lane >> 3, l7 = lane & 7;
    const int ra = lane & 15, ca = lane >> 4;

    const uint32_t QH = sb, QL = sb + 8192;
    const uint32_t KVB = sb + 16384;   // KH +0, KL +8192, VH +16384, VL +24576

    {
        const __nv_bfloat16* qh_g = Qh + ((size_t)bh * SEQ + qblk * 64) * DK;
        const __nv_bfloat16* ql_g = Ql + ((size_t)bh * SEQ + qblk * 64) * DK;
#pragma unroll
        for (int u = tid; u < 512; u += ATT_NT) {
            int row = u >> 3, c = u & 7;
            uint32_t sw = SW128((uint32_t)(row * 128 + c * 16));
            CP_ASYNC16(QH + sw, qh_g + (size_t)row * DK + c * 8);
            CP_ASYNC16(QL + sw, ql_g + (size_t)row * DK + c * 8);
        }
        CP_COMMIT();
        CP_WAIT(0);
        __syncthreads();
    }

    uint32_t qhf[16], qlf[16];
#pragma unroll
    for (int ks = 0; ks < 4; ks++) {
        uint32_t sw = SW128((uint32_t)((wid * 16 + ra) * 128 + (ks * 2 + ca) * 16));
        LDSM_X4(qhf[4 * ks], qhf[4 * ks + 1], qhf[4 * ks + 2], qhf[4 * ks + 3], QH + sw);
        LDSM_X4(qlf[4 * ks], qlf[4 * ks + 1], qlf[4 * ks + 2], qlf[4 * ks + 3], QL + sw);
    }

    float o[8][4];
#pragma unroll
    for (int j = 0; j < 8; j++)
#pragma unroll
        for (int r = 0; r < 4; r++) o[j][r] = 0.f;
    float m0 = NEG_INF, m1 = NEG_INF, l0 = 0.f, l1 = 0.f;

    const int nkb = qblk + 1;

    for (int kb = 0; kb < nkb; kb++) {
        const int k0 = kb * 64;

#pragma unroll
        for (int u = tid; u < 512; u += ATT_NT) {
            int r = u >> 3, c = u & 7;
            uint32_t sw = SW128((uint32_t)(r * 128 + c * 16));
            const size_t kg = ((size_t)bh * SEQ + k0 + r) * DK + c * 8;
            CP_ASYNC16(KVB + sw,         Kh + kg);
            CP_ASYNC16(KVB + 8192 + sw,  Kl + kg);
            const size_t vg = ((size_t)bh * DK + r) * SEQ + k0 + c * 8;
            CP_ASYNC16(KVB + 16384 + sw, Vh + vg);
            CP_ASYNC16(KVB + 24576 + sw, Vl + vg);
        }
        CP_COMMIT();
        CP_WAIT(0);
        __syncthreads();

        const uint32_t KHs = KVB;
        const uint32_t KLs = KVB + 8192;
        const uint32_t VHs = KVB + 16384;
        const uint32_t VLs = KVB + 24576;

        float sf[8][4];
#pragma unroll
        for (int j = 0; j < 8; j++)
#pragma unroll
            for (int r = 0; r < 4; r++) sf[j][r] = 0.f;

#pragma unroll
        for (int ks = 0; ks < 4; ks++) {
            uint32_t bhf[16], blf[16];
#pragma unroll
            for (int jj = 0; jj < 4; jj++) {
                uint32_t sw = SW128((uint32_t)(((jj * 2 + (qb2 >> 1)) * 8 + l7) * 128
                                               + (ks * 2 + (qb2 & 1)) * 16));
                LDSM_X4(bhf[4 * jj], bhf[4 * jj + 1], bhf[4 * jj + 2], bhf[4 * jj + 3], KHs + sw);
                LDSM_X4(blf[4 * jj], blf[4 * jj + 1], blf[4 * jj + 2], blf[4 * jj + 3], KLs + sw);
            }
#pragma unroll
            for (int j = 0; j < 8; j++) {
                MMA_BF16(sf[j], &qhf[4 * ks], &bhf[2 * j]);
                MMA_BF16(sf[j], &qhf[4 * ks], &blf[2 * j]);
                MMA_BF16(sf[j], &qlf[4 * ks], &bhf[2 * j]);
            }
        }

        if (k0 + 63 > qr0) {
            const int row0 = qr0 + g, row1 = row0 + 8;
#pragma unroll
            for (int j = 0; j < 8; j++) {
                const int key = k0 + 8 * j + 2 * t;
                if (key     > row0) sf[j][0] = NEG_INF;
                if (key + 1 > row0) sf[j][1] = NEG_INF;
                if (key     > row1) sf[j][2] = NEG_INF;
                if (key + 1 > row1) sf[j][3] = NEG_INF;
            }
        }

        float mx0 = NEG_INF, mx1 = NEG_INF;
#pragma unroll
        for (int j = 0; j < 8; j++) {
            mx0 = fmaxf(mx0, fmaxf(sf[j][0], sf[j][1]));
            mx1 = fmaxf(mx1, fmaxf(sf[j][2], sf[j][3]));
        }
        mx0 = fmaxf(mx0, __shfl_xor_sync(0xffffffffu, mx0, 1));
        mx0 = fmaxf(mx0, __shfl_xor_sync(0xffffffffu, mx0, 2));
        mx1 = fmaxf(mx1, __shfl_xor_sync(0xffffffffu, mx1, 1));
        mx1 = fmaxf(mx1, __shfl_xor_sync(0xffffffffu, mx1, 2));
        const float mn0 = fmaxf(m0, mx0), mn1 = fmaxf(m1, mx1);
        const float a0 = __expf(m0 - mn0), a1 = __expf(m1 - mn1);
        m0 = mn0; m1 = mn1;

        float rs0 = 0.f, rs1 = 0.f;
        uint32_t ph[16], pl[16];
#pragma unroll
        for (int j = 0; j < 8; j++) {
            float p0 = __expf(sf[j][0] - mn0);
            float p1 = __expf(sf[j][1] - mn0);
            float p2 = __expf(sf[j][2] - mn1);
            float p3 = __expf(sf[j][3] - mn1);
            rs0 += p0 + p1;
            rs1 += p2 + p3;
            const int ks2 = j >> 1, hf = j & 1;
            split2(p0, p1, ph[4 * ks2 + 2 * hf],     pl[4 * ks2 + 2 * hf]);
            split2(p2, p3, ph[4 * ks2 + 2 * hf + 1], pl[4 * ks2 + 2 * hf + 1]);
        }
        rs0 += __shfl_xor_sync(0xffffffffu, rs0, 1);
        rs0 += __shfl_xor_sync(0xffffffffu, rs0, 2);
        rs1 += __shfl_xor_sync(0xffffffffu, rs1, 1);
        rs1 += __shfl_xor_sync(0xffffffffu, rs1, 2);
        l0 = l0 * a0 + rs0;
        l1 = l1 * a1 + rs1;

#pragma unroll
        for (int j = 0; j < 8; j++) {
            o[j][0] *= a0; o[j][1] *= a0;
            o[j][2] *= a1; o[j][3] *= a1;
        }

#pragma unroll
        for (int ks = 0; ks < 4; ks++) {
            uint32_t vhf[16], vlf[16];
#pragma unroll
            for (int jj = 0; jj < 4; jj++) {
                uint32_t sw = SW128((uint32_t)(((jj * 2 + (qb2 >> 1)) * 8 + l7) * 128
                                               + (ks * 2 + (qb2 & 1)) * 16));
                LDSM_X4(vhf[4 * jj], vhf[4 * jj + 1], vhf[4 * jj + 2], vhf[4 * jj + 3], VHs + sw);
                LDSM_X4(vlf[4 * jj], vlf[4 * jj + 1], vlf[4 * jj + 2], vlf[4 * jj + 3], VLs + sw);
            }
#pragma unroll
            for (int j = 0; j < 8; j++) {
                MMA_BF16(o[j], &ph[4 * ks], &vhf[2 * j]);
                MMA_BF16(o[j], &ph[4 * ks], &vlf[2 * j]);
                MMA_BF16(o[j], &pl[4 * ks], &vhf[2 * j]);
            }
        }

        __syncthreads();
    }

    const float il0 = 1.f / l0, il1 = 1.f / l1;
    const size_t r0 = (size_t)(b * SEQ + qr0 + g) * D_MODEL + h * DK;
    const size_t r1 = r0 + (size_t)8 * D_MODEL;
#pragma unroll
    for (int j = 0; j < 8; j++) {
        const int c = 8 * j + 2 * t;
        uint32_t hv, lv;
        split2h(o[j][0] * il0, o[j][1] * il0, hv, lv);
        *(uint32_t*)(Ohi + r0 + c) = hv;
        *(uint32_t*)(Olo + r0 + c) = lv;
        split2h(o[j][2] * il1, o[j][3] * il1, hv, lv);
        *(uint32_t*)(Ohi + r1 + c) = hv;
        *(uint32_t*)(Olo + r1 + c) = lv;
    }
}

// ---------------------------------------------------------------------------
extern "C" void kernel_launch(void* const* d_in, const int* in_sizes, int n_in,
                              void* d_out, int out_size)
{
    (void)in_sizes; (void)n_in; (void)out_size;
    const float* x  = (const float*)d_in[0];
    const float* Wq = (const float*)d_in[1];
    const float* Wk = (const float*)d_in[2];
    const float* Wv = (const float*)d_in[3];
    const float* Wo = (const float*)d_in[4];
    float* out = (float*)d_out;

    __half *xhi, *xlo, *ohi, *olo, *whi;
    cudaGetSymbolAddress((void**)&xhi, g_x_hi);
    cudaGetSymbolAddress((void**)&xlo, g_x_lo);
    cudaGetSymbolAddress((void**)&ohi, g_o_hi);
    cudaGetSymbolAddress((void**)&olo, g_o_lo);
    cudaGetSymbolAddress((void**)&whi, g_w_hi);
    __nv_bfloat16 *qh, *ql, *kh, *kl, *vth, *vtl;
    cudaGetSymbolAddress((void**)&qh,  g_qh);
    cudaGetSymbolAddress((void**)&ql,  g_ql);
    cudaGetSymbolAddress((void**)&kh,  g_kh);
    cudaGetSymbolAddress((void**)&kl,  g_kl);
    cudaGetSymbolAddress((void**)&vth, g_vth);
    cudaGetSymbolAddress((void**)&vtl, g_vtl);

    cudaFuncSetAttribute(gemm_qkv, cudaFuncAttributeMaxDynamicSharedMemorySize, GEMM_SMEM);
    cudaFuncSetAttribute(gemm_mma, cudaFuncAttributeMaxDynamicSharedMemorySize, GEMM_SMEM);
    cudaFuncSetAttribute(attn_mma, cudaFuncAttributeMaxDynamicSharedMemorySize, ATT_SMEM);

    const int NW4 = D_MODEL * D_MODEL / 4;   // 262,144
    const int WSZ = D_MODEL * D_MODEL;

    cvt_all<<<dim3(NW4 / 256, 8), 256>>>(x, Wq, Wk, Wv, Wo, xhi, xlo, whi);

    gemm_qkv<<<dim3(D_MODEL / 128, MTOT / 128, 3), 256, GEMM_SMEM>>>(
        xhi, xlo, whi, qh, ql, kh, kl, vth, vtl);

    attn_mma<<<dim3(SEQ / 64, BH), ATT_NT, ATT_SMEM>>>(qh, ql, kh, kl, vth, vtl, ohi, olo);

    gemm_mma<<<dim3(D_MODEL / 128, MTOT / 128), 256, GEMM_SMEM>>>(
        ohi, olo, whi + 3 * WSZ, out);
}

// round 12
// speedup vs baseline: 2.0292x; 1.0229x over previous
#include <cuda_runtime.h>
#include <cuda_bf16.h>
#include <cuda_fp16.h>
#include <cstdint>

#define D_MODEL 1024
#define NHEAD   16
#define DK      64
#define BATCH   2
#define SEQ     2048
#define MTOT    (BATCH * SEQ)   // 4096
#define BH      (BATCH * NHEAD) // 32

#define NEG_INF __int_as_float(0xff800000)

// ---------------------------------------------------------------------------
// Scratch (__device__ globals: allocations are forbidden)
// ---------------------------------------------------------------------------
__device__ __half g_x_hi[MTOT * D_MODEL];
__device__ __half g_x_lo[MTOT * D_MODEL];
__device__ __half g_o_hi[MTOT * D_MODEL];
__device__ __half g_o_lo[MTOT * D_MODEL];
__device__ __half g_w_hi[4][D_MODEL * D_MODEL];   // fp16 hi only (2-pass scheme)

// head-major bf16 hi/lo for attention (unchanged, validated)
__device__ __nv_bfloat16 g_qh[BH * SEQ * DK];
__device__ __nv_bfloat16 g_ql[BH * SEQ * DK];
__device__ __nv_bfloat16 g_kh[BH * SEQ * DK];
__device__ __nv_bfloat16 g_kl[BH * SEQ * DK];
__device__ __nv_bfloat16 g_vth[BH * DK * SEQ];  // transposed: [bh][d][s]
__device__ __nv_bfloat16 g_vtl[BH * DK * SEQ];

// ---------------------------------------------------------------------------
// Base-ISA helpers (NO tcgen05 — harness ptxas targets plain sm_103)
// ---------------------------------------------------------------------------
__device__ __forceinline__ uint32_t smem_to_u32(const void* p) {
    uint32_t a;
    asm("{ .reg .u64 t; cvta.to.shared.u64 t, %1; cvt.u32.u64 %0, t; }" : "=r"(a) : "l"(p));
    return a;
}
#define SW128(o) ((o) ^ (((o) >> 3) & 0x70))

#define CP_ASYNC16(dst, src) \
    asm volatile("cp.async.cg.shared.global [%0], [%1], 16;" :: "r"(dst), "l"(src))
#define CP_COMMIT() asm volatile("cp.async.commit_group;" ::: "memory")
#define CP_WAIT(n)  asm volatile("cp.async.wait_group %0;" :: "n"(n) : "memory")

#define LDSM_X4(r0, r1, r2, r3, addr) \
    asm volatile("ldmatrix.sync.aligned.m8n8.x4.shared.b16 {%0,%1,%2,%3}, [%4];" \
                 : "=r"(r0), "=r"(r1), "=r"(r2), "=r"(r3) : "r"(addr))

#define MMA_BF16(c, a, b) \
    asm volatile("mma.sync.aligned.m16n8k16.row.col.f32.bf16.bf16.f32 " \
                 "{%0,%1,%2,%3}, {%4,%5,%6,%7}, {%8,%9}, {%0,%1,%2,%3};" \
                 : "+f"((c)[0]), "+f"((c)[1]), "+f"((c)[2]), "+f"((c)[3]) \
                 : "r"((a)[0]), "r"((a)[1]), "r"((a)[2]), "r"((a)[3]), \
                   "r"((b)[0]), "r"((b)[1]))

#define MMA_F16(c, a, b) \
    asm volatile("mma.sync.aligned.m16n8k16.row.col.f32.f16.f16.f32 " \
                 "{%0,%1,%2,%3}, {%4,%5,%6,%7}, {%8,%9}, {%0,%1,%2,%3};" \
                 : "+f"((c)[0]), "+f"((c)[1]), "+f"((c)[2]), "+f"((c)[3]) \
                 : "r"((a)[0]), "r"((a)[1]), "r"((a)[2]), "r"((a)[3]), \
                   "r"((b)[0]), "r"((b)[1]))

__device__ __forceinline__ void split2(float x, float y, uint32_t& hi, uint32_t& lo) {
    __nv_bfloat16 hx = __float2bfloat16(x), hy = __float2bfloat16(y);
    __nv_bfloat16 lx = __float2bfloat16(x - __bfloat162float(hx));
    __nv_bfloat16 ly = __float2bfloat16(y - __bfloat162float(hy));
    __nv_bfloat162 th(hx, hy), tl(lx, ly);
    hi = *(uint32_t*)&th;
    lo = *(uint32_t*)&tl;
}

__device__ __forceinline__ void split2h(float x, float y, uint32_t& hi, uint32_t& lo) {
    __half hx = __float2half_rn(x), hy = __float2half_rn(y);
    __half lx = __float2half_rn(x - __half2float(hx));
    __half ly = __float2half_rn(y - __half2float(hy));
    __half2 th(hx, hy), tl(lx, ly);
    hi = *(uint32_t*)&th;
    lo = *(uint32_t*)&tl;
}

// ---------------------------------------------------------------------------
// fp32 -> fp16 conversion, one launch: weights (hi only) + x (hi/lo split)
// ---------------------------------------------------------------------------
__global__ __launch_bounds__(256)
void cvt_all(const float* __restrict__ x,
             const float* __restrict__ w0, const float* __restrict__ w1,
             const float* __restrict__ w2, const float* __restrict__ w3,
             __half* __restrict__ xhi, __half* __restrict__ xlo,
             __half* __restrict__ whi)
{
    const int y = blockIdx.y;
    const size_t WSZ4 = (size_t)D_MODEL * D_MODEL / 4;
    int i = blockIdx.x * 256 + threadIdx.x;
    if (y < 4) {
        const float* src = (y == 0) ? w0 : (y == 1) ? w1 : (y == 2) ? w2 : w3;
        __half* hi = whi + (size_t)y * D_MODEL * D_MODEL;
        float4 v = ((const float4*)src)[i];
        __half2 a(__float2half_rn(v.x), __float2half_rn(v.y));
        __half2 b(__float2half_rn(v.z), __float2half_rn(v.w));
        ((uint32_t*)hi)[2 * i]     = *(uint32_t*)&a;
        ((uint32_t*)hi)[2 * i + 1] = *(uint32_t*)&b;
    } else {
        const float* src = x + (size_t)(y - 4) * WSZ4 * 4;
        __half* hi = xhi + (size_t)(y - 4) * WSZ4 * 4;
        __half* lo = xlo + (size_t)(y - 4) * WSZ4 * 4;
        float4 v = ((const float4*)src)[i];
        uint32_t h0, l0, h1, l1;
        split2h(v.x, v.y, h0, l0);
        split2h(v.z, v.w, h1, l1);
        ((uint32_t*)hi)[2 * i] = h0;     ((uint32_t*)hi)[2 * i + 1] = h1;
        ((uint32_t*)lo)[2 * i] = l0;     ((uint32_t*)lo)[2 * i + 1] = l1;
    }
}

// ---------------------------------------------------------------------------
// GEMM core — fp16 2-pass: C = (Ahi + Alo) * Bhi
// 128x128 CTA tile, 8 warps (2x4), warp tile 64x32, KC=64, double buffering.
// NEW (R12): regs capped via __launch_bounds__(256, 2) -> 2 CTAs/SM.
// ---------------------------------------------------------------------------
#define KC        64
#define NCHUNK    (D_MODEL / KC)      // 16
#define TILE_B    16384
#define BUF_B     (3 * TILE_B)
#define GEMM_SMEM (2 * BUF_B)         // 98304

__device__ __forceinline__ void cp_tile(uint32_t dst_base, const __half* src, int tid)
{
#pragma unroll
    for (int u = tid; u < 1024; u += 256) {
        int row = u >> 3, c = u & 7;
        uint32_t off = row * 128 + c * 16;
        CP_ASYNC16(dst_base + SW128(off), src + (size_t)row * D_MODEL + c * 8);
    }
}

__device__ __forceinline__ void gemm_mainloop(
    uint32_t sbase, int tid, int lane, int m0, int n0,
    const __half* pAh, const __half* pAl, const __half* pBh,
    float acc[4][4][4])
{
#pragma unroll
    for (int i = 0; i < 4; i++)
#pragma unroll
        for (int j = 0; j < 4; j++)
#pragma unroll
            for (int r = 0; r < 4; r++) acc[i][j][r] = 0.f;

    const int ra = lane & 15;
    const int ca = lane >> 4;
    const int qb = lane >> 3;
    const int l7 = lane & 7;

    cp_tile(sbase + 0 * TILE_B, pAh, tid);
    cp_tile(sbase + 1 * TILE_B, pAl, tid);
    cp_tile(sbase + 2 * TILE_B, pBh, tid);
    CP_COMMIT();

    for (int ch = 0; ch < NCHUNK; ch++) {
        const int buf = ch & 1;
        if (ch + 1 < NCHUNK) {
            const uint32_t nb = sbase + (buf ^ 1) * BUF_B;
            const int kc = (ch + 1) * KC;
            cp_tile(nb + 0 * TILE_B, pAh + kc, tid);
            cp_tile(nb + 1 * TILE_B, pAl + kc, tid);
            cp_tile(nb + 2 * TILE_B, pBh + kc, tid);
            CP_COMMIT();
            CP_WAIT(1);
        } else {
            CP_WAIT(0);
        }
        __syncthreads();

        const uint32_t aH = sbase + buf * BUF_B + 0 * TILE_B;
        const uint32_t aL = sbase + buf * BUF_B + 1 * TILE_B;
        const uint32_t bH = sbase + buf * BUF_B + 2 * TILE_B;

#pragma unroll
        for (int ks = 0; ks < 4; ks++) {
            uint32_t ah[16], al[16];
#pragma unroll
            for (int i = 0; i < 4; i++) {
                uint32_t off = (uint32_t)(m0 + i * 16 + ra) * 128 + (ks * 2 + ca) * 16;
                uint32_t sw = SW128(off);
                LDSM_X4(ah[4 * i], ah[4 * i + 1], ah[4 * i + 2], ah[4 * i + 3], aH + sw);
                LDSM_X4(al[4 * i], al[4 * i + 1], al[4 * i + 2], al[4 * i + 3], aL + sw);
            }
            uint32_t bh[8];
#pragma unroll
            for (int jj = 0; jj < 2; jj++) {
                uint32_t off = (uint32_t)(n0 + (jj * 2 + (qb >> 1)) * 8 + l7) * 128
                             + (ks * 2 + (qb & 1)) * 16;
                uint32_t sw = SW128(off);
                LDSM_X4(bh[4 * jj], bh[4 * jj + 1], bh[4 * jj + 2], bh[4 * jj + 3], bH + sw);
            }
#pragma unroll
            for (int i = 0; i < 4; i++)
#pragma unroll
                for (int j = 0; j < 4; j++) {
                    MMA_F16(acc[i][j], &ah[4 * i], &bh[2 * j]);
                    MMA_F16(acc[i][j], &al[4 * i], &bh[2 * j]);
                }
        }
        __syncthreads();
    }
}

// ---------------------------------------------------------------------------
// QKV projections, one launch (grid.z = 0:Q, 1:K, 2:V).
// ---------------------------------------------------------------------------
__global__ __launch_bounds__(256, 2)
void gemm_qkv(const __half* __restrict__ Ahi, const __half* __restrict__ Alo,
              const __half* __restrict__ Whi,
              __nv_bfloat16* __restrict__ qh, __nv_bfloat16* __restrict__ ql,
              __nv_bfloat16* __restrict__ kh, __nv_bfloat16* __restrict__ kl,
              __nv_bfloat16* __restrict__ vth, __nv_bfloat16* __restrict__ vtl)
{
    extern __shared__ char smem[];
    const uint32_t sbase = smem_to_u32(smem);
    const int tid = threadIdx.x;
    const int wid = tid >> 5, lane = tid & 31;
    const int bm = blockIdx.y * 128;
    const int bn = blockIdx.x * 128;
    const int z  = blockIdx.z;
    const int m0 = (wid & 1) * 64;
    const int n0 = (wid >> 1) * 32;

    float acc[4][4][4];
    gemm_mainloop(sbase, tid, lane, m0, n0,
                  Ahi + (size_t)bm * D_MODEL,
                  Alo + (size_t)bm * D_MODEL,
                  Whi + (size_t)z * D_MODEL * D_MODEL + (size_t)bn * D_MODEL,
                  acc);

    const int g = lane >> 2, t = lane & 3;

    if (z == 2) {
#pragma unroll
        for (int i = 0; i < 4; i++) {
#pragma unroll
            for (int j = 0; j < 4; j++) {
                const int c  = bn + n0 + j * 8 + 2 * t;
                const int hh = c >> 6, d0 = c & 63;
#pragma unroll
                for (int rr = 0; rr < 4; rr++) {
                    const int row = bm + m0 + i * 16 + g + ((rr >> 1) * 8);
                    const int b = row >> 11, s = row & (SEQ - 1);
                    const int d = d0 + (rr & 1);
                    float v = acc[i][j][rr];
                    __nv_bfloat16 hv = __float2bfloat16(v);
                    __nv_bfloat16 lv = __float2bfloat16(v - __bfloat162float(hv));
                    const size_t dst = ((size_t)((b * NHEAD + hh) * DK + d)) * SEQ + s;
                    vth[dst] = hv;
                    vtl[dst] = lv;
                }
            }
        }
    } else {
        __nv_bfloat16* Hi = (z == 0) ? qh : kh;
        __nv_bfloat16* Lo = (z == 0) ? ql : kl;
        const float sc = (z == 0) ? 0.125f : 1.0f;
#pragma unroll
        for (int i = 0; i < 4; i++) {
#pragma unroll
            for (int j = 0; j < 4; j++) {
                const int c  = bn + n0 + j * 8 + 2 * t;
                const int hh = c >> 6, d = c & 63;
                const int row0 = bm + m0 + i * 16 + g;
                uint32_t hv, lv;
                {
                    const int b = row0 >> 11, s = row0 & (SEQ - 1);
                    split2(acc[i][j][0] * sc, acc[i][j][1] * sc, hv, lv);
                    const size_t dst = ((size_t)((b * NHEAD + hh) * SEQ + s)) * DK + d;
                    *(uint32_t*)(Hi + dst) = hv;
                    *(uint32_t*)(Lo + dst) = lv;
                }
                {
                    const int row1 = row0 + 8;
                    const int b = row1 >> 11, s = row1 & (SEQ - 1);
                    split2(acc[i][j][2] * sc, acc[i][j][3] * sc, hv, lv);
                    const size_t dst = ((size_t)((b * NHEAD + hh) * SEQ + s)) * DK + d;
                    *(uint32_t*)(Hi + dst) = hv;
                    *(uint32_t*)(Lo + dst) = lv;
                }
            }
        }
    }
}

// ---------------------------------------------------------------------------
// Output projection GEMM (fp32 result to d_out)
// ---------------------------------------------------------------------------
__global__ __launch_bounds__(256, 2)
void gemm_mma(const __half* __restrict__ Ahi, const __half* __restrict__ Alo,
              const __half* __restrict__ Bhi, float* __restrict__ C)
{
    extern __shared__ char smem[];
    const uint32_t sbase = smem_to_u32(smem);
    const int tid = threadIdx.x;
    const int wid = tid >> 5, lane = tid & 31;
    const int bm = blockIdx.y * 128;
    const int bn = blockIdx.x * 128;
    const int m0 = (wid & 1) * 64;
    const int n0 = (wid >> 1) * 32;

    float acc[4][4][4];
    gemm_mainloop(sbase, tid, lane, m0, n0,
                  Ahi + (size_t)bm * D_MODEL,
                  Alo + (size_t)bm * D_MODEL,
                  Bhi + (size_t)bn * D_MODEL,
                  acc);

    const int g = lane >> 2, t = lane & 3;
#pragma unroll
    for (int i = 0; i < 4; i++) {
#pragma unroll
        for (int j = 0; j < 4; j++) {
            float* cp0 = C + (size_t)(bm + m0 + i * 16 + g) * D_MODEL + bn + n0 + j * 8 + 2 * t;
            float* cp1 = cp0 + 8 * D_MODEL;
            *(float2*)cp0 = make_float2(acc[i][j][0], acc[i][j][1]);
            *(float2*)cp1 = make_float2(acc[i][j][2], acc[i][j][3]);
        }
    }
}

// ---------------------------------------------------------------------------
// Tensor-core causal flash attention (validated R10/R11: 4 warps / 64 q-rows,
// 2 CTAs/SM). Internals bf16 3-pass; output written as fp16 hi/lo.
// ---------------------------------------------------------------------------
#define ATT_NT   128
#define ATT_SMEM (16384 + 32768)   // Q(hi+lo, 64 rows) + one KV buffer

__global__ __launch_bounds__(ATT_NT, 2)
void attn_mma(const __nv_bfloat16* __restrict__ Qh, const __nv_bfloat16* __restrict__ Ql,
              const __nv_bfloat16* __restrict__ Kh, const __nv_bfloat16* __restrict__ Kl,
              const __nv_bfloat16* __restrict__ Vh, const __nv_bfloat16* __restrict__ Vl,
              __half* __restrict__ Ohi, __half* __restrict__ Olo)
{
    extern __shared__ char smem[];
    const uint32_t sb = smem_to_u32(smem);
    const int tid = threadIdx.x, wid = tid >> 5, lane = tid & 31;
    const int qblk = gridDim.x - 1 - blockIdx.x;   // heavy CTAs first
    const int bh = blockIdx.y;
    const int b = bh >> 4, h = bh & 15;
    const int qr0 = qblk * 64 + wid * 16;
    const int g = lane >> 2, t = lane & 3;
    const int qb2 = lane >> 3, l7 = lane & 7;
    const int ra = lane & 15, ca = lane >> 4;

    const uint32_t QH = sb, QL = sb + 8192;
    const uint32_t KVB = sb + 16384;   // KH +0, KL +8192, VH +16384, VL +24576

    {
        const __nv_bfloat16* qh_g = Qh + ((size_t)bh * SEQ + qblk * 64) * DK;
        const __nv_bfloat16* ql_g = Ql + ((size_t)bh * SEQ + qblk * 64) * DK;
#pragma unroll
        for (int u = tid; u < 512; u += ATT_NT) {
            int row = u >> 3, c = u & 7;
            uint32_t sw = SW128((uint32_t)(row * 128 + c * 16));
            CP_ASYNC16(QH + sw, qh_g + (size_t)row * DK + c * 8);
            CP_ASYNC16(QL + sw, ql_g + (size_t)row * DK + c * 8);
        }
        CP_COMMIT();
        CP_WAIT(0);
        __syncthreads();
    }

    uint32_t qhf[16], qlf[16];
#pragma unroll
    for (int ks = 0; ks < 4; ks++) {
        uint32_t sw = SW128((uint32_t)((wid * 16 + ra) * 128 + (ks * 2 + ca) * 16));
        LDSM_X4(qhf[4 * ks], qhf[4 * ks + 1], qhf[4 * ks + 2], qhf[4 * ks + 3], QH + sw);
        LDSM_X4(qlf[4 * ks], qlf[4 * ks + 1], qlf[4 * ks + 2], qlf[4 * ks + 3], QL + sw);
    }

    float o[8][4];
#pragma unroll
    for (int j = 0; j < 8; j++)
#pragma unroll
        for (int r = 0; r < 4; r++) o[j][r] = 0.f;
    float m0 = NEG_INF, m1 = NEG_INF, l0 = 0.f, l1 = 0.f;

    const int nkb = qblk + 1;

    for (int kb = 0; kb < nkb; kb++) {
        const int k0 = kb * 64;

#pragma unroll
        for (int u = tid; u < 512; u += ATT_NT) {
            int r = u >> 3, c = u & 7;
            uint32_t sw = SW128((uint32_t)(r * 128 + c * 16));
            const size_t kg = ((size_t)bh * SEQ + k0 + r) * DK + c * 8;
            CP_ASYNC16(KVB + sw,         Kh + kg);
            CP_ASYNC16(KVB + 8192 + sw,  Kl + kg);
            const size_t vg = ((size_t)bh * DK + r) * SEQ + k0 + c * 8;
            CP_ASYNC16(KVB + 16384 + sw, Vh + vg);
            CP_ASYNC16(KVB + 24576 + sw, Vl + vg);
        }
        CP_COMMIT();
        CP_WAIT(0);
        __syncthreads();

        const uint32_t KHs = KVB;
        const uint32_t KLs = KVB + 8192;
        const uint32_t VHs = KVB + 16384;
        const uint32_t VLs = KVB + 24576;

        float sf[8][4];
#pragma unroll
        for (int j = 0; j < 8; j++)
#pragma unroll
            for (int r = 0; r < 4; r++) sf[j][r] = 0.f;

#pragma unroll
        for (int ks = 0; ks < 4; ks++) {
            uint32_t bhf[16], blf[16];
#pragma unroll
            for (int jj = 0; jj < 4; jj++) {
                uint32_t sw = SW128((uint32_t)(((jj * 2 + (qb2 >> 1)) * 8 + l7) * 128
                                               + (ks * 2 + (qb2 & 1)) * 16));
                LDSM_X4(bhf[4 * jj], bhf[4 * jj + 1], bhf[4 * jj + 2], bhf[4 * jj + 3], KHs + sw);
                LDSM_X4(blf[4 * jj], blf[4 * jj + 1], blf[4 * jj + 2], blf[4 * jj + 3], KLs + sw);
            }
#pragma unroll
            for (int j = 0; j < 8; j++) {
                MMA_BF16(sf[j], &qhf[4 * ks], &bhf[2 * j]);
                MMA_BF16(sf[j], &qhf[4 * ks], &blf[2 * j]);
                MMA_BF16(sf[j], &qlf[4 * ks], &bhf[2 * j]);
            }
        }

        if (k0 + 63 > qr0) {
            const int row0 = qr0 + g, row1 = row0 + 8;
#pragma unroll
            for (int j = 0; j < 8; j++) {
                const int key = k0 + 8 * j + 2 * t;
                if (key     > row0) sf[j][0] = NEG_INF;
                if (key + 1 > row0) sf[j][1] = NEG_INF;
                if (key     > row1) sf[j][2] = NEG_INF;
                if (key + 1 > row1) sf[j][3] = NEG_INF;
            }
        }

        float mx0 = NEG_INF, mx1 = NEG_INF;
#pragma unroll
        for (int j = 0; j < 8; j++) {
            mx0 = fmaxf(mx0, fmaxf(sf[j][0], sf[j][1]));
            mx1 = fmaxf(mx1, fmaxf(sf[j][2], sf[j][3]));
        }
        mx0 = fmaxf(mx0, __shfl_xor_sync(0xffffffffu, mx0, 1));
        mx0 = fmaxf(mx0, __shfl_xor_sync(0xffffffffu, mx0, 2));
        mx1 = fmaxf(mx1, __shfl_xor_sync(0xffffffffu, mx1, 1));
        mx1 = fmaxf(mx1, __shfl_xor_sync(0xffffffffu, mx1, 2));
        const float mn0 = fmaxf(m0, mx0), mn1 = fmaxf(m1, mx1);
        const float a0 = __expf(m0 - mn0), a1 = __expf(m1 - mn1);
        m0 = mn0; m1 = mn1;

        float rs0 = 0.f, rs1 = 0.f;
        uint32_t ph[16], pl[16];
#pragma unroll
        for (int j = 0; j < 8; j++) {
            float p0 = __expf(sf[j][0] - mn0);
            float p1 = __expf(sf[j][1] - mn0);
            float p2 = __expf(sf[j][2] - mn1);
            float p3 = __expf(sf[j][3] - mn1);
            rs0 += p0 + p1;
            rs1 += p2 + p3;
            const int ks2 = j >> 1, hf = j & 1;
            split2(p0, p1, ph[4 * ks2 + 2 * hf],     pl[4 * ks2 + 2 * hf]);
            split2(p2, p3, ph[4 * ks2 + 2 * hf + 1], pl[4 * ks2 + 2 * hf + 1]);
        }
        rs0 += __shfl_xor_sync(0xffffffffu, rs0, 1);
        rs0 += __shfl_xor_sync(0xffffffffu, rs0, 2);
        rs1 += __shfl_xor_sync(0xffffffffu, rs1, 1);
        rs1 += __shfl_xor_sync(0xffffffffu, rs1, 2);
        l0 = l0 * a0 + rs0;
        l1 = l1 * a1 + rs1;

#pragma unroll
        for (int j = 0; j < 8; j++) {
            o[j][0] *= a0; o[j][1] *= a0;
            o[j][2] *= a1; o[j][3] *= a1;
        }

#pragma unroll
        for (int ks = 0; ks < 4; ks++) {
            uint32_t vhf[16], vlf[16];
#pragma unroll
            for (int jj = 0; jj < 4; jj++) {
                uint32_t sw = SW128((uint32_t)(((jj * 2 + (qb2 >> 1)) * 8 + l7) * 128
                                               + (ks * 2 + (qb2 & 1)) * 16));
                LDSM_X4(vhf[4 * jj], vhf[4 * jj + 1], vhf[4 * jj + 2], vhf[4 * jj + 3], VHs + sw);
                LDSM_X4(vlf[4 * jj], vlf[4 * jj + 1], vlf[4 * jj + 2], vlf[4 * jj + 3], VLs + sw);
            }
#pragma unroll
            for (int j = 0; j < 8; j++) {
                MMA_BF16(o[j], &ph[4 * ks], &vhf[2 * j]);
                MMA_BF16(o[j], &ph[4 * ks], &vlf[2 * j]);
                MMA_BF16(o[j], &pl[4 * ks], &vhf[2 * j]);
            }
        }

        __syncthreads();
    }

    const float il0 = 1.f / l0, il1 = 1.f / l1;
    const size_t r0 = (size_t)(b * SEQ + qr0 + g) * D_MODEL + h * DK;
    const size_t r1 = r0 + (size_t)8 * D_MODEL;
#pragma unroll
    for (int j = 0; j < 8; j++) {
        const int c = 8 * j + 2 * t;
        uint32_t hv, lv;
        split2h(o[j][0] * il0, o[j][1] * il0, hv, lv);
        *(uint32_t*)(Ohi + r0 + c) = hv;
        *(uint32_t*)(Olo + r0 + c) = lv;
        split2h(o[j][2] * il1, o[j][3] * il1, hv, lv);
        *(uint32_t*)(Ohi + r1 + c) = hv;
        *(uint32_t*)(Olo + r1 + c) = lv;
    }
}

// ---------------------------------------------------------------------------
extern "C" void kernel_launch(void* const* d_in, const int* in_sizes, int n_in,
                              void* d_out, int out_size)
{
    (void)in_sizes; (void)n_in; (void)out_size;
    const float* x  = (const float*)d_in[0];
    const float* Wq = (const float*)d_in[1];
    const float* Wk = (const float*)d_in[2];
    const float* Wv = (const float*)d_in[3];
    const float* Wo = (const float*)d_in[4];
    float* out = (float*)d_out;

    __half *xhi, *xlo, *ohi, *olo, *whi;
    cudaGetSymbolAddress((void**)&xhi, g_x_hi);
    cudaGetSymbolAddress((void**)&xlo, g_x_lo);
    cudaGetSymbolAddress((void**)&ohi, g_o_hi);
    cudaGetSymbolAddress((void**)&olo, g_o_lo);
    cudaGetSymbolAddress((void**)&whi, g_w_hi);
    __nv_bfloat16 *qh, *ql, *kh, *kl, *vth, *vtl;
    cudaGetSymbolAddress((void**)&qh,  g_qh);
    cudaGetSymbolAddress((void**)&ql,  g_ql);
    cudaGetSymbolAddress((void**)&kh,  g_kh);
    cudaGetSymbolAddress((void**)&kl,  g_kl);
    cudaGetSymbolAddress((void**)&vth, g_vth);
    cudaGetSymbolAddress((void**)&vtl, g_vtl);

    cudaFuncSetAttribute(gemm_qkv, cudaFuncAttributeMaxDynamicSharedMemorySize, GEMM_SMEM);
    cudaFuncSetAttribute(gemm_mma, cudaFuncAttributeMaxDynamicSharedMemorySize, GEMM_SMEM);
    cudaFuncSetAttribute(attn_mma, cudaFuncAttributeMaxDynamicSharedMemorySize, ATT_SMEM);

    const int NW4 = D_MODEL * D_MODEL / 4;   // 262,144
    const int WSZ = D_MODEL * D_MODEL;

    cvt_all<<<dim3(NW4 / 256, 8), 256>>>(x, Wq, Wk, Wv, Wo, xhi, xlo, whi);

    gemm_qkv<<<dim3(D_MODEL / 128, MTOT / 128, 3), 256, GEMM_SMEM>>>(
        xhi, xlo, whi, qh, ql, kh, kl, vth, vtl);

    attn_mma<<<dim3(SEQ / 64, BH), ATT_NT, ATT_SMEM>>>(qh, ql, kh, kl, vth, vtl, ohi, olo);

    gemm_mma<<<dim3(D_MODEL / 128, MTOT / 128), 256, GEMM_SMEM>>>(
        ohi, olo, whi + 3 * WSZ, out);
}

// round 13
// speedup vs baseline: 2.3132x; 1.1400x over previous
#include <cuda_runtime.h>
#include <cuda_bf16.h>
#include <cuda_fp16.h>
#include <cstdint>

#define D_MODEL 1024
#define NHEAD   16
#define DK      64
#define BATCH   2
#define SEQ     2048
#define MTOT    (BATCH * SEQ)   // 4096
#define BH      (BATCH * NHEAD) // 32

#define NEG_INF __int_as_float(0xff800000)

// ---------------------------------------------------------------------------
// Scratch (__device__ globals: allocations are forbidden)
// ---------------------------------------------------------------------------
__device__ __half g_x_hi[MTOT * D_MODEL];
__device__ __half g_x_lo[MTOT * D_MODEL];
__device__ __half g_o_hi[MTOT * D_MODEL];
__device__ __half g_o_lo[MTOT * D_MODEL];
__device__ __half g_w_hi[4][D_MODEL * D_MODEL];   // fp16 hi only (2-pass scheme)

// head-major fp16 for attention (R13: fp16 2-pass attention)
__device__ __half g_qh[BH * SEQ * DK];
__device__ __half g_ql[BH * SEQ * DK];
__device__ __half g_kh[BH * SEQ * DK];            // K hi only
__device__ __half g_vth[BH * DK * SEQ];           // transposed: [bh][d][s]
__device__ __half g_vtl[BH * DK * SEQ];

// ---------------------------------------------------------------------------
// Base-ISA helpers (NO tcgen05 — harness ptxas targets plain sm_103)
// ---------------------------------------------------------------------------
__device__ __forceinline__ uint32_t smem_to_u32(const void* p) {
    uint32_t a;
    asm("{ .reg .u64 t; cvta.to.shared.u64 t, %1; cvt.u32.u64 %0, t; }" : "=r"(a) : "l"(p));
    return a;
}
#define SW128(o) ((o) ^ (((o) >> 3) & 0x70))

#define CP_ASYNC16(dst, src) \
    asm volatile("cp.async.cg.shared.global [%0], [%1], 16;" :: "r"(dst), "l"(src))
#define CP_COMMIT() asm volatile("cp.async.commit_group;" ::: "memory")
#define CP_WAIT(n)  asm volatile("cp.async.wait_group %0;" :: "n"(n) : "memory")

#define LDSM_X4(r0, r1, r2, r3, addr) \
    asm volatile("ldmatrix.sync.aligned.m8n8.x4.shared.b16 {%0,%1,%2,%3}, [%4];" \
                 : "=r"(r0), "=r"(r1), "=r"(r2), "=r"(r3) : "r"(addr))

#define MMA_F16(c, a, b) \
    asm volatile("mma.sync.aligned.m16n8k16.row.col.f32.f16.f16.f32 " \
                 "{%0,%1,%2,%3}, {%4,%5,%6,%7}, {%8,%9}, {%0,%1,%2,%3};" \
                 : "+f"((c)[0]), "+f"((c)[1]), "+f"((c)[2]), "+f"((c)[3]) \
                 : "r"((a)[0]), "r"((a)[1]), "r"((a)[2]), "r"((a)[3]), \
                   "r"((b)[0]), "r"((b)[1]))

__device__ __forceinline__ void split2h(float x, float y, uint32_t& hi, uint32_t& lo) {
    __half hx = __float2half_rn(x), hy = __float2half_rn(y);
    __half lx = __float2half_rn(x - __half2float(hx));
    __half ly = __float2half_rn(y - __half2float(hy));
    __half2 th(hx, hy), tl(lx, ly);
    hi = *(uint32_t*)&th;
    lo = *(uint32_t*)&tl;
}

__device__ __forceinline__ uint32_t pack_h2(float x, float y) {
    __half2 t(__float2half_rn(x), __float2half_rn(y));
    return *(uint32_t*)&t;
}

// ---------------------------------------------------------------------------
// fp32 -> fp16 conversion, one launch: weights (hi only) + x (hi/lo split)
// ---------------------------------------------------------------------------
__global__ __launch_bounds__(256)
void cvt_all(const float* __restrict__ x,
             const float* __restrict__ w0, const float* __restrict__ w1,
             const float* __restrict__ w2, const float* __restrict__ w3,
             __half* __restrict__ xhi, __half* __restrict__ xlo,
             __half* __restrict__ whi)
{
    const int y = blockIdx.y;
    const size_t WSZ4 = (size_t)D_MODEL * D_MODEL / 4;
    int i = blockIdx.x * 256 + threadIdx.x;
    if (y < 4) {
        const float* src = (y == 0) ? w0 : (y == 1) ? w1 : (y == 2) ? w2 : w3;
        __half* hi = whi + (size_t)y * D_MODEL * D_MODEL;
        float4 v = ((const float4*)src)[i];
        ((uint32_t*)hi)[2 * i]     = pack_h2(v.x, v.y);
        ((uint32_t*)hi)[2 * i + 1] = pack_h2(v.z, v.w);
    } else {
        const float* src = x + (size_t)(y - 4) * WSZ4 * 4;
        __half* hi = xhi + (size_t)(y - 4) * WSZ4 * 4;
        __half* lo = xlo + (size_t)(y - 4) * WSZ4 * 4;
        float4 v = ((const float4*)src)[i];
        uint32_t h0, l0, h1, l1;
        split2h(v.x, v.y, h0, l0);
        split2h(v.z, v.w, h1, l1);
        ((uint32_t*)hi)[2 * i] = h0;     ((uint32_t*)hi)[2 * i + 1] = h1;
        ((uint32_t*)lo)[2 * i] = l0;     ((uint32_t*)lo)[2 * i + 1] = l1;
    }
}

// ---------------------------------------------------------------------------
// GEMM core — fp16 2-pass: C = (Ahi + Alo) * Bhi (validated R11/R12 config)
// ---------------------------------------------------------------------------
#define KC        64
#define NCHUNK    (D_MODEL / KC)      // 16
#define TILE_B    16384
#define BUF_B     (3 * TILE_B)
#define GEMM_SMEM (2 * BUF_B)         // 98304

__device__ __forceinline__ void cp_tile(uint32_t dst_base, const __half* src, int tid)
{
#pragma unroll
    for (int u = tid; u < 1024; u += 256) {
        int row = u >> 3, c = u & 7;
        uint32_t off = row * 128 + c * 16;
        CP_ASYNC16(dst_base + SW128(off), src + (size_t)row * D_MODEL + c * 8);
    }
}

__device__ __forceinline__ void gemm_mainloop(
    uint32_t sbase, int tid, int lane, int m0, int n0,
    const __half* pAh, const __half* pAl, const __half* pBh,
    float acc[4][4][4])
{
#pragma unroll
    for (int i = 0; i < 4; i++)
#pragma unroll
        for (int j = 0; j < 4; j++)
#pragma unroll
            for (int r = 0; r < 4; r++) acc[i][j][r] = 0.f;

    const int ra = lane & 15;
    const int ca = lane >> 4;
    const int qb = lane >> 3;
    const int l7 = lane & 7;

    cp_tile(sbase + 0 * TILE_B, pAh, tid);
    cp_tile(sbase + 1 * TILE_B, pAl, tid);
    cp_tile(sbase + 2 * TILE_B, pBh, tid);
    CP_COMMIT();

    for (int ch = 0; ch < NCHUNK; ch++) {
        const int buf = ch & 1;
        if (ch + 1 < NCHUNK) {
            const uint32_t nb = sbase + (buf ^ 1) * BUF_B;
            const int kc = (ch + 1) * KC;
            cp_tile(nb + 0 * TILE_B, pAh + kc, tid);
            cp_tile(nb + 1 * TILE_B, pAl + kc, tid);
            cp_tile(nb + 2 * TILE_B, pBh + kc, tid);
            CP_COMMIT();
            CP_WAIT(1);
        } else {
            CP_WAIT(0);
        }
        __syncthreads();

        const uint32_t aH = sbase + buf * BUF_B + 0 * TILE_B;
        const uint32_t aL = sbase + buf * BUF_B + 1 * TILE_B;
        const uint32_t bH = sbase + buf * BUF_B + 2 * TILE_B;

#pragma unroll
        for (int ks = 0; ks < 4; ks++) {
            uint32_t ah[16], al[16];
#pragma unroll
            for (int i = 0; i < 4; i++) {
                uint32_t off = (uint32_t)(m0 + i * 16 + ra) * 128 + (ks * 2 + ca) * 16;
                uint32_t sw = SW128(off);
                LDSM_X4(ah[4 * i], ah[4 * i + 1], ah[4 * i + 2], ah[4 * i + 3], aH + sw);
                LDSM_X4(al[4 * i], al[4 * i + 1], al[4 * i + 2], al[4 * i + 3], aL + sw);
            }
            uint32_t bh[8];
#pragma unroll
            for (int jj = 0; jj < 2; jj++) {
                uint32_t off = (uint32_t)(n0 + (jj * 2 + (qb >> 1)) * 8 + l7) * 128
                             + (ks * 2 + (qb & 1)) * 16;
                uint32_t sw = SW128(off);
                LDSM_X4(bh[4 * jj], bh[4 * jj + 1], bh[4 * jj + 2], bh[4 * jj + 3], bH + sw);
            }
#pragma unroll
            for (int i = 0; i < 4; i++)
#pragma unroll
                for (int j = 0; j < 4; j++) {
                    MMA_F16(acc[i][j], &ah[4 * i], &bh[2 * j]);
                    MMA_F16(acc[i][j], &al[4 * i], &bh[2 * j]);
                }
        }
        __syncthreads();
    }
}

// ---------------------------------------------------------------------------
// QKV projections, one launch (grid.z = 0:Q, 1:K, 2:V).
// Epilogue writes attention-ready fp16 layouts:
//   Q: head-major [bh][s][64] hi/lo, pre-scaled by 1/8
//   K: head-major [bh][s][64] hi only
//   V: transposed  [bh][d][s] hi/lo
// ---------------------------------------------------------------------------
__global__ __launch_bounds__(256, 2)
void gemm_qkv(const __half* __restrict__ Ahi, const __half* __restrict__ Alo,
              const __half* __restrict__ Whi,
              __half* __restrict__ qh, __half* __restrict__ ql,
              __half* __restrict__ kh,
              __half* __restrict__ vth, __half* __restrict__ vtl)
{
    extern __shared__ char smem[];
    const uint32_t sbase = smem_to_u32(smem);
    const int tid = threadIdx.x;
    const int wid = tid >> 5, lane = tid & 31;
    const int bm = blockIdx.y * 128;
    const int bn = blockIdx.x * 128;
    const int z  = blockIdx.z;
    const int m0 = (wid & 1) * 64;
    const int n0 = (wid >> 1) * 32;

    float acc[4][4][4];
    gemm_mainloop(sbase, tid, lane, m0, n0,
                  Ahi + (size_t)bm * D_MODEL,
                  Alo + (size_t)bm * D_MODEL,
                  Whi + (size_t)z * D_MODEL * D_MODEL + (size_t)bn * D_MODEL,
                  acc);

    const int g = lane >> 2, t = lane & 3;

    if (z == 2) {
        // V: transposed scattered fp16 hi/lo writes
#pragma unroll
        for (int i = 0; i < 4; i++) {
#pragma unroll
            for (int j = 0; j < 4; j++) {
                const int c  = bn + n0 + j * 8 + 2 * t;
                const int hh = c >> 6, d0 = c & 63;
#pragma unroll
                for (int rr = 0; rr < 4; rr++) {
                    const int row = bm + m0 + i * 16 + g + ((rr >> 1) * 8);
                    const int b = row >> 11, s = row & (SEQ - 1);
                    const int d = d0 + (rr & 1);
                    float v = acc[i][j][rr];
                    __half hv = __float2half_rn(v);
                    __half lv = __float2half_rn(v - __half2float(hv));
                    const size_t dst = ((size_t)((b * NHEAD + hh) * DK + d)) * SEQ + s;
                    vth[dst] = hv;
                    vtl[dst] = lv;
                }
            }
        }
    } else if (z == 0) {
        // Q: head-major hi/lo, scaled
#pragma unroll
        for (int i = 0; i < 4; i++) {
#pragma unroll
            for (int j = 0; j < 4; j++) {
                const int c  = bn + n0 + j * 8 + 2 * t;
                const int hh = c >> 6, d = c & 63;
                const int row0 = bm + m0 + i * 16 + g;
                uint32_t hv, lv;
                {
                    const int b = row0 >> 11, s = row0 & (SEQ - 1);
                    split2h(acc[i][j][0] * 0.125f, acc[i][j][1] * 0.125f, hv, lv);
                    const size_t dst = ((size_t)((b * NHEAD + hh) * SEQ + s)) * DK + d;
                    *(uint32_t*)(qh + dst) = hv;
                    *(uint32_t*)(ql + dst) = lv;
                }
                {
                    const int row1 = row0 + 8;
                    const int b = row1 >> 11, s = row1 & (SEQ - 1);
                    split2h(acc[i][j][2] * 0.125f, acc[i][j][3] * 0.125f, hv, lv);
                    const size_t dst = ((size_t)((b * NHEAD + hh) * SEQ + s)) * DK + d;
                    *(uint32_t*)(qh + dst) = hv;
                    *(uint32_t*)(ql + dst) = lv;
                }
            }
        }
    } else {
        // K: head-major hi only
#pragma unroll
        for (int i = 0; i < 4; i++) {
#pragma unroll
            for (int j = 0; j < 4; j++) {
                const int c  = bn + n0 + j * 8 + 2 * t;
                const int hh = c >> 6, d = c & 63;
                const int row0 = bm + m0 + i * 16 + g;
                {
                    const int b = row0 >> 11, s = row0 & (SEQ - 1);
                    const size_t dst = ((size_t)((b * NHEAD + hh) * SEQ + s)) * DK + d;
                    *(uint32_t*)(kh + dst) = pack_h2(acc[i][j][0], acc[i][j][1]);
                }
                {
                    const int row1 = row0 + 8;
                    const int b = row1 >> 11, s = row1 & (SEQ - 1);
                    const size_t dst = ((size_t)((b * NHEAD + hh) * SEQ + s)) * DK + d;
                    *(uint32_t*)(kh + dst) = pack_h2(acc[i][j][2], acc[i][j][3]);
                }
            }
        }
    }
}

// ---------------------------------------------------------------------------
// Output projection GEMM (fp32 result to d_out)
// ---------------------------------------------------------------------------
__global__ __launch_bounds__(256, 2)
void gemm_mma(const __half* __restrict__ Ahi, const __half* __restrict__ Alo,
              const __half* __restrict__ Bhi, float* __restrict__ C)
{
    extern __shared__ char smem[];
    const uint32_t sbase = smem_to_u32(smem);
    const int tid = threadIdx.x;
    const int wid = tid >> 5, lane = tid & 31;
    const int bm = blockIdx.y * 128;
    const int bn = blockIdx.x * 128;
    const int m0 = (wid & 1) * 64;
    const int n0 = (wid >> 1) * 32;

    float acc[4][4][4];
    gemm_mainloop(sbase, tid, lane, m0, n0,
                  Ahi + (size_t)bm * D_MODEL,
                  Alo + (size_t)bm * D_MODEL,
                  Bhi + (size_t)bn * D_MODEL,
                  acc);

    const int g = lane >> 2, t = lane & 3;
#pragma unroll
    for (int i = 0; i < 4; i++) {
#pragma unroll
        for (int j = 0; j < 4; j++) {
            float* cp0 = C + (size_t)(bm + m0 + i * 16 + g) * D_MODEL + bn + n0 + j * 8 + 2 * t;
            float* cp1 = cp0 + 8 * D_MODEL;
            *(float2*)cp0 = make_float2(acc[i][j][0], acc[i][j][1]);
            *(float2*)cp1 = make_float2(acc[i][j][2], acc[i][j][3]);
        }
    }
}

// ---------------------------------------------------------------------------
// Tensor-core causal flash attention — fp16 2-pass (R13):
//   S = (Qh+Ql)·Kh ; P -> fp16 ; O = Ph·(Vh+Vl)
// 4 warps / 64 q-rows per CTA, single-buffered KV (Kh,Vh,Vl = 24KB), 2 CTAs/SM.
// ---------------------------------------------------------------------------
#define ATT_NT   128
#define ATT_SMEM (16384 + 24576)   // Q(hi+lo) + (Kh, Vh, Vl)

__global__ __launch_bounds__(ATT_NT, 2)
void attn_mma(const __half* __restrict__ Qh, const __half* __restrict__ Ql,
              const __half* __restrict__ Kh,
              const __half* __restrict__ Vh, const __half* __restrict__ Vl,
              __half* __restrict__ Ohi, __half* __restrict__ Olo)
{
    extern __shared__ char smem[];
    const uint32_t sb = smem_to_u32(smem);
    const int tid = threadIdx.x, wid = tid >> 5, lane = tid & 31;
    const int qblk = gridDim.x - 1 - blockIdx.x;   // heavy CTAs first
    const int bh = blockIdx.y;
    const int b = bh >> 4, h = bh & 15;
    const int qr0 = qblk * 64 + wid * 16;
    const int g = lane >> 2, t = lane & 3;
    const int qb2 = lane >> 3, l7 = lane & 7;
    const int ra = lane & 15, ca = lane >> 4;

    const uint32_t QH = sb, QL = sb + 8192;
    const uint32_t KVB = sb + 16384;   // KH +0, VH +8192, VL +16384

    {
        const __half* qh_g = Qh + ((size_t)bh * SEQ + qblk * 64) * DK;
        const __half* ql_g = Ql + ((size_t)bh * SEQ + qblk * 64) * DK;
#pragma unroll
        for (int u = tid; u < 512; u += ATT_NT) {
            int row = u >> 3, c = u & 7;
            uint32_t sw = SW128((uint32_t)(row * 128 + c * 16));
            CP_ASYNC16(QH + sw, qh_g + (size_t)row * DK + c * 8);
            CP_ASYNC16(QL + sw, ql_g + (size_t)row * DK + c * 8);
        }
        CP_COMMIT();
        CP_WAIT(0);
        __syncthreads();
    }

    uint32_t qhf[16], qlf[16];
#pragma unroll
    for (int ks = 0; ks < 4; ks++) {
        uint32_t sw = SW128((uint32_t)((wid * 16 + ra) * 128 + (ks * 2 + ca) * 16));
        LDSM_X4(qhf[4 * ks], qhf[4 * ks + 1], qhf[4 * ks + 2], qhf[4 * ks + 3], QH + sw);
        LDSM_X4(qlf[4 * ks], qlf[4 * ks + 1], qlf[4 * ks + 2], qlf[4 * ks + 3], QL + sw);
    }

    float o[8][4];
#pragma unroll
    for (int j = 0; j < 8; j++)
#pragma unroll
        for (int r = 0; r < 4; r++) o[j][r] = 0.f;
    float m0 = NEG_INF, m1 = NEG_INF, l0 = 0.f, l1 = 0.f;

    const int nkb = qblk + 1;

    for (int kb = 0; kb < nkb; kb++) {
        const int k0 = kb * 64;

#pragma unroll
        for (int u = tid; u < 512; u += ATT_NT) {
            int r = u >> 3, c = u & 7;
            uint32_t sw = SW128((uint32_t)(r * 128 + c * 16));
            const size_t kg = ((size_t)bh * SEQ + k0 + r) * DK + c * 8;
            CP_ASYNC16(KVB + sw, Kh + kg);
            const size_t vg = ((size_t)bh * DK + r) * SEQ + k0 + c * 8;
            CP_ASYNC16(KVB + 8192 + sw,  Vh + vg);
            CP_ASYNC16(KVB + 16384 + sw, Vl + vg);
        }
        CP_COMMIT();
        CP_WAIT(0);
        __syncthreads();

        const uint32_t KHs = KVB;
        const uint32_t VHs = KVB + 8192;
        const uint32_t VLs = KVB + 16384;

        // --- S = (Qh+Ql) Kh ---
        float sf[8][4];
#pragma unroll
        for (int j = 0; j < 8; j++)
#pragma unroll
            for (int r = 0; r < 4; r++) sf[j][r] = 0.f;

#pragma unroll
        for (int ks = 0; ks < 4; ks++) {
            uint32_t bhf[16];
#pragma unroll
            for (int jj = 0; jj < 4; jj++) {
                uint32_t sw = SW128((uint32_t)(((jj * 2 + (qb2 >> 1)) * 8 + l7) * 128
                                               + (ks * 2 + (qb2 & 1)) * 16));
                LDSM_X4(bhf[4 * jj], bhf[4 * jj + 1], bhf[4 * jj + 2], bhf[4 * jj + 3], KHs + sw);
            }
#pragma unroll
            for (int j = 0; j < 8; j++) {
                MMA_F16(sf[j], &qhf[4 * ks], &bhf[2 * j]);
                MMA_F16(sf[j], &qlf[4 * ks], &bhf[2 * j]);
            }
        }

        if (k0 + 63 > qr0) {
            const int row0 = qr0 + g, row1 = row0 + 8;
#pragma unroll
            for (int j = 0; j < 8; j++) {
                const int key = k0 + 8 * j + 2 * t;
                if (key     > row0) sf[j][0] = NEG_INF;
                if (key + 1 > row0) sf[j][1] = NEG_INF;
                if (key     > row1) sf[j][2] = NEG_INF;
                if (key + 1 > row1) sf[j][3] = NEG_INF;
            }
        }

        float mx0 = NEG_INF, mx1 = NEG_INF;
#pragma unroll
        for (int j = 0; j < 8; j++) {
            mx0 = fmaxf(mx0, fmaxf(sf[j][0], sf[j][1]));
            mx1 = fmaxf(mx1, fmaxf(sf[j][2], sf[j][3]));
        }
        mx0 = fmaxf(mx0, __shfl_xor_sync(0xffffffffu, mx0, 1));
        mx0 = fmaxf(mx0, __shfl_xor_sync(0xffffffffu, mx0, 2));
        mx1 = fmaxf(mx1, __shfl_xor_sync(0xffffffffu, mx1, 1));
        mx1 = fmaxf(mx1, __shfl_xor_sync(0xffffffffu, mx1, 2));
        const float mn0 = fmaxf(m0, mx0), mn1 = fmaxf(m1, mx1);
        const float a0 = __expf(m0 - mn0), a1 = __expf(m1 - mn1);
        m0 = mn0; m1 = mn1;

        float rs0 = 0.f, rs1 = 0.f;
        uint32_t ph[16];
#pragma unroll
        for (int j = 0; j < 8; j++) {
            float p0 = __expf(sf[j][0] - mn0);
            float p1 = __expf(sf[j][1] - mn0);
            float p2 = __expf(sf[j][2] - mn1);
            float p3 = __expf(sf[j][3] - mn1);
            rs0 += p0 + p1;
            rs1 += p2 + p3;
            const int ks2 = j >> 1, hf = j & 1;
            ph[4 * ks2 + 2 * hf]     = pack_h2(p0, p1);
            ph[4 * ks2 + 2 * hf + 1] = pack_h2(p2, p3);
        }
        rs0 += __shfl_xor_sync(0xffffffffu, rs0, 1);
        rs0 += __shfl_xor_sync(0xffffffffu, rs0, 2);
        rs1 += __shfl_xor_sync(0xffffffffu, rs1, 1);
        rs1 += __shfl_xor_sync(0xffffffffu, rs1, 2);
        l0 = l0 * a0 + rs0;
        l1 = l1 * a1 + rs1;

#pragma unroll
        for (int j = 0; j < 8; j++) {
            o[j][0] *= a0; o[j][1] *= a0;
            o[j][2] *= a1; o[j][3] *= a1;
        }

        // --- O += Ph (Vh + Vl) ---
#pragma unroll
        for (int ks = 0; ks < 4; ks++) {
            uint32_t vhf[16], vlf[16];
#pragma unroll
            for (int jj = 0; jj < 4; jj++) {
                uint32_t sw = SW128((uint32_t)(((jj * 2 + (qb2 >> 1)) * 8 + l7) * 128
                                               + (ks * 2 + (qb2 & 1)) * 16));
                LDSM_X4(vhf[4 * jj], vhf[4 * jj + 1], vhf[4 * jj + 2], vhf[4 * jj + 3], VHs + sw);
                LDSM_X4(vlf[4 * jj], vlf[4 * jj + 1], vlf[4 * jj + 2], vlf[4 * jj + 3], VLs + sw);
            }
#pragma unroll
            for (int j = 0; j < 8; j++) {
                MMA_F16(o[j], &ph[4 * ks], &vhf[2 * j]);
                MMA_F16(o[j], &ph[4 * ks], &vlf[2 * j]);
            }
        }

        __syncthreads();
    }

    const float il0 = 1.f / l0, il1 = 1.f / l1;
    const size_t r0 = (size_t)(b * SEQ + qr0 + g) * D_MODEL + h * DK;
    const size_t r1 = r0 + (size_t)8 * D_MODEL;
#pragma unroll
    for (int j = 0; j < 8; j++) {
        const int c = 8 * j + 2 * t;
        uint32_t hv, lv;
        split2h(o[j][0] * il0, o[j][1] * il0, hv, lv);
        *(uint32_t*)(Ohi + r0 + c) = hv;
        *(uint32_t*)(Olo + r0 + c) = lv;
        split2h(o[j][2] * il1, o[j][3] * il1, hv, lv);
        *(uint32_t*)(Ohi + r1 + c) = hv;
        *(uint32_t*)(Olo + r1 + c) = lv;
    }
}

// ---------------------------------------------------------------------------
extern "C" void kernel_launch(void* const* d_in, const int* in_sizes, int n_in,
                              void* d_out, int out_size)
{
    (void)in_sizes; (void)n_in; (void)out_size;
    const float* x  = (const float*)d_in[0];
    const float* Wq = (const float*)d_in[1];
    const float* Wk = (const float*)d_in[2];
    const float* Wv = (const float*)d_in[3];
    const float* Wo = (const float*)d_in[4];
    float* out = (float*)d_out;

    __half *xhi, *xlo, *ohi, *olo, *whi;
    cudaGetSymbolAddress((void**)&xhi, g_x_hi);
    cudaGetSymbolAddress((void**)&xlo, g_x_lo);
    cudaGetSymbolAddress((void**)&ohi, g_o_hi);
    cudaGetSymbolAddress((void**)&olo, g_o_lo);
    cudaGetSymbolAddress((void**)&whi, g_w_hi);
    __half *qh, *ql, *kh, *vth, *vtl;
    cudaGetSymbolAddress((void**)&qh,  g_qh);
    cudaGetSymbolAddress((void**)&ql,  g_ql);
    cudaGetSymbolAddress((void**)&kh,  g_kh);
    cudaGetSymbolAddress((void**)&vth, g_vth);
    cudaGetSymbolAddress((void**)&vtl, g_vtl);

    cudaFuncSetAttribute(gemm_qkv, cudaFuncAttributeMaxDynamicSharedMemorySize, GEMM_SMEM);
    cudaFuncSetAttribute(gemm_mma, cudaFuncAttributeMaxDynamicSharedMemorySize, GEMM_SMEM);
    cudaFuncSetAttribute(attn_mma, cudaFuncAttributeMaxDynamicSharedMemorySize, ATT_SMEM);

    const int NW4 = D_MODEL * D_MODEL / 4;   // 262,144
    const int WSZ = D_MODEL * D_MODEL;

    cvt_all<<<dim3(NW4 / 256, 8), 256>>>(x, Wq, Wk, Wv, Wo, xhi, xlo, whi);

    gemm_qkv<<<dim3(D_MODEL / 128, MTOT / 128, 3), 256, GEMM_SMEM>>>(
        xhi, xlo, whi, qh, ql, kh, vth, vtl);

    attn_mma<<<dim3(SEQ / 64, BH), ATT_NT, ATT_SMEM>>>(qh, ql, kh, vth, vtl, ohi, olo);

    gemm_mma<<<dim3(D_MODEL / 128, MTOT / 128), 256, GEMM_SMEM>>>(
        ohi, olo, whi + 3 * WSZ, out);
}

// round 14
// speedup vs baseline: 2.3211x; 1.0034x over previous
#include <cuda_runtime.h>
#include <cuda_bf16.h>
#include <cuda_fp16.h>
#include <cstdint>

#define D_MODEL 1024
#define NHEAD   16
#define DK      64
#define BATCH   2
#define SEQ     2048
#define MTOT    (BATCH * SEQ)   // 4096
#define BH      (BATCH * NHEAD) // 32

#define NEG_INF __int_as_float(0xff800000)

// ---------------------------------------------------------------------------
// Scratch (__device__ globals: allocations are forbidden)
// ---------------------------------------------------------------------------
__device__ __half g_x_hi[MTOT * D_MODEL];
__device__ __half g_x_lo[MTOT * D_MODEL];
__device__ __half g_o_hi[MTOT * D_MODEL];
__device__ __half g_o_lo[MTOT * D_MODEL];
__device__ __half g_w_hi[4][D_MODEL * D_MODEL];   // fp16 hi only (2-pass scheme)

// head-major fp16 for attention (R13: fp16 2-pass attention)
__device__ __half g_qh[BH * SEQ * DK];
__device__ __half g_ql[BH * SEQ * DK];
__device__ __half g_kh[BH * SEQ * DK];            // K hi only
__device__ __half g_vth[BH * DK * SEQ];           // transposed: [bh][d][s]
__device__ __half g_vtl[BH * DK * SEQ];

// ---------------------------------------------------------------------------
// Base-ISA helpers (NO tcgen05 — harness ptxas targets plain sm_103)
// ---------------------------------------------------------------------------
__device__ __forceinline__ uint32_t smem_to_u32(const void* p) {
    uint32_t a;
    asm("{ .reg .u64 t; cvta.to.shared.u64 t, %1; cvt.u32.u64 %0, t; }" : "=r"(a) : "l"(p));
    return a;
}
#define SW128(o) ((o) ^ (((o) >> 3) & 0x70))

#define CP_ASYNC16(dst, src) \
    asm volatile("cp.async.cg.shared.global [%0], [%1], 16;" :: "r"(dst), "l"(src))
#define CP_COMMIT() asm volatile("cp.async.commit_group;" ::: "memory")
#define CP_WAIT(n)  asm volatile("cp.async.wait_group %0;" :: "n"(n) : "memory")

#define LDSM_X4(r0, r1, r2, r3, addr) \
    asm volatile("ldmatrix.sync.aligned.m8n8.x4.shared.b16 {%0,%1,%2,%3}, [%4];" \
                 : "=r"(r0), "=r"(r1), "=r"(r2), "=r"(r3) : "r"(addr))

#define MMA_F16(c, a, b) \
    asm volatile("mma.sync.aligned.m16n8k16.row.col.f32.f16.f16.f32 " \
                 "{%0,%1,%2,%3}, {%4,%5,%6,%7}, {%8,%9}, {%0,%1,%2,%3};" \
                 : "+f"((c)[0]), "+f"((c)[1]), "+f"((c)[2]), "+f"((c)[3]) \
                 : "r"((a)[0]), "r"((a)[1]), "r"((a)[2]), "r"((a)[3]), \
                   "r"((b)[0]), "r"((b)[1]))

__device__ __forceinline__ void split2h(float x, float y, uint32_t& hi, uint32_t& lo) {
    __half hx = __float2half_rn(x), hy = __float2half_rn(y);
    __half lx = __float2half_rn(x - __half2float(hx));
    __half ly = __float2half_rn(y - __half2float(hy));
    __half2 th(hx, hy), tl(lx, ly);
    hi = *(uint32_t*)&th;
    lo = *(uint32_t*)&tl;
}

__device__ __forceinline__ uint32_t pack_h2(float x, float y) {
    __half2 t(__float2half_rn(x), __float2half_rn(y));
    return *(uint32_t*)&t;
}

// ---------------------------------------------------------------------------
// fp32 -> fp16 conversion, one launch: weights (hi only) + x (hi/lo split)
// ---------------------------------------------------------------------------
__global__ __launch_bounds__(256)
void cvt_all(const float* __restrict__ x,
             const float* __restrict__ w0, const float* __restrict__ w1,
             const float* __restrict__ w2, const float* __restrict__ w3,
             __half* __restrict__ xhi, __half* __restrict__ xlo,
             __half* __restrict__ whi)
{
    const int y = blockIdx.y;
    const size_t WSZ4 = (size_t)D_MODEL * D_MODEL / 4;
    int i = blockIdx.x * 256 + threadIdx.x;
    if (y < 4) {
        const float* src = (y == 0) ? w0 : (y == 1) ? w1 : (y == 2) ? w2 : w3;
        __half* hi = whi + (size_t)y * D_MODEL * D_MODEL;
        float4 v = ((const float4*)src)[i];
        ((uint32_t*)hi)[2 * i]     = pack_h2(v.x, v.y);
        ((uint32_t*)hi)[2 * i + 1] = pack_h2(v.z, v.w);
    } else {
        const float* src = x + (size_t)(y - 4) * WSZ4 * 4;
        __half* hi = xhi + (size_t)(y - 4) * WSZ4 * 4;
        __half* lo = xlo + (size_t)(y - 4) * WSZ4 * 4;
        float4 v = ((const float4*)src)[i];
        uint32_t h0, l0, h1, l1;
        split2h(v.x, v.y, h0, l0);
        split2h(v.z, v.w, h1, l1);
        ((uint32_t*)hi)[2 * i] = h0;     ((uint32_t*)hi)[2 * i + 1] = h1;
        ((uint32_t*)lo)[2 * i] = l0;     ((uint32_t*)lo)[2 * i + 1] = l1;
    }
}

// ---------------------------------------------------------------------------
// GEMM core — fp16 2-pass: C = (Ahi + Alo) * Bhi (validated R11/R12 config)
// ---------------------------------------------------------------------------
#define KC        64
#define NCHUNK    (D_MODEL / KC)      // 16
#define TILE_B    16384
#define BUF_B     (3 * TILE_B)
#define GEMM_SMEM (2 * BUF_B)         // 98304

__device__ __forceinline__ void cp_tile(uint32_t dst_base, const __half* src, int tid)
{
#pragma unroll
    for (int u = tid; u < 1024; u += 256) {
        int row = u >> 3, c = u & 7;
        uint32_t off = row * 128 + c * 16;
        CP_ASYNC16(dst_base + SW128(off), src + (size_t)row * D_MODEL + c * 8);
    }
}

__device__ __forceinline__ void gemm_mainloop(
    uint32_t sbase, int tid, int lane, int m0, int n0,
    const __half* pAh, const __half* pAl, const __half* pBh,
    float acc[4][4][4])
{
#pragma unroll
    for (int i = 0; i < 4; i++)
#pragma unroll
        for (int j = 0; j < 4; j++)
#pragma unroll
            for (int r = 0; r < 4; r++) acc[i][j][r] = 0.f;

    const int ra = lane & 15;
    const int ca = lane >> 4;
    const int qb = lane >> 3;
    const int l7 = lane & 7;

    cp_tile(sbase + 0 * TILE_B, pAh, tid);
    cp_tile(sbase + 1 * TILE_B, pAl, tid);
    cp_tile(sbase + 2 * TILE_B, pBh, tid);
    CP_COMMIT();

    for (int ch = 0; ch < NCHUNK; ch++) {
        const int buf = ch & 1;
        if (ch + 1 < NCHUNK) {
            const uint32_t nb = sbase + (buf ^ 1) * BUF_B;
            const int kc = (ch + 1) * KC;
            cp_tile(nb + 0 * TILE_B, pAh + kc, tid);
            cp_tile(nb + 1 * TILE_B, pAl + kc, tid);
            cp_tile(nb + 2 * TILE_B, pBh + kc, tid);
            CP_COMMIT();
            CP_WAIT(1);
        } else {
            CP_WAIT(0);
        }
        __syncthreads();

        const uint32_t aH = sbase + buf * BUF_B + 0 * TILE_B;
        const uint32_t aL = sbase + buf * BUF_B + 1 * TILE_B;
        const uint32_t bH = sbase + buf * BUF_B + 2 * TILE_B;

#pragma unroll
        for (int ks = 0; ks < 4; ks++) {
            uint32_t ah[16], al[16];
#pragma unroll
            for (int i = 0; i < 4; i++) {
                uint32_t off = (uint32_t)(m0 + i * 16 + ra) * 128 + (ks * 2 + ca) * 16;
                uint32_t sw = SW128(off);
                LDSM_X4(ah[4 * i], ah[4 * i + 1], ah[4 * i + 2], ah[4 * i + 3], aH + sw);
                LDSM_X4(al[4 * i], al[4 * i + 1], al[4 * i + 2], al[4 * i + 3], aL + sw);
            }
            uint32_t bh[8];
#pragma unroll
            for (int jj = 0; jj < 2; jj++) {
                uint32_t off = (uint32_t)(n0 + (jj * 2 + (qb >> 1)) * 8 + l7) * 128
                             + (ks * 2 + (qb & 1)) * 16;
                uint32_t sw = SW128(off);
                LDSM_X4(bh[4 * jj], bh[4 * jj + 1], bh[4 * jj + 2], bh[4 * jj + 3], bH + sw);
            }
#pragma unroll
            for (int i = 0; i < 4; i++)
#pragma unroll
                for (int j = 0; j < 4; j++) {
                    MMA_F16(acc[i][j], &ah[4 * i], &bh[2 * j]);
                    MMA_F16(acc[i][j], &al[4 * i], &bh[2 * j]);
                }
        }
        __syncthreads();
    }
}

// ---------------------------------------------------------------------------
// QKV projections, one launch (grid.z = 0:Q, 1:K, 2:V).
// Epilogue writes attention-ready fp16 layouts:
//   Q: head-major [bh][s][64] hi/lo, pre-scaled by 1/8
//   K: head-major [bh][s][64] hi only
//   V: transposed  [bh][d][s] hi/lo
// ---------------------------------------------------------------------------
__global__ __launch_bounds__(256, 2)
void gemm_qkv(const __half* __restrict__ Ahi, const __half* __restrict__ Alo,
              const __half* __restrict__ Whi,
              __half* __restrict__ qh, __half* __restrict__ ql,
              __half* __restrict__ kh,
              __half* __restrict__ vth, __half* __restrict__ vtl)
{
    extern __shared__ char smem[];
    const uint32_t sbase = smem_to_u32(smem);
    const int tid = threadIdx.x;
    const int wid = tid >> 5, lane = tid & 31;
    const int bm = blockIdx.y * 128;
    const int bn = blockIdx.x * 128;
    const int z  = blockIdx.z;
    const int m0 = (wid & 1) * 64;
    const int n0 = (wid >> 1) * 32;

    float acc[4][4][4];
    gemm_mainloop(sbase, tid, lane, m0, n0,
                  Ahi + (size_t)bm * D_MODEL,
                  Alo + (size_t)bm * D_MODEL,
                  Whi + (size_t)z * D_MODEL * D_MODEL + (size_t)bn * D_MODEL,
                  acc);

    const int g = lane >> 2, t = lane & 3;

    if (z == 2) {
        // V: transposed scattered fp16 hi/lo writes
#pragma unroll
        for (int i = 0; i < 4; i++) {
#pragma unroll
            for (int j = 0; j < 4; j++) {
                const int c  = bn + n0 + j * 8 + 2 * t;
                const int hh = c >> 6, d0 = c & 63;
#pragma unroll
                for (int rr = 0; rr < 4; rr++) {
                    const int row = bm + m0 + i * 16 + g + ((rr >> 1) * 8);
                    const int b = row >> 11, s = row & (SEQ - 1);
                    const int d = d0 + (rr & 1);
                    float v = acc[i][j][rr];
                    __half hv = __float2half_rn(v);
                    __half lv = __float2half_rn(v - __half2float(hv));
                    const size_t dst = ((size_t)((b * NHEAD + hh) * DK + d)) * SEQ + s;
                    vth[dst] = hv;
                    vtl[dst] = lv;
                }
            }
        }
    } else if (z == 0) {
        // Q: head-major hi/lo, scaled
#pragma unroll
        for (int i = 0; i < 4; i++) {
#pragma unroll
            for (int j = 0; j < 4; j++) {
                const int c  = bn + n0 + j * 8 + 2 * t;
                const int hh = c >> 6, d = c & 63;
                const int row0 = bm + m0 + i * 16 + g;
                uint32_t hv, lv;
                {
                    const int b = row0 >> 11, s = row0 & (SEQ - 1);
                    split2h(acc[i][j][0] * 0.125f, acc[i][j][1] * 0.125f, hv, lv);
                    const size_t dst = ((size_t)((b * NHEAD + hh) * SEQ + s)) * DK + d;
                    *(uint32_t*)(qh + dst) = hv;
                    *(uint32_t*)(ql + dst) = lv;
                }
                {
                    const int row1 = row0 + 8;
                    const int b = row1 >> 11, s = row1 & (SEQ - 1);
                    split2h(acc[i][j][2] * 0.125f, acc[i][j][3] * 0.125f, hv, lv);
                    const size_t dst = ((size_t)((b * NHEAD + hh) * SEQ + s)) * DK + d;
                    *(uint32_t*)(qh + dst) = hv;
                    *(uint32_t*)(ql + dst) = lv;
                }
            }
        }
    } else {
        // K: head-major hi only
#pragma unroll
        for (int i = 0; i < 4; i++) {
#pragma unroll
            for (int j = 0; j < 4; j++) {
                const int c  = bn + n0 + j * 8 + 2 * t;
                const int hh = c >> 6, d = c & 63;
                const int row0 = bm + m0 + i * 16 + g;
                {
                    const int b = row0 >> 11, s = row0 & (SEQ - 1);
                    const size_t dst = ((size_t)((b * NHEAD + hh) * SEQ + s)) * DK + d;
                    *(uint32_t*)(kh + dst) = pack_h2(acc[i][j][0], acc[i][j][1]);
                }
                {
                    const int row1 = row0 + 8;
                    const int b = row1 >> 11, s = row1 & (SEQ - 1);
                    const size_t dst = ((size_t)((b * NHEAD + hh) * SEQ + s)) * DK + d;
                    *(uint32_t*)(kh + dst) = pack_h2(acc[i][j][2], acc[i][j][3]);
                }
            }
        }
    }
}

// ---------------------------------------------------------------------------
// Output projection GEMM (fp32 result to d_out)
// ---------------------------------------------------------------------------
__global__ __launch_bounds__(256, 2)
void gemm_mma(const __half* __restrict__ Ahi, const __half* __restrict__ Alo,
              const __half* __restrict__ Bhi, float* __restrict__ C)
{
    extern __shared__ char smem[];
    const uint32_t sbase = smem_to_u32(smem);
    const int tid = threadIdx.x;
    const int wid = tid >> 5, lane = tid & 31;
    const int bm = blockIdx.y * 128;
    const int bn = blockIdx.x * 128;
    const int m0 = (wid & 1) * 64;
    const int n0 = (wid >> 1) * 32;

    float acc[4][4][4];
    gemm_mainloop(sbase, tid, lane, m0, n0,
                  Ahi + (size_t)bm * D_MODEL,
                  Alo + (size_t)bm * D_MODEL,
                  Bhi + (size_t)bn * D_MODEL,
                  acc);

    const int g = lane >> 2, t = lane & 3;
#pragma unroll
    for (int i = 0; i < 4; i++) {
#pragma unroll
        for (int j = 0; j < 4; j++) {
            float* cp0 = C + (size_t)(bm + m0 + i * 16 + g) * D_MODEL + bn + n0 + j * 8 + 2 * t;
            float* cp1 = cp0 + 8 * D_MODEL;
            *(float2*)cp0 = make_float2(acc[i][j][0], acc[i][j][1]);
            *(float2*)cp1 = make_float2(acc[i][j][2], acc[i][j][3]);
        }
    }
}

// ---------------------------------------------------------------------------
// Tensor-core causal flash attention — fp16 2-pass (R13):
//   S = (Qh+Ql)·Kh ; P -> fp16 ; O = Ph·(Vh+Vl)
// 4 warps / 64 q-rows per CTA, single-buffered KV (Kh,Vh,Vl = 24KB), 2 CTAs/SM.
// ---------------------------------------------------------------------------
#define ATT_NT   128
#define ATT_SMEM (16384 + 24576)   // Q(hi+lo) + (Kh, Vh, Vl)

__global__ __launch_bounds__(ATT_NT, 2)
void attn_mma(const __half* __restrict__ Qh, const __half* __restrict__ Ql,
              const __half* __restrict__ Kh,
              const __half* __restrict__ Vh, const __half* __restrict__ Vl,
              __half* __restrict__ Ohi, __half* __restrict__ Olo)
{
    extern __shared__ char smem[];
    const uint32_t sb = smem_to_u32(smem);
    const int tid = threadIdx.x, wid = tid >> 5, lane = tid & 31;
    const int qblk = gridDim.x - 1 - blockIdx.x;   // heavy CTAs first
    const int bh = blockIdx.y;
    const int b = bh >> 4, h = bh & 15;
    const int qr0 = qblk * 64 + wid * 16;
    const int g = lane >> 2, t = lane & 3;
    const int qb2 = lane >> 3, l7 = lane & 7;
    const int ra = lane & 15, ca = lane >> 4;

    const uint32_t QH = sb, QL = sb + 8192;
    const uint32_t KVB = sb + 16384;   // KH +0, VH +8192, VL +16384

    {
        const __half* qh_g = Qh + ((size_t)bh * SEQ + qblk * 64) * DK;
        const __half* ql_g = Ql + ((size_t)bh * SEQ + qblk * 64) * DK;
#pragma unroll
        for (int u = tid; u < 512; u += ATT_NT) {
            int row = u >> 3, c = u & 7;
            uint32_t sw = SW128((uint32_t)(row * 128 + c * 16));
            CP_ASYNC16(QH + sw, qh_g + (size_t)row * DK + c * 8);
            CP_ASYNC16(QL + sw, ql_g + (size_t)row * DK + c * 8);
        }
        CP_COMMIT();
        CP_WAIT(0);
        __syncthreads();
    }

    uint32_t qhf[16], qlf[16];
#pragma unroll
    for (int ks = 0; ks < 4; ks++) {
        uint32_t sw = SW128((uint32_t)((wid * 16 + ra) * 128 + (ks * 2 + ca) * 16));
        LDSM_X4(qhf[4 * ks], qhf[4 * ks + 1], qhf[4 * ks + 2], qhf[4 * ks + 3], QH + sw);
        LDSM_X4(qlf[4 * ks], qlf[4 * ks + 1], qlf[4 * ks + 2], qlf[4 * ks + 3], QL + sw);
    }

    float o[8][4];
#pragma unroll
    for (int j = 0; j < 8; j++)
#pragma unroll
        for (int r = 0; r < 4; r++) o[j][r] = 0.f;
    float m0 = NEG_INF, m1 = NEG_INF, l0 = 0.f, l1 = 0.f;

    const int nkb = qblk + 1;

    for (int kb = 0; kb < nkb; kb++) {
        const int k0 = kb * 64;

#pragma unroll
        for (int u = tid; u < 512; u += ATT_NT) {
            int r = u >> 3, c = u & 7;
            uint32_t sw = SW128((uint32_t)(r * 128 + c * 16));
            const size_t kg = ((size_t)bh * SEQ + k0 + r) * DK + c * 8;
            CP_ASYNC16(KVB + sw, Kh + kg);
            const size_t vg = ((size_t)bh * DK + r) * SEQ + k0 + c * 8;
            CP_ASYNC16(KVB + 8192 + sw,  Vh + vg);
            CP_ASYNC16(KVB + 16384 + sw, Vl + vg);
        }
        CP_COMMIT();
        CP_WAIT(0);
        __syncthreads();

        const uint32_t KHs = KVB;
        const uint32_t VHs = KVB + 8192;
        const uint32_t VLs = KVB + 16384;

        // --- S = (Qh+Ql) Kh ---
        float sf[8][4];
#pragma unroll
        for (int j = 0; j < 8; j++)
#pragma unroll
            for (int r = 0; r < 4; r++) sf[j][r] = 0.f;

#pragma unroll
        for (int ks = 0; ks < 4; ks++) {
            uint32_t bhf[16];
#pragma unroll
            for (int jj = 0; jj < 4; jj++) {
                uint32_t sw = SW128((uint32_t)(((jj * 2 + (qb2 >> 1)) * 8 + l7) * 128
                                               + (ks * 2 + (qb2 & 1)) * 16));
                LDSM_X4(bhf[4 * jj], bhf[4 * jj + 1], bhf[4 * jj + 2], bhf[4 * jj + 3], KHs + sw);
            }
#pragma unroll
            for (int j = 0; j < 8; j++) {
                MMA_F16(sf[j], &qhf[4 * ks], &bhf[2 * j]);
                MMA_F16(sf[j], &qlf[4 * ks], &bhf[2 * j]);
            }
        }

        if (k0 + 63 > qr0) {
            const int row0 = qr0 + g, row1 = row0 + 8;
#pragma unroll
            for (int j = 0; j < 8; j++) {
                const int key = k0 + 8 * j + 2 * t;
                if (key     > row0) sf[j][0] = NEG_INF;
                if (key + 1 > row0) sf[j][1] = NEG_INF;
                if (key     > row1) sf[j][2] = NEG_INF;
                if (key + 1 > row1) sf[j][3] = NEG_INF;
            }
        }

        float mx0 = NEG_INF, mx1 = NEG_INF;
#pragma unroll
        for (int j = 0; j < 8; j++) {
            mx0 = fmaxf(mx0, fmaxf(sf[j][0], sf[j][1]));
            mx1 = fmaxf(mx1, fmaxf(sf[j][2], sf[j][3]));
        }
        mx0 = fmaxf(mx0, __shfl_xor_sync(0xffffffffu, mx0, 1));
        mx0 = fmaxf(mx0, __shfl_xor_sync(0xffffffffu, mx0, 2));
        mx1 = fmaxf(mx1, __shfl_xor_sync(0xffffffffu, mx1, 1));
        mx1 = fmaxf(mx1, __shfl_xor_sync(0xffffffffu, mx1, 2));
        const float mn0 = fmaxf(m0, mx0), mn1 = fmaxf(m1, mx1);
        const float a0 = __expf(m0 - mn0), a1 = __expf(m1 - mn1);
        m0 = mn0; m1 = mn1;

        float rs0 = 0.f, rs1 = 0.f;
        uint32_t ph[16];
#pragma unroll
        for (int j = 0; j < 8; j++) {
            float p0 = __expf(sf[j][0] - mn0);
            float p1 = __expf(sf[j][1] - mn0);
            float p2 = __expf(sf[j][2] - mn1);
            float p3 = __expf(sf[j][3] - mn1);
            rs0 += p0 + p1;
            rs1 += p2 + p3;
            const int ks2 = j >> 1, hf = j & 1;
            ph[4 * ks2 + 2 * hf]     = pack_h2(p0, p1);
            ph[4 * ks2 + 2 * hf + 1] = pack_h2(p2, p3);
        }
        rs0 += __shfl_xor_sync(0xffffffffu, rs0, 1);
        rs0 += __shfl_xor_sync(0xffffffffu, rs0, 2);
        rs1 += __shfl_xor_sync(0xffffffffu, rs1, 1);
        rs1 += __shfl_xor_sync(0xffffffffu, rs1, 2);
        l0 = l0 * a0 + rs0;
        l1 = l1 * a1 + rs1;

#pragma unroll
        for (int j = 0; j < 8; j++) {
            o[j][0] *= a0; o[j][1] *= a0;
            o[j][2] *= a1; o[j][3] *= a1;
        }

        // --- O += Ph (Vh + Vl) ---
#pragma unroll
        for (int ks = 0; ks < 4; ks++) {
            uint32_t vhf[16], vlf[16];
#pragma unroll
            for (int jj = 0; jj < 4; jj++) {
                uint32_t sw = SW128((uint32_t)(((jj * 2 + (qb2 >> 1)) * 8 + l7) * 128
                                               + (ks * 2 + (qb2 & 1)) * 16));
                LDSM_X4(vhf[4 * jj], vhf[4 * jj + 1], vhf[4 * jj + 2], vhf[4 * jj + 3], VHs + sw);
                LDSM_X4(vlf[4 * jj], vlf[4 * jj + 1], vlf[4 * jj + 2], vlf[4 * jj + 3], VLs + sw);
            }
#pragma unroll
            for (int j = 0; j < 8; j++) {
                MMA_F16(o[j], &ph[4 * ks], &vhf[2 * j]);
                MMA_F16(o[j], &ph[4 * ks], &vlf[2 * j]);
            }
        }

        __syncthreads();
    }

    const float il0 = 1.f / l0, il1 = 1.f / l1;
    const size_t r0 = (size_t)(b * SEQ + qr0 + g) * D_MODEL + h * DK;
    const size_t r1 = r0 + (size_t)8 * D_MODEL;
#pragma unroll
    for (int j = 0; j < 8; j++) {
        const int c = 8 * j + 2 * t;
        uint32_t hv, lv;
        split2h(o[j][0] * il0, o[j][1] * il0, hv, lv);
        *(uint32_t*)(Ohi + r0 + c) = hv;
        *(uint32_t*)(Olo + r0 + c) = lv;
        split2h(o[j][2] * il1, o[j][3] * il1, hv, lv);
        *(uint32_t*)(Ohi + r1 + c) = hv;
        *(uint32_t*)(Olo + r1 + c) = lv;
    }
}

// ---------------------------------------------------------------------------
extern "C" void kernel_launch(void* const* d_in, const int* in_sizes, int n_in,
                              void* d_out, int out_size)
{
    (void)in_sizes; (void)n_in; (void)out_size;
    const float* x  = (const float*)d_in[0];
    const float* Wq = (const float*)d_in[1];
    const float* Wk = (const float*)d_in[2];
    const float* Wv = (const float*)d_in[3];
    const float* Wo = (const float*)d_in[4];
    float* out = (float*)d_out;

    __half *xhi, *xlo, *ohi, *olo, *whi;
    cudaGetSymbolAddress((void**)&xhi, g_x_hi);
    cudaGetSymbolAddress((void**)&xlo, g_x_lo);
    cudaGetSymbolAddress((void**)&ohi, g_o_hi);
    cudaGetSymbolAddress((void**)&olo, g_o_lo);
    cudaGetSymbolAddress((void**)&whi, g_w_hi);
    __half *qh, *ql, *kh, *vth, *vtl;
    cudaGetSymbolAddress((void**)&qh,  g_qh);
    cudaGetSymbolAddress((void**)&ql,  g_ql);
    cudaGetSymbolAddress((void**)&kh,  g_kh);
    cudaGetSymbolAddress((void**)&vth, g_vth);
    cudaGetSymbolAddress((void**)&vtl, g_vtl);

    cudaFuncSetAttribute(gemm_qkv, cudaFuncAttributeMaxDynamicSharedMemorySize, GEMM_SMEM);
    cudaFuncSetAttribute(gemm_mma, cudaFuncAttributeMaxDynamicSharedMemorySize, GEMM_SMEM);
    cudaFuncSetAttribute(attn_mma, cudaFuncAttributeMaxDynamicSharedMemorySize, ATT_SMEM);

    const int NW4 = D_MODEL * D_MODEL / 4;   // 262,144
    const int WSZ = D_MODEL * D_MODEL;

    cvt_all<<<dim3(NW4 / 256, 8), 256>>>(x, Wq, Wk, Wv, Wo, xhi, xlo, whi);

    gemm_qkv<<<dim3(D_MODEL / 128, MTOT / 128, 3), 256, GEMM_SMEM>>>(
        xhi, xlo, whi, qh, ql, kh, vth, vtl);

    attn_mma<<<dim3(SEQ / 64, BH), ATT_NT, ATT_SMEM>>>(qh, ql, kh, vth, vtl, ohi, olo);

    gemm_mma<<<dim3(D_MODEL / 128, MTOT / 128), 256, GEMM_SMEM>>>(
        ohi, olo, whi + 3 * WSZ, out);
}

// round 15
// speedup vs baseline: 2.3759x; 1.0236x over previous
#include <cuda_runtime.h>
#include <cuda_bf16.h>
#include <cuda_fp16.h>
#include <cstdint>

#define D_MODEL 1024
#define NHEAD   16
#define DK      64
#define BATCH   2
#define SEQ     2048
#define MTOT    (BATCH * SEQ)   // 4096
#define BH      (BATCH * NHEAD) // 32

#define NEG_INF __int_as_float(0xff800000)

// ---------------------------------------------------------------------------
// Scratch (__device__ globals: allocations are forbidden)
// ---------------------------------------------------------------------------
__device__ __half g_x_hi[MTOT * D_MODEL];
__device__ __half g_x_lo[MTOT * D_MODEL];
__device__ __half g_o_hi[MTOT * D_MODEL];
__device__ __half g_o_lo[MTOT * D_MODEL];
__device__ __half g_w_hi[4][D_MODEL * D_MODEL];   // fp16 hi only (2-pass scheme)

// head-major fp16 for attention
__device__ __half g_qh[BH * SEQ * DK];
__device__ __half g_ql[BH * SEQ * DK];
__device__ __half g_kh[BH * SEQ * DK];            // K hi only
__device__ __half g_vth[BH * DK * SEQ];           // transposed: [bh][d][s]
__device__ __half g_vtl[BH * DK * SEQ];

// ---------------------------------------------------------------------------
// Base-ISA helpers (NO tcgen05 — harness ptxas targets plain sm_103)
// ---------------------------------------------------------------------------
__device__ __forceinline__ uint32_t smem_to_u32(const void* p) {
    uint32_t a;
    asm("{ .reg .u64 t; cvta.to.shared.u64 t, %1; cvt.u32.u64 %0, t; }" : "=r"(a) : "l"(p));
    return a;
}
#define SW128(o) ((o) ^ (((o) >> 3) & 0x70))

#define CP_ASYNC16(dst, src) \
    asm volatile("cp.async.cg.shared.global [%0], [%1], 16;" :: "r"(dst), "l"(src))
#define CP_COMMIT() asm volatile("cp.async.commit_group;" ::: "memory")
#define CP_WAIT(n)  asm volatile("cp.async.wait_group %0;" :: "n"(n) : "memory")

#define LDSM_X4(r0, r1, r2, r3, addr) \
    asm volatile("ldmatrix.sync.aligned.m8n8.x4.shared.b16 {%0,%1,%2,%3}, [%4];" \
                 : "=r"(r0), "=r"(r1), "=r"(r2), "=r"(r3) : "r"(addr))

#define MMA_F16(c, a, b) \
    asm volatile("mma.sync.aligned.m16n8k16.row.col.f32.f16.f16.f32 " \
                 "{%0,%1,%2,%3}, {%4,%5,%6,%7}, {%8,%9}, {%0,%1,%2,%3};" \
                 : "+f"((c)[0]), "+f"((c)[1]), "+f"((c)[2]), "+f"((c)[3]) \
                 : "r"((a)[0]), "r"((a)[1]), "r"((a)[2]), "r"((a)[3]), \
                   "r"((b)[0]), "r"((b)[1]))

__device__ __forceinline__ void split2h(float x, float y, uint32_t& hi, uint32_t& lo) {
    __half hx = __float2half_rn(x), hy = __float2half_rn(y);
    __half lx = __float2half_rn(x - __half2float(hx));
    __half ly = __float2half_rn(y - __half2float(hy));
    __half2 th(hx, hy), tl(lx, ly);
    hi = *(uint32_t*)&th;
    lo = *(uint32_t*)&tl;
}

__device__ __forceinline__ uint32_t pack_h2(float x, float y) {
    __half2 t(__float2half_rn(x), __float2half_rn(y));
    return *(uint32_t*)&t;
}

// ---------------------------------------------------------------------------
// fp32 -> fp16 conversion, one launch: weights (hi only) + x (hi/lo split)
// ---------------------------------------------------------------------------
__global__ __launch_bounds__(256)
void cvt_all(const float* __restrict__ x,
             const float* __restrict__ w0, const float* __restrict__ w1,
             const float* __restrict__ w2, const float* __restrict__ w3,
             __half* __restrict__ xhi, __half* __restrict__ xlo,
             __half* __restrict__ whi)
{
    const int y = blockIdx.y;
    const size_t WSZ4 = (size_t)D_MODEL * D_MODEL / 4;
    int i = blockIdx.x * 256 + threadIdx.x;
    if (y < 4) {
        const float* src = (y == 0) ? w0 : (y == 1) ? w1 : (y == 2) ? w2 : w3;
        __half* hi = whi + (size_t)y * D_MODEL * D_MODEL;
        float4 v = ((const float4*)src)[i];
        ((uint32_t*)hi)[2 * i]     = pack_h2(v.x, v.y);
        ((uint32_t*)hi)[2 * i + 1] = pack_h2(v.z, v.w);
    } else {
        const float* src = x + (size_t)(y - 4) * WSZ4 * 4;
        __half* hi = xhi + (size_t)(y - 4) * WSZ4 * 4;
        __half* lo = xlo + (size_t)(y - 4) * WSZ4 * 4;
        float4 v = ((const float4*)src)[i];
        uint32_t h0, l0, h1, l1;
        split2h(v.x, v.y, h0, l0);
        split2h(v.z, v.w, h1, l1);
        ((uint32_t*)hi)[2 * i] = h0;     ((uint32_t*)hi)[2 * i + 1] = h1;
        ((uint32_t*)lo)[2 * i] = l0;     ((uint32_t*)lo)[2 * i + 1] = l1;
    }
}

// ---------------------------------------------------------------------------
// GEMM core — fp16 2-pass: C = (Ahi + Alo) * Bhi (validated R11-R14 config)
// ---------------------------------------------------------------------------
#define KC        64
#define NCHUNK    (D_MODEL / KC)      // 16
#define TILE_B    16384
#define BUF_B     (3 * TILE_B)
#define GEMM_SMEM (2 * BUF_B)         // 98304

__device__ __forceinline__ void cp_tile(uint32_t dst_base, const __half* src, int tid)
{
#pragma unroll
    for (int u = tid; u < 1024; u += 256) {
        int row = u >> 3, c = u & 7;
        uint32_t off = row * 128 + c * 16;
        CP_ASYNC16(dst_base + SW128(off), src + (size_t)row * D_MODEL + c * 8);
    }
}

__device__ __forceinline__ void gemm_mainloop(
    uint32_t sbase, int tid, int lane, int m0, int n0,
    const __half* pAh, const __half* pAl, const __half* pBh,
    float acc[4][4][4])
{
#pragma unroll
    for (int i = 0; i < 4; i++)
#pragma unroll
        for (int j = 0; j < 4; j++)
#pragma unroll
            for (int r = 0; r < 4; r++) acc[i][j][r] = 0.f;

    const int ra = lane & 15;
    const int ca = lane >> 4;
    const int qb = lane >> 3;
    const int l7 = lane & 7;

    cp_tile(sbase + 0 * TILE_B, pAh, tid);
    cp_tile(sbase + 1 * TILE_B, pAl, tid);
    cp_tile(sbase + 2 * TILE_B, pBh, tid);
    CP_COMMIT();

    for (int ch = 0; ch < NCHUNK; ch++) {
        const int buf = ch & 1;
        if (ch + 1 < NCHUNK) {
            const uint32_t nb = sbase + (buf ^ 1) * BUF_B;
            const int kc = (ch + 1) * KC;
            cp_tile(nb + 0 * TILE_B, pAh + kc, tid);
            cp_tile(nb + 1 * TILE_B, pAl + kc, tid);
            cp_tile(nb + 2 * TILE_B, pBh + kc, tid);
            CP_COMMIT();
            CP_WAIT(1);
        } else {
            CP_WAIT(0);
        }
        __syncthreads();

        const uint32_t aH = sbase + buf * BUF_B + 0 * TILE_B;
        const uint32_t aL = sbase + buf * BUF_B + 1 * TILE_B;
        const uint32_t bH = sbase + buf * BUF_B + 2 * TILE_B;

#pragma unroll
        for (int ks = 0; ks < 4; ks++) {
            uint32_t ah[16], al[16];
#pragma unroll
            for (int i = 0; i < 4; i++) {
                uint32_t off = (uint32_t)(m0 + i * 16 + ra) * 128 + (ks * 2 + ca) * 16;
                uint32_t sw = SW128(off);
                LDSM_X4(ah[4 * i], ah[4 * i + 1], ah[4 * i + 2], ah[4 * i + 3], aH + sw);
                LDSM_X4(al[4 * i], al[4 * i + 1], al[4 * i + 2], al[4 * i + 3], aL + sw);
            }
            uint32_t bh[8];
#pragma unroll
            for (int jj = 0; jj < 2; jj++) {
                uint32_t off = (uint32_t)(n0 + (jj * 2 + (qb >> 1)) * 8 + l7) * 128
                             + (ks * 2 + (qb & 1)) * 16;
                uint32_t sw = SW128(off);
                LDSM_X4(bh[4 * jj], bh[4 * jj + 1], bh[4 * jj + 2], bh[4 * jj + 3], bH + sw);
            }
#pragma unroll
            for (int i = 0; i < 4; i++)
#pragma unroll
                for (int j = 0; j < 4; j++) {
                    MMA_F16(acc[i][j], &ah[4 * i], &bh[2 * j]);
                    MMA_F16(acc[i][j], &al[4 * i], &bh[2 * j]);
                }
        }
        __syncthreads();
    }
}

// ---------------------------------------------------------------------------
// QKV projections, one launch (grid.z = 0:Q, 1:K, 2:V).
// ---------------------------------------------------------------------------
__global__ __launch_bounds__(256, 2)
void gemm_qkv(const __half* __restrict__ Ahi, const __half* __restrict__ Alo,
              const __half* __restrict__ Whi,
              __half* __restrict__ qh, __half* __restrict__ ql,
              __half* __restrict__ kh,
              __half* __restrict__ vth, __half* __restrict__ vtl)
{
    extern __shared__ char smem[];
    const uint32_t sbase = smem_to_u32(smem);
    const int tid = threadIdx.x;
    const int wid = tid >> 5, lane = tid & 31;
    const int bm = blockIdx.y * 128;
    const int bn = blockIdx.x * 128;
    const int z  = blockIdx.z;
    const int m0 = (wid & 1) * 64;
    const int n0 = (wid >> 1) * 32;

    float acc[4][4][4];
    gemm_mainloop(sbase, tid, lane, m0, n0,
                  Ahi + (size_t)bm * D_MODEL,
                  Alo + (size_t)bm * D_MODEL,
                  Whi + (size_t)z * D_MODEL * D_MODEL + (size_t)bn * D_MODEL,
                  acc);

    const int g = lane >> 2, t = lane & 3;

    if (z == 2) {
#pragma unroll
        for (int i = 0; i < 4; i++) {
#pragma unroll
            for (int j = 0; j < 4; j++) {
                const int c  = bn + n0 + j * 8 + 2 * t;
                const int hh = c >> 6, d0 = c & 63;
#pragma unroll
                for (int rr = 0; rr < 4; rr++) {
                    const int row = bm + m0 + i * 16 + g + ((rr >> 1) * 8);
                    const int b = row >> 11, s = row & (SEQ - 1);
                    const int d = d0 + (rr & 1);
                    float v = acc[i][j][rr];
                    __half hv = __float2half_rn(v);
                    __half lv = __float2half_rn(v - __half2float(hv));
                    const size_t dst = ((size_t)((b * NHEAD + hh) * DK + d)) * SEQ + s;
                    vth[dst] = hv;
                    vtl[dst] = lv;
                }
            }
        }
    } else if (z == 0) {
#pragma unroll
        for (int i = 0; i < 4; i++) {
#pragma unroll
            for (int j = 0; j < 4; j++) {
                const int c  = bn + n0 + j * 8 + 2 * t;
                const int hh = c >> 6, d = c & 63;
                const int row0 = bm + m0 + i * 16 + g;
                uint32_t hv, lv;
                {
                    const int b = row0 >> 11, s = row0 & (SEQ - 1);
                    split2h(acc[i][j][0] * 0.125f, acc[i][j][1] * 0.125f, hv, lv);
                    const size_t dst = ((size_t)((b * NHEAD + hh) * SEQ + s)) * DK + d;
                    *(uint32_t*)(qh + dst) = hv;
                    *(uint32_t*)(ql + dst) = lv;
                }
                {
                    const int row1 = row0 + 8;
                    const int b = row1 >> 11, s = row1 & (SEQ - 1);
                    split2h(acc[i][j][2] * 0.125f, acc[i][j][3] * 0.125f, hv, lv);
                    const size_t dst = ((size_t)((b * NHEAD + hh) * SEQ + s)) * DK + d;
                    *(uint32_t*)(qh + dst) = hv;
                    *(uint32_t*)(ql + dst) = lv;
                }
            }
        }
    } else {
#pragma unroll
        for (int i = 0; i < 4; i++) {
#pragma unroll
            for (int j = 0; j < 4; j++) {
                const int c  = bn + n0 + j * 8 + 2 * t;
                const int hh = c >> 6, d = c & 63;
                const int row0 = bm + m0 + i * 16 + g;
                {
                    const int b = row0 >> 11, s = row0 & (SEQ - 1);
                    const size_t dst = ((size_t)((b * NHEAD + hh) * SEQ + s)) * DK + d;
                    *(uint32_t*)(kh + dst) = pack_h2(acc[i][j][0], acc[i][j][1]);
                }
                {
                    const int row1 = row0 + 8;
                    const int b = row1 >> 11, s = row1 & (SEQ - 1);
                    const size_t dst = ((size_t)((b * NHEAD + hh) * SEQ + s)) * DK + d;
                    *(uint32_t*)(kh + dst) = pack_h2(acc[i][j][2], acc[i][j][3]);
                }
            }
        }
    }
}

// ---------------------------------------------------------------------------
// Output projection GEMM (fp32 result to d_out)
// ---------------------------------------------------------------------------
__global__ __launch_bounds__(256, 2)
void gemm_mma(const __half* __restrict__ Ahi, const __half* __restrict__ Alo,
              const __half* __restrict__ Bhi, float* __restrict__ C)
{
    extern __shared__ char smem[];
    const uint32_t sbase = smem_to_u32(smem);
    const int tid = threadIdx.x;
    const int wid = tid >> 5, lane = tid & 31;
    const int bm = blockIdx.y * 128;
    const int bn = blockIdx.x * 128;
    const int m0 = (wid & 1) * 64;
    const int n0 = (wid >> 1) * 32;

    float acc[4][4][4];
    gemm_mainloop(sbase, tid, lane, m0, n0,
                  Ahi + (size_t)bm * D_MODEL,
                  Alo + (size_t)bm * D_MODEL,
                  Bhi + (size_t)bn * D_MODEL,
                  acc);

    const int g = lane >> 2, t = lane & 3;
#pragma unroll
    for (int i = 0; i < 4; i++) {
#pragma unroll
        for (int j = 0; j < 4; j++) {
            float* cp0 = C + (size_t)(bm + m0 + i * 16 + g) * D_MODEL + bn + n0 + j * 8 + 2 * t;
            float* cp1 = cp0 + 8 * D_MODEL;
            *(float2*)cp0 = make_float2(acc[i][j][0], acc[i][j][1]);
            *(float2*)cp1 = make_float2(acc[i][j][2], acc[i][j][3]);
        }
    }
}

// ---------------------------------------------------------------------------
// Tensor-core causal flash attention — fp16 2-pass, R15: double-buffered KV
// (prefetch block k+1 during compute of block k) + up to 3 CTAs/SM.
// smem: Q(hi+lo) 16KB + 2 x (Kh,Vh,Vl) 24KB = 64KB.
// ---------------------------------------------------------------------------
#define ATT_NT    128
#define KV_B      24576
#define ATT_SMEM  (16384 + 2 * KV_B)   // 65536

__global__ __launch_bounds__(ATT_NT, 3)
void attn_mma(const __half* __restrict__ Qh, const __half* __restrict__ Ql,
              const __half* __restrict__ Kh,
              const __half* __restrict__ Vh, const __half* __restrict__ Vl,
              __half* __restrict__ Ohi, __half* __restrict__ Olo)
{
    extern __shared__ char smem[];
    const uint32_t sb = smem_to_u32(smem);
    const int tid = threadIdx.x, wid = tid >> 5, lane = tid & 31;
    const int qblk = gridDim.x - 1 - blockIdx.x;   // heavy CTAs first
    const int bh = blockIdx.y;
    const int b = bh >> 4, h = bh & 15;
    const int qr0 = qblk * 64 + wid * 16;
    const int g = lane >> 2, t = lane & 3;
    const int qb2 = lane >> 3, l7 = lane & 7;
    const int ra = lane & 15, ca = lane >> 4;

    const uint32_t QH = sb, QL = sb + 8192;
    const uint32_t KVB = sb + 16384;   // per buffer: KH +0, VH +8192, VL +16384

    const int nkb = qblk + 1;

    // kv tile loader into buffer `dbuf`
    auto load_kv = [&](uint32_t dbuf, int k0) {
#pragma unroll
        for (int u = tid; u < 512; u += ATT_NT) {
            int r = u >> 3, c = u & 7;
            uint32_t sw = SW128((uint32_t)(r * 128 + c * 16));
            const size_t kg = ((size_t)bh * SEQ + k0 + r) * DK + c * 8;
            CP_ASYNC16(dbuf + sw, Kh + kg);
            const size_t vg = ((size_t)bh * DK + r) * SEQ + k0 + c * 8;
            CP_ASYNC16(dbuf + 8192 + sw,  Vh + vg);
            CP_ASYNC16(dbuf + 16384 + sw, Vl + vg);
        }
    };

    // prologue: Q (group 1), kv0 (group 2); wait for Q only
    {
        const __half* qh_g = Qh + ((size_t)bh * SEQ + qblk * 64) * DK;
        const __half* ql_g = Ql + ((size_t)bh * SEQ + qblk * 64) * DK;
#pragma unroll
        for (int u = tid; u < 512; u += ATT_NT) {
            int row = u >> 3, c = u & 7;
            uint32_t sw = SW128((uint32_t)(row * 128 + c * 16));
            CP_ASYNC16(QH + sw, qh_g + (size_t)row * DK + c * 8);
            CP_ASYNC16(QL + sw, ql_g + (size_t)row * DK + c * 8);
        }
        CP_COMMIT();
    }
    load_kv(KVB, 0);
    CP_COMMIT();
    CP_WAIT(1);          // Q group done; kv0 may still be in flight
    __syncthreads();

    uint32_t qhf[16], qlf[16];
#pragma unroll
    for (int ks = 0; ks < 4; ks++) {
        uint32_t sw = SW128((uint32_t)((wid * 16 + ra) * 128 + (ks * 2 + ca) * 16));
        LDSM_X4(qhf[4 * ks], qhf[4 * ks + 1], qhf[4 * ks + 2], qhf[4 * ks + 3], QH + sw);
        LDSM_X4(qlf[4 * ks], qlf[4 * ks + 1], qlf[4 * ks + 2], qlf[4 * ks + 3], QL + sw);
    }

    float o[8][4];
#pragma unroll
    for (int j = 0; j < 8; j++)
#pragma unroll
        for (int r = 0; r < 4; r++) o[j][r] = 0.f;
    float m0 = NEG_INF, m1 = NEG_INF, l0 = 0.f, l1 = 0.f;

    for (int kb = 0; kb < nkb; kb++) {
        const int buf = kb & 1;
        const int k0 = kb * 64;

        // prefetch next block into the other buffer (safe: end-of-iter sync of
        // kb-1 guarantees all warps finished reading buf^1)
        if (kb + 1 < nkb) {
            load_kv(KVB + (buf ^ 1) * KV_B, (kb + 1) * 64);
            CP_COMMIT();
            CP_WAIT(1);   // current block's group complete
        } else {
            CP_WAIT(0);
        }
        __syncthreads();

        const uint32_t KHs = KVB + buf * KV_B;
        const uint32_t VHs = KHs + 8192;
        const uint32_t VLs = KHs + 16384;

        // --- S = (Qh+Ql) Kh ---
        float sf[8][4];
#pragma unroll
        for (int j = 0; j < 8; j++)
#pragma unroll
            for (int r = 0; r < 4; r++) sf[j][r] = 0.f;

#pragma unroll
        for (int ks = 0; ks < 4; ks++) {
            uint32_t bhf[16];
#pragma unroll
            for (int jj = 0; jj < 4; jj++) {
                uint32_t sw = SW128((uint32_t)(((jj * 2 + (qb2 >> 1)) * 8 + l7) * 128
                                               + (ks * 2 + (qb2 & 1)) * 16));
                LDSM_X4(bhf[4 * jj], bhf[4 * jj + 1], bhf[4 * jj + 2], bhf[4 * jj + 3], KHs + sw);
            }
#pragma unroll
            for (int j = 0; j < 8; j++) {
                MMA_F16(sf[j], &qhf[4 * ks], &bhf[2 * j]);
                MMA_F16(sf[j], &qlf[4 * ks], &bhf[2 * j]);
            }
        }

        if (k0 + 63 > qr0) {
            const int row0 = qr0 + g, row1 = row0 + 8;
#pragma unroll
            for (int j = 0; j < 8; j++) {
                const int key = k0 + 8 * j + 2 * t;
                if (key     > row0) sf[j][0] = NEG_INF;
                if (key + 1 > row0) sf[j][1] = NEG_INF;
                if (key     > row1) sf[j][2] = NEG_INF;
                if (key + 1 > row1) sf[j][3] = NEG_INF;
            }
        }

        float mx0 = NEG_INF, mx1 = NEG_INF;
#pragma unroll
        for (int j = 0; j < 8; j++) {
            mx0 = fmaxf(mx0, fmaxf(sf[j][0], sf[j][1]));
            mx1 = fmaxf(mx1, fmaxf(sf[j][2], sf[j][3]));
        }
        mx0 = fmaxf(mx0, __shfl_xor_sync(0xffffffffu, mx0, 1));
        mx0 = fmaxf(mx0, __shfl_xor_sync(0xffffffffu, mx0, 2));
        mx1 = fmaxf(mx1, __shfl_xor_sync(0xffffffffu, mx1, 1));
        mx1 = fmaxf(mx1, __shfl_xor_sync(0xffffffffu, mx1, 2));
        const float mn0 = fmaxf(m0, mx0), mn1 = fmaxf(m1, mx1);
        const float a0 = __expf(m0 - mn0), a1 = __expf(m1 - mn1);
        m0 = mn0; m1 = mn1;

        float rs0 = 0.f, rs1 = 0.f;
        uint32_t ph[16];
#pragma unroll
        for (int j = 0; j < 8; j++) {
            float p0 = __expf(sf[j][0] - mn0);
            float p1 = __expf(sf[j][1] - mn0);
            float p2 = __expf(sf[j][2] - mn1);
            float p3 = __expf(sf[j][3] - mn1);
            rs0 += p0 + p1;
            rs1 += p2 + p3;
            const int ks2 = j >> 1, hf = j & 1;
            ph[4 * ks2 + 2 * hf]     = pack_h2(p0, p1);
            ph[4 * ks2 + 2 * hf + 1] = pack_h2(p2, p3);
        }
        rs0 += __shfl_xor_sync(0xffffffffu, rs0, 1);
        rs0 += __shfl_xor_sync(0xffffffffu, rs0, 2);
        rs1 += __shfl_xor_sync(0xffffffffu, rs1, 1);
        rs1 += __shfl_xor_sync(0xffffffffu, rs1, 2);
        l0 = l0 * a0 + rs0;
        l1 = l1 * a1 + rs1;

#pragma unroll
        for (int j = 0; j < 8; j++) {
            o[j][0] *= a0; o[j][1] *= a0;
            o[j][2] *= a1; o[j][3] *= a1;
        }

        // --- O += Ph (Vh + Vl) ---
#pragma unroll
        for (int ks = 0; ks < 4; ks++) {
            uint32_t vhf[16], vlf[16];
#pragma unroll
            for (int jj = 0; jj < 4; jj++) {
                uint32_t sw = SW128((uint32_t)(((jj * 2 + (qb2 >> 1)) * 8 + l7) * 128
                                               + (ks * 2 + (qb2 & 1)) * 16));
                LDSM_X4(vhf[4 * jj], vhf[4 * jj + 1], vhf[4 * jj + 2], vhf[4 * jj + 3], VHs + sw);
                LDSM_X4(vlf[4 * jj], vlf[4 * jj + 1], vlf[4 * jj + 2], vlf[4 * jj + 3], VLs + sw);
            }
#pragma unroll
            for (int j = 0; j < 8; j++) {
                MMA_F16(o[j], &ph[4 * ks], &vhf[2 * j]);
                MMA_F16(o[j], &ph[4 * ks], &vlf[2 * j]);
            }
        }

        __syncthreads();   // all reads of this buffer done before it is reused
    }

    const float il0 = 1.f / l0, il1 = 1.f / l1;
    const size_t r0 = (size_t)(b * SEQ + qr0 + g) * D_MODEL + h * DK;
    const size_t r1 = r0 + (size_t)8 * D_MODEL;
#pragma unroll
    for (int j = 0; j < 8; j++) {
        const int c = 8 * j + 2 * t;
        uint32_t hv, lv;
        split2h(o[j][0] * il0, o[j][1] * il0, hv, lv);
        *(uint32_t*)(Ohi + r0 + c) = hv;
        *(uint32_t*)(Olo + r0 + c) = lv;
        split2h(o[j][2] * il1, o[j][3] * il1, hv, lv);
        *(uint32_t*)(Ohi + r1 + c) = hv;
        *(uint32_t*)(Olo + r1 + c) = lv;
    }
}

// ---------------------------------------------------------------------------
extern "C" void kernel_launch(void* const* d_in, const int* in_sizes, int n_in,
                              void* d_out, int out_size)
{
    (void)in_sizes; (void)n_in; (void)out_size;
    const float* x  = (const float*)d_in[0];
    const float* Wq = (const float*)d_in[1];
    const float* Wk = (const float*)d_in[2];
    const float* Wv = (const float*)d_in[3];
    const float* Wo = (const float*)d_in[4];
    float* out = (float*)d_out;

    __half *xhi, *xlo, *ohi, *olo, *whi;
    cudaGetSymbolAddress((void**)&xhi, g_x_hi);
    cudaGetSymbolAddress((void**)&xlo, g_x_lo);
    cudaGetSymbolAddress((void**)&ohi, g_o_hi);
    cudaGetSymbolAddress((void**)&olo, g_o_lo);
    cudaGetSymbolAddress((void**)&whi, g_w_hi);
    __half *qh, *ql, *kh, *vth, *vtl;
    cudaGetSymbolAddress((void**)&qh,  g_qh);
    cudaGetSymbolAddress((void**)&ql,  g_ql);
    cudaGetSymbolAddress((void**)&kh,  g_kh);
    cudaGetSymbolAddress((void**)&vth, g_vth);
    cudaGetSymbolAddress((void**)&vtl, g_vtl);

    cudaFuncSetAttribute(gemm_qkv, cudaFuncAttributeMaxDynamicSharedMemorySize, GEMM_SMEM);
    cudaFuncSetAttribute(gemm_mma, cudaFuncAttributeMaxDynamicSharedMemorySize, GEMM_SMEM);
    cudaFuncSetAttribute(attn_mma, cudaFuncAttributeMaxDynamicSharedMemorySize, ATT_SMEM);

    const int NW4 = D_MODEL * D_MODEL / 4;   // 262,144
    const int WSZ = D_MODEL * D_MODEL;

    cvt_all<<<dim3(NW4 / 256, 8), 256>>>(x, Wq, Wk, Wv, Wo, xhi, xlo, whi);

    gemm_qkv<<<dim3(D_MODEL / 128, MTOT / 128, 3), 256, GEMM_SMEM>>>(
        xhi, xlo, whi, qh, ql, kh, vth, vtl);

    attn_mma<<<dim3(SEQ / 64, BH), ATT_NT, ATT_SMEM>>>(qh, ql, kh, vth, vtl, ohi, olo);

    gemm_mma<<<dim3(D_MODEL / 128, MTOT / 128), 256, GEMM_SMEM>>>(
        ohi, olo, whi + 3 * WSZ, out);
}

// round 16
// speedup vs baseline: 2.4395x; 1.0268x over previous
#include <cuda_runtime.h>
#include <cuda_bf16.h>
#include <cuda_fp16.h>
#include <cstdint>

#define D_MODEL 1024
#define NHEAD   16
#define DK      64
#define BATCH   2
#define SEQ     2048
#define MTOT    (BATCH * SEQ)   // 4096
#define BH      (BATCH * NHEAD) // 32

#define NEG_INF __int_as_float(0xff800000)

// ---------------------------------------------------------------------------
// Scratch (__device__ globals: allocations are forbidden)
// ---------------------------------------------------------------------------
__device__ __half g_x_hi[MTOT * D_MODEL];
__device__ __half g_x_lo[MTOT * D_MODEL];
__device__ __half g_o_hi[MTOT * D_MODEL];
__device__ __half g_o_lo[MTOT * D_MODEL];
__device__ __half g_w_hi[4][D_MODEL * D_MODEL];   // fp16 hi only (2-pass scheme)

// head-major fp16 for attention
__device__ __half g_qh[BH * SEQ * DK];
__device__ __half g_ql[BH * SEQ * DK];
__device__ __half g_kh[BH * SEQ * DK];            // K hi only
__device__ __half g_vth[BH * DK * SEQ];           // transposed: [bh][d][s]
__device__ __half g_vtl[BH * DK * SEQ];

// ---------------------------------------------------------------------------
// Base-ISA helpers (NO tcgen05 — harness ptxas targets plain sm_103)
// ---------------------------------------------------------------------------
__device__ __forceinline__ uint32_t smem_to_u32(const void* p) {
    uint32_t a;
    asm("{ .reg .u64 t; cvta.to.shared.u64 t, %1; cvt.u32.u64 %0, t; }" : "=r"(a) : "l"(p));
    return a;
}
#define SW128(o) ((o) ^ (((o) >> 3) & 0x70))

#define CP_ASYNC16(dst, src) \
    asm volatile("cp.async.cg.shared.global [%0], [%1], 16;" :: "r"(dst), "l"(src))
#define CP_COMMIT() asm volatile("cp.async.commit_group;" ::: "memory")
#define CP_WAIT(n)  asm volatile("cp.async.wait_group %0;" :: "n"(n) : "memory")

#define LDSM_X4(r0, r1, r2, r3, addr) \
    asm volatile("ldmatrix.sync.aligned.m8n8.x4.shared.b16 {%0,%1,%2,%3}, [%4];" \
                 : "=r"(r0), "=r"(r1), "=r"(r2), "=r"(r3) : "r"(addr))

#define MMA_F16(c, a, b) \
    asm volatile("mma.sync.aligned.m16n8k16.row.col.f32.f16.f16.f32 " \
                 "{%0,%1,%2,%3}, {%4,%5,%6,%7}, {%8,%9}, {%0,%1,%2,%3};" \
                 : "+f"((c)[0]), "+f"((c)[1]), "+f"((c)[2]), "+f"((c)[3]) \
                 : "r"((a)[0]), "r"((a)[1]), "r"((a)[2]), "r"((a)[3]), \
                   "r"((b)[0]), "r"((b)[1]))

__device__ __forceinline__ void split2h(float x, float y, uint32_t& hi, uint32_t& lo) {
    __half hx = __float2half_rn(x), hy = __float2half_rn(y);
    __half lx = __float2half_rn(x - __half2float(hx));
    __half ly = __float2half_rn(y - __half2float(hy));
    __half2 th(hx, hy), tl(lx, ly);
    hi = *(uint32_t*)&th;
    lo = *(uint32_t*)&tl;
}

__device__ __forceinline__ uint32_t pack_h2(float x, float y) {
    __half2 t(__float2half_rn(x), __float2half_rn(y));
    return *(uint32_t*)&t;
}

// ---------------------------------------------------------------------------
// fp32 -> fp16 conversion, one launch: weights (hi only) + x (hi/lo split)
// ---------------------------------------------------------------------------
__global__ __launch_bounds__(256)
void cvt_all(const float* __restrict__ x,
             const float* __restrict__ w0, const float* __restrict__ w1,
             const float* __restrict__ w2, const float* __restrict__ w3,
             __half* __restrict__ xhi, __half* __restrict__ xlo,
             __half* __restrict__ whi)
{
    const int y = blockIdx.y;
    const size_t WSZ4 = (size_t)D_MODEL * D_MODEL / 4;
    int i = blockIdx.x * 256 + threadIdx.x;
    if (y < 4) {
        const float* src = (y == 0) ? w0 : (y == 1) ? w1 : (y == 2) ? w2 : w3;
        __half* hi = whi + (size_t)y * D_MODEL * D_MODEL;
        float4 v = ((const float4*)src)[i];
        ((uint32_t*)hi)[2 * i]     = pack_h2(v.x, v.y);
        ((uint32_t*)hi)[2 * i + 1] = pack_h2(v.z, v.w);
    } else {
        const float* src = x + (size_t)(y - 4) * WSZ4 * 4;
        __half* hi = xhi + (size_t)(y - 4) * WSZ4 * 4;
        __half* lo = xlo + (size_t)(y - 4) * WSZ4 * 4;
        float4 v = ((const float4*)src)[i];
        uint32_t h0, l0, h1, l1;
        split2h(v.x, v.y, h0, l0);
        split2h(v.z, v.w, h1, l1);
        ((uint32_t*)hi)[2 * i] = h0;     ((uint32_t*)hi)[2 * i + 1] = h1;
        ((uint32_t*)lo)[2 * i] = l0;     ((uint32_t*)lo)[2 * i + 1] = l1;
    }
}

// ---------------------------------------------------------------------------
// GEMM core — fp16 2-pass: C = (Ahi + Alo) * Bhi
// R16: CTA tile 128x256, 8 warps (2x4), warp tile 64x64 (better MMA:LDSM ratio)
// KC=64, double buffering. smem/chunk: Ahi 16K + Alo 16K + Bh 32K = 64K.
// ---------------------------------------------------------------------------
#define KC        64
#define NCHUNK    (D_MODEL / KC)      // 16
#define TILE_A    16384               // 128 rows x 128 B
#define TILE_BB   32768               // 256 rows x 128 B
#define BUF_B     (2 * TILE_A + TILE_BB)   // 65536
#define GEMM_SMEM (2 * BUF_B)              // 131072

__device__ __forceinline__ void cp_tileA(uint32_t dst_base, const __half* src, int tid)
{
#pragma unroll
    for (int u = tid; u < 1024; u += 256) {
        int row = u >> 3, c = u & 7;
        uint32_t off = row * 128 + c * 16;
        CP_ASYNC16(dst_base + SW128(off), src + (size_t)row * D_MODEL + c * 8);
    }
}

__device__ __forceinline__ void cp_tileB(uint32_t dst_base, const __half* src, int tid)
{
#pragma unroll
    for (int u = tid; u < 2048; u += 256) {
        int row = u >> 3, c = u & 7;
        uint32_t off = row * 128 + c * 16;
        CP_ASYNC16(dst_base + SW128(off), src + (size_t)row * D_MODEL + c * 8);
    }
}

__device__ __forceinline__ void gemm_mainloop(
    uint32_t sbase, int tid, int lane, int m0, int n0,
    const __half* pAh, const __half* pAl, const __half* pBh,
    float acc[4][8][4])
{
#pragma unroll
    for (int i = 0; i < 4; i++)
#pragma unroll
        for (int j = 0; j < 8; j++)
#pragma unroll
            for (int r = 0; r < 4; r++) acc[i][j][r] = 0.f;

    const int ra = lane & 15;
    const int ca = lane >> 4;
    const int qb = lane >> 3;
    const int l7 = lane & 7;

    cp_tileA(sbase + 0 * TILE_A, pAh, tid);
    cp_tileA(sbase + 1 * TILE_A, pAl, tid);
    cp_tileB(sbase + 2 * TILE_A, pBh, tid);
    CP_COMMIT();

    for (int ch = 0; ch < NCHUNK; ch++) {
        const int buf = ch & 1;
        if (ch + 1 < NCHUNK) {
            const uint32_t nb = sbase + (buf ^ 1) * BUF_B;
            const int kc = (ch + 1) * KC;
            cp_tileA(nb + 0 * TILE_A, pAh + kc, tid);
            cp_tileA(nb + 1 * TILE_A, pAl + kc, tid);
            cp_tileB(nb + 2 * TILE_A, pBh + kc, tid);
            CP_COMMIT();
            CP_WAIT(1);
        } else {
            CP_WAIT(0);
        }
        __syncthreads();

        const uint32_t aH = sbase + buf * BUF_B + 0 * TILE_A;
        const uint32_t aL = sbase + buf * BUF_B + 1 * TILE_A;
        const uint32_t bH = sbase + buf * BUF_B + 2 * TILE_A;

#pragma unroll
        for (int ks = 0; ks < 4; ks++) {
            uint32_t ah[16], al[16];
#pragma unroll
            for (int i = 0; i < 4; i++) {
                uint32_t off = (uint32_t)(m0 + i * 16 + ra) * 128 + (ks * 2 + ca) * 16;
                uint32_t sw = SW128(off);
                LDSM_X4(ah[4 * i], ah[4 * i + 1], ah[4 * i + 2], ah[4 * i + 3], aH + sw);
                LDSM_X4(al[4 * i], al[4 * i + 1], al[4 * i + 2], al[4 * i + 3], aL + sw);
            }
            // 64-column B fragments (validated recipe from attention kernel)
            uint32_t bh[16];
#pragma unroll
            for (int jj = 0; jj < 4; jj++) {
                uint32_t off = (uint32_t)((n0 + (jj * 2 + (qb >> 1)) * 8 + l7) * 128
                                          + (ks * 2 + (qb & 1)) * 16);
                uint32_t sw = SW128(off);
                LDSM_X4(bh[4 * jj], bh[4 * jj + 1], bh[4 * jj + 2], bh[4 * jj + 3], bH + sw);
            }
#pragma unroll
            for (int i = 0; i < 4; i++)
#pragma unroll
                for (int j = 0; j < 8; j++) {
                    MMA_F16(acc[i][j], &ah[4 * i], &bh[2 * j]);
                    MMA_F16(acc[i][j], &al[4 * i], &bh[2 * j]);
                }
        }
        __syncthreads();
    }
}

// ---------------------------------------------------------------------------
// QKV projections, one launch (grid.z = 0:Q, 1:K, 2:V). CTA tile 128x256.
// ---------------------------------------------------------------------------
__global__ __launch_bounds__(256, 1)
void gemm_qkv(const __half* __restrict__ Ahi, const __half* __restrict__ Alo,
              const __half* __restrict__ Whi,
              __half* __restrict__ qh, __half* __restrict__ ql,
              __half* __restrict__ kh,
              __half* __restrict__ vth, __half* __restrict__ vtl)
{
    extern __shared__ char smem[];
    const uint32_t sbase = smem_to_u32(smem);
    const int tid = threadIdx.x;
    const int wid = tid >> 5, lane = tid & 31;
    const int bm = blockIdx.y * 128;
    const int bn = blockIdx.x * 256;
    const int z  = blockIdx.z;
    const int m0 = (wid & 1) * 64;
    const int n0 = (wid >> 1) * 64;

    float acc[4][8][4];
    gemm_mainloop(sbase, tid, lane, m0, n0,
                  Ahi + (size_t)bm * D_MODEL,
                  Alo + (size_t)bm * D_MODEL,
                  Whi + (size_t)z * D_MODEL * D_MODEL + (size_t)bn * D_MODEL,
                  acc);

    const int g = lane >> 2, t = lane & 3;

    if (z == 2) {
#pragma unroll
        for (int i = 0; i < 4; i++) {
#pragma unroll
            for (int j = 0; j < 8; j++) {
                const int c  = bn + n0 + j * 8 + 2 * t;
                const int hh = c >> 6, d0 = c & 63;
#pragma unroll
                for (int rr = 0; rr < 4; rr++) {
                    const int row = bm + m0 + i * 16 + g + ((rr >> 1) * 8);
                    const int b = row >> 11, s = row & (SEQ - 1);
                    const int d = d0 + (rr & 1);
                    float v = acc[i][j][rr];
                    __half hv = __float2half_rn(v);
                    __half lv = __float2half_rn(v - __half2float(hv));
                    const size_t dst = ((size_t)((b * NHEAD + hh) * DK + d)) * SEQ + s;
                    vth[dst] = hv;
                    vtl[dst] = lv;
                }
            }
        }
    } else if (z == 0) {
#pragma unroll
        for (int i = 0; i < 4; i++) {
#pragma unroll
            for (int j = 0; j < 8; j++) {
                const int c  = bn + n0 + j * 8 + 2 * t;
                const int hh = c >> 6, d = c & 63;
                const int row0 = bm + m0 + i * 16 + g;
                uint32_t hv, lv;
                {
                    const int b = row0 >> 11, s = row0 & (SEQ - 1);
                    split2h(acc[i][j][0] * 0.125f, acc[i][j][1] * 0.125f, hv, lv);
                    const size_t dst = ((size_t)((b * NHEAD + hh) * SEQ + s)) * DK + d;
                    *(uint32_t*)(qh + dst) = hv;
                    *(uint32_t*)(ql + dst) = lv;
                }
                {
                    const int row1 = row0 + 8;
                    const int b = row1 >> 11, s = row1 & (SEQ - 1);
                    split2h(acc[i][j][2] * 0.125f, acc[i][j][3] * 0.125f, hv, lv);
                    const size_t dst = ((size_t)((b * NHEAD + hh) * SEQ + s)) * DK + d;
                    *(uint32_t*)(qh + dst) = hv;
                    *(uint32_t*)(ql + dst) = lv;
                }
            }
        }
    } else {
#pragma unroll
        for (int i = 0; i < 4; i++) {
#pragma unroll
            for (int j = 0; j < 8; j++) {
                const int c  = bn + n0 + j * 8 + 2 * t;
                const int hh = c >> 6, d = c & 63;
                const int row0 = bm + m0 + i * 16 + g;
                {
                    const int b = row0 >> 11, s = row0 & (SEQ - 1);
                    const size_t dst = ((size_t)((b * NHEAD + hh) * SEQ + s)) * DK + d;
                    *(uint32_t*)(kh + dst) = pack_h2(acc[i][j][0], acc[i][j][1]);
                }
                {
                    const int row1 = row0 + 8;
                    const int b = row1 >> 11, s = row1 & (SEQ - 1);
                    const size_t dst = ((size_t)((b * NHEAD + hh) * SEQ + s)) * DK + d;
                    *(uint32_t*)(kh + dst) = pack_h2(acc[i][j][2], acc[i][j][3]);
                }
            }
        }
    }
}

// ---------------------------------------------------------------------------
// Output projection GEMM (fp32 result to d_out). CTA tile 128x256.
// ---------------------------------------------------------------------------
__global__ __launch_bounds__(256, 1)
void gemm_mma(const __half* __restrict__ Ahi, const __half* __restrict__ Alo,
              const __half* __restrict__ Bhi, float* __restrict__ C)
{
    extern __shared__ char smem[];
    const uint32_t sbase = smem_to_u32(smem);
    const int tid = threadIdx.x;
    const int wid = tid >> 5, lane = tid & 31;
    const int bm = blockIdx.y * 128;
    const int bn = blockIdx.x * 256;
    const int m0 = (wid & 1) * 64;
    const int n0 = (wid >> 1) * 64;

    float acc[4][8][4];
    gemm_mainloop(sbase, tid, lane, m0, n0,
                  Ahi + (size_t)bm * D_MODEL,
                  Alo + (size_t)bm * D_MODEL,
                  Bhi + (size_t)bn * D_MODEL,
                  acc);

    const int g = lane >> 2, t = lane & 3;
#pragma unroll
    for (int i = 0; i < 4; i++) {
#pragma unroll
        for (int j = 0; j < 8; j++) {
            float* cp0 = C + (size_t)(bm + m0 + i * 16 + g) * D_MODEL + bn + n0 + j * 8 + 2 * t;
            float* cp1 = cp0 + 8 * D_MODEL;
            *(float2*)cp0 = make_float2(acc[i][j][0], acc[i][j][1]);
            *(float2*)cp1 = make_float2(acc[i][j][2], acc[i][j][3]);
        }
    }
}

// ---------------------------------------------------------------------------
// Tensor-core causal flash attention — fp16 2-pass, double-buffered KV,
// up to 3 CTAs/SM (validated R15, unchanged).
// ---------------------------------------------------------------------------
#define ATT_NT    128
#define KV_B      24576
#define ATT_SMEM  (16384 + 2 * KV_B)   // 65536

__global__ __launch_bounds__(ATT_NT, 3)
void attn_mma(const __half* __restrict__ Qh, const __half* __restrict__ Ql,
              const __half* __restrict__ Kh,
              const __half* __restrict__ Vh, const __half* __restrict__ Vl,
              __half* __restrict__ Ohi, __half* __restrict__ Olo)
{
    extern __shared__ char smem[];
    const uint32_t sb = smem_to_u32(smem);
    const int tid = threadIdx.x, wid = tid >> 5, lane = tid & 31;
    const int qblk = gridDim.x - 1 - blockIdx.x;   // heavy CTAs first
    const int bh = blockIdx.y;
    const int b = bh >> 4, h = bh & 15;
    const int qr0 = qblk * 64 + wid * 16;
    const int g = lane >> 2, t = lane & 3;
    const int qb2 = lane >> 3, l7 = lane & 7;
    const int ra = lane & 15, ca = lane >> 4;

    const uint32_t QH = sb, QL = sb + 8192;
    const uint32_t KVB = sb + 16384;   // per buffer: KH +0, VH +8192, VL +16384

    const int nkb = qblk + 1;

    auto load_kv = [&](uint32_t dbuf, int k0) {
#pragma unroll
        for (int u = tid; u < 512; u += ATT_NT) {
            int r = u >> 3, c = u & 7;
            uint32_t sw = SW128((uint32_t)(r * 128 + c * 16));
            const size_t kg = ((size_t)bh * SEQ + k0 + r) * DK + c * 8;
            CP_ASYNC16(dbuf + sw, Kh + kg);
            const size_t vg = ((size_t)bh * DK + r) * SEQ + k0 + c * 8;
            CP_ASYNC16(dbuf + 8192 + sw,  Vh + vg);
            CP_ASYNC16(dbuf + 16384 + sw, Vl + vg);
        }
    };

    {
        const __half* qh_g = Qh + ((size_t)bh * SEQ + qblk * 64) * DK;
        const __half* ql_g = Ql + ((size_t)bh * SEQ + qblk * 64) * DK;
#pragma unroll
        for (int u = tid; u < 512; u += ATT_NT) {
            int row = u >> 3, c = u & 7;
            uint32_t sw = SW128((uint32_t)(row * 128 + c * 16));
            CP_ASYNC16(QH + sw, qh_g + (size_t)row * DK + c * 8);
            CP_ASYNC16(QL + sw, ql_g + (size_t)row * DK + c * 8);
        }
        CP_COMMIT();
    }
    load_kv(KVB, 0);
    CP_COMMIT();
    CP_WAIT(1);
    __syncthreads();

    uint32_t qhf[16], qlf[16];
#pragma unroll
    for (int ks = 0; ks < 4; ks++) {
        uint32_t sw = SW128((uint32_t)((wid * 16 + ra) * 128 + (ks * 2 + ca) * 16));
        LDSM_X4(qhf[4 * ks], qhf[4 * ks + 1], qhf[4 * ks + 2], qhf[4 * ks + 3], QH + sw);
        LDSM_X4(qlf[4 * ks], qlf[4 * ks + 1], qlf[4 * ks + 2], qlf[4 * ks + 3], QL + sw);
    }

    float o[8][4];
#pragma unroll
    for (int j = 0; j < 8; j++)
#pragma unroll
        for (int r = 0; r < 4; r++) o[j][r] = 0.f;
    float m0 = NEG_INF, m1 = NEG_INF, l0 = 0.f, l1 = 0.f;

    for (int kb = 0; kb < nkb; kb++) {
        const int buf = kb & 1;
        const int k0 = kb * 64;

        if (kb + 1 < nkb) {
            load_kv(KVB + (buf ^ 1) * KV_B, (kb + 1) * 64);
            CP_COMMIT();
            CP_WAIT(1);
        } else {
            CP_WAIT(0);
        }
        __syncthreads();

        const uint32_t KHs = KVB + buf * KV_B;
        const uint32_t VHs = KHs + 8192;
        const uint32_t VLs = KHs + 16384;

        float sf[8][4];
#pragma unroll
        for (int j = 0; j < 8; j++)
#pragma unroll
            for (int r = 0; r < 4; r++) sf[j][r] = 0.f;

#pragma unroll
        for (int ks = 0; ks < 4; ks++) {
            uint32_t bhf[16];
#pragma unroll
            for (int jj = 0; jj < 4; jj++) {
                uint32_t sw = SW128((uint32_t)(((jj * 2 + (qb2 >> 1)) * 8 + l7) * 128
                                               + (ks * 2 + (qb2 & 1)) * 16));
                LDSM_X4(bhf[4 * jj], bhf[4 * jj + 1], bhf[4 * jj + 2], bhf[4 * jj + 3], KHs + sw);
            }
#pragma unroll
            for (int j = 0; j < 8; j++) {
                MMA_F16(sf[j], &qhf[4 * ks], &bhf[2 * j]);
                MMA_F16(sf[j], &qlf[4 * ks], &bhf[2 * j]);
            }
        }

        if (k0 + 63 > qr0) {
            const int row0 = qr0 + g, row1 = row0 + 8;
#pragma unroll
            for (int j = 0; j < 8; j++) {
                const int key = k0 + 8 * j + 2 * t;
                if (key     > row0) sf[j][0] = NEG_INF;
                if (key + 1 > row0) sf[j][1] = NEG_INF;
                if (key     > row1) sf[j][2] = NEG_INF;
                if (key + 1 > row1) sf[j][3] = NEG_INF;
            }
        }

        float mx0 = NEG_INF, mx1 = NEG_INF;
#pragma unroll
        for (int j = 0; j < 8; j++) {
            mx0 = fmaxf(mx0, fmaxf(sf[j][0], sf[j][1]));
            mx1 = fmaxf(mx1, fmaxf(sf[j][2], sf[j][3]));
        }
        mx0 = fmaxf(mx0, __shfl_xor_sync(0xffffffffu, mx0, 1));
        mx0 = fmaxf(mx0, __shfl_xor_sync(0xffffffffu, mx0, 2));
        mx1 = fmaxf(mx1, __shfl_xor_sync(0xffffffffu, mx1, 1));
        mx1 = fmaxf(mx1, __shfl_xor_sync(0xffffffffu, mx1, 2));
        const float mn0 = fmaxf(m0, mx0), mn1 = fmaxf(m1, mx1);
        const float a0 = __expf(m0 - mn0), a1 = __expf(m1 - mn1);
        m0 = mn0; m1 = mn1;

        float rs0 = 0.f, rs1 = 0.f;
        uint32_t ph[16];
#pragma unroll
        for (int j = 0; j < 8; j++) {
            float p0 = __expf(sf[j][0] - mn0);
            float p1 = __expf(sf[j][1] - mn0);
            float p2 = __expf(sf[j][2] - mn1);
            float p3 = __expf(sf[j][3] - mn1);
            rs0 += p0 + p1;
            rs1 += p2 + p3;
            const int ks2 = j >> 1, hf = j & 1;
            ph[4 * ks2 + 2 * hf]     = pack_h2(p0, p1);
            ph[4 * ks2 + 2 * hf + 1] = pack_h2(p2, p3);
        }
        rs0 += __shfl_xor_sync(0xffffffffu, rs0, 1);
        rs0 += __shfl_xor_sync(0xffffffffu, rs0, 2);
        rs1 += __shfl_xor_sync(0xffffffffu, rs1, 1);
        rs1 += __shfl_xor_sync(0xffffffffu, rs1, 2);
        l0 = l0 * a0 + rs0;
        l1 = l1 * a1 + rs1;

#pragma unroll
        for (int j = 0; j < 8; j++) {
            o[j][0] *= a0; o[j][1] *= a0;
            o[j][2] *= a1; o[j][3] *= a1;
        }

#pragma unroll
        for (int ks = 0; ks < 4; ks++) {
            uint32_t vhf[16], vlf[16];
#pragma unroll
            for (int jj = 0; jj < 4; jj++) {
                uint32_t sw = SW128((uint32_t)(((jj * 2 + (qb2 >> 1)) * 8 + l7) * 128
                                               + (ks * 2 + (qb2 & 1)) * 16));
                LDSM_X4(vhf[4 * jj], vhf[4 * jj + 1], vhf[4 * jj + 2], vhf[4 * jj + 3], VHs + sw);
                LDSM_X4(vlf[4 * jj], vlf[4 * jj + 1], vlf[4 * jj + 2], vlf[4 * jj + 3], VLs + sw);
            }
#pragma unroll
            for (int j = 0; j < 8; j++) {
                MMA_F16(o[j], &ph[4 * ks], &vhf[2 * j]);
                MMA_F16(o[j], &ph[4 * ks], &vlf[2 * j]);
            }
        }

        __syncthreads();
    }

    const float il0 = 1.f / l0, il1 = 1.f / l1;
    const size_t r0 = (size_t)(b * SEQ + qr0 + g) * D_MODEL + h * DK;
    const size_t r1 = r0 + (size_t)8 * D_MODEL;
#pragma unroll
    for (int j = 0; j < 8; j++) {
        const int c = 8 * j + 2 * t;
        uint32_t hv, lv;
        split2h(o[j][0] * il0, o[j][1] * il0, hv, lv);
        *(uint32_t*)(Ohi + r0 + c) = hv;
        *(uint32_t*)(Olo + r0 + c) = lv;
        split2h(o[j][2] * il1, o[j][3] * il1, hv, lv);
        *(uint32_t*)(Ohi + r1 + c) = hv;
        *(uint32_t*)(Olo + r1 + c) = lv;
    }
}

// ---------------------------------------------------------------------------
extern "C" void kernel_launch(void* const* d_in, const int* in_sizes, int n_in,
                              void* d_out, int out_size)
{
    (void)in_sizes; (void)n_in; (void)out_size;
    const float* x  = (const float*)d_in[0];
    const float* Wq = (const float*)d_in[1];
    const float* Wk = (const float*)d_in[2];
    const float* Wv = (const float*)d_in[3];
    const float* Wo = (const float*)d_in[4];
    float* out = (float*)d_out;

    __half *xhi, *xlo, *ohi, *olo, *whi;
    cudaGetSymbolAddress((void**)&xhi, g_x_hi);
    cudaGetSymbolAddress((void**)&xlo, g_x_lo);
    cudaGetSymbolAddress((void**)&ohi, g_o_hi);
    cudaGetSymbolAddress((void**)&olo, g_o_lo);
    cudaGetSymbolAddress((void**)&whi, g_w_hi);
    __half *qh, *ql, *kh, *vth, *vtl;
    cudaGetSymbolAddress((void**)&qh,  g_qh);
    cudaGetSymbolAddress((void**)&ql,  g_ql);
    cudaGetSymbolAddress((void**)&kh,  g_kh);
    cudaGetSymbolAddress((void**)&vth, g_vth);
    cudaGetSymbolAddress((void**)&vtl, g_vtl);

    cudaFuncSetAttribute(gemm_qkv, cudaFuncAttributeMaxDynamicSharedMemorySize, GEMM_SMEM);
    cudaFuncSetAttribute(gemm_mma, cudaFuncAttributeMaxDynamicSharedMemorySize, GEMM_SMEM);
    cudaFuncSetAttribute(attn_mma, cudaFuncAttributeMaxDynamicSharedMemorySize, ATT_SMEM);

    const int NW4 = D_MODEL * D_MODEL / 4;   // 262,144
    const int WSZ = D_MODEL * D_MODEL;

    cvt_all<<<dim3(NW4 / 256, 8), 256>>>(x, Wq, Wk, Wv, Wo, xhi, xlo, whi);

    gemm_qkv<<<dim3(D_MODEL / 256, MTOT / 128, 3), 256, GEMM_SMEM>>>(
        xhi, xlo, whi, qh, ql, kh, vth, vtl);

    attn_mma<<<dim3(SEQ / 64, BH), ATT_NT, ATT_SMEM>>>(qh, ql, kh, vth, vtl, ohi, olo);

    gemm_mma<<<dim3(D_MODEL / 256, MTOT / 128), 256, GEMM_SMEM>>>(
        ohi, olo, whi + 3 * WSZ, out);
}

// round 17
// speedup vs baseline: 3.1614x; 1.2959x over previous
#include <cuda_runtime.h>
#include <cuda_bf16.h>
#include <cuda_fp16.h>
#include <cstdint>

#define D_MODEL 1024
#define NHEAD   16
#define DK      64
#define BATCH   2
#define SEQ     2048
#define MTOT    (BATCH * SEQ)   // 4096
#define BH      (BATCH * NHEAD) // 32

#define NEG_INF __int_as_float(0xff800000)

// ---------------------------------------------------------------------------
// Scratch (__device__ globals: allocations are forbidden)
// ---------------------------------------------------------------------------
__device__ __half g_x_hi[MTOT * D_MODEL];
__device__ __half g_o_hi[MTOT * D_MODEL];
__device__ __half g_w_hi[4][D_MODEL * D_MODEL];   // fp16 (pure fp16 GEMMs)

// head-major fp16 for attention (attention keeps internal hi/lo splits)
__device__ __half g_qh[BH * SEQ * DK];
__device__ __half g_ql[BH * SEQ * DK];
__device__ __half g_kh[BH * SEQ * DK];            // K hi only
__device__ __half g_vth[BH * DK * SEQ];           // transposed: [bh][d][s]
__device__ __half g_vtl[BH * DK * SEQ];

// ---------------------------------------------------------------------------
// Base-ISA helpers (NO tcgen05 — harness ptxas targets plain sm_103)
// ---------------------------------------------------------------------------
__device__ __forceinline__ uint32_t smem_to_u32(const void* p) {
    uint32_t a;
    asm("{ .reg .u64 t; cvta.to.shared.u64 t, %1; cvt.u32.u64 %0, t; }" : "=r"(a) : "l"(p));
    return a;
}
#define SW128(o) ((o) ^ (((o) >> 3) & 0x70))

#define CP_ASYNC16(dst, src) \
    asm volatile("cp.async.cg.shared.global [%0], [%1], 16;" :: "r"(dst), "l"(src))
#define CP_COMMIT() asm volatile("cp.async.commit_group;" ::: "memory")
#define CP_WAIT(n)  asm volatile("cp.async.wait_group %0;" :: "n"(n) : "memory")

#define LDSM_X4(r0, r1, r2, r3, addr) \
    asm volatile("ldmatrix.sync.aligned.m8n8.x4.shared.b16 {%0,%1,%2,%3}, [%4];" \
                 : "=r"(r0), "=r"(r1), "=r"(r2), "=r"(r3) : "r"(addr))

#define MMA_F16(c, a, b) \
    asm volatile("mma.sync.aligned.m16n8k16.row.col.f32.f16.f16.f32 " \
                 "{%0,%1,%2,%3}, {%4,%5,%6,%7}, {%8,%9}, {%0,%1,%2,%3};" \
                 : "+f"((c)[0]), "+f"((c)[1]), "+f"((c)[2]), "+f"((c)[3]) \
                 : "r"((a)[0]), "r"((a)[1]), "r"((a)[2]), "r"((a)[3]), \
                   "r"((b)[0]), "r"((b)[1]))

__device__ __forceinline__ void split2h(float x, float y, uint32_t& hi, uint32_t& lo) {
    __half hx = __float2half_rn(x), hy = __float2half_rn(y);
    __half lx = __float2half_rn(x - __half2float(hx));
    __half ly = __float2half_rn(y - __half2float(hy));
    __half2 th(hx, hy), tl(lx, ly);
    hi = *(uint32_t*)&th;
    lo = *(uint32_t*)&tl;
}

__device__ __forceinline__ uint32_t pack_h2(float x, float y) {
    __half2 t(__float2half_rn(x), __float2half_rn(y));
    return *(uint32_t*)&t;
}

// ---------------------------------------------------------------------------
// fp32 -> fp16 conversion, one launch: 4 weights + 4 x-slices, all hi-only.
// ---------------------------------------------------------------------------
__global__ __launch_bounds__(256)
void cvt_all(const float* __restrict__ x,
             const float* __restrict__ w0, const float* __restrict__ w1,
             const float* __restrict__ w2, const float* __restrict__ w3,
             __half* __restrict__ xhi, __half* __restrict__ whi)
{
    const int y = blockIdx.y;
    const size_t WSZ4 = (size_t)D_MODEL * D_MODEL / 4;
    int i = blockIdx.x * 256 + threadIdx.x;
    const float* src;
    __half* hi;
    if (y < 4) {
        src = (y == 0) ? w0 : (y == 1) ? w1 : (y == 2) ? w2 : w3;
        hi = whi + (size_t)y * D_MODEL * D_MODEL;
    } else {
        src = x + (size_t)(y - 4) * WSZ4 * 4;
        hi = xhi + (size_t)(y - 4) * WSZ4 * 4;
    }
    float4 v = ((const float4*)src)[i];
    ((uint32_t*)hi)[2 * i]     = pack_h2(v.x, v.y);
    ((uint32_t*)hi)[2 * i + 1] = pack_h2(v.z, v.w);
}

// ---------------------------------------------------------------------------
// GEMM core — pure fp16 1-pass: C = A * B  (R17)
// CTA tile 128x256, 8 warps (2x4), warp tile 64x64, KC=64, double buffering.
// smem/chunk: A 16K + B 32K = 48K; x2 buffers = 96K.
// ---------------------------------------------------------------------------
#define KC        64
#define NCHUNK    (D_MODEL / KC)      // 16
#define TILE_A    16384               // 128 rows x 128 B
#define TILE_BB   32768               // 256 rows x 128 B
#define BUF_B     (TILE_A + TILE_BB)  // 49152
#define GEMM_SMEM (2 * BUF_B)         // 98304

__device__ __forceinline__ void cp_tileA(uint32_t dst_base, const __half* src, int tid)
{
#pragma unroll
    for (int u = tid; u < 1024; u += 256) {
        int row = u >> 3, c = u & 7;
        uint32_t off = row * 128 + c * 16;
        CP_ASYNC16(dst_base + SW128(off), src + (size_t)row * D_MODEL + c * 8);
    }
}

__device__ __forceinline__ void cp_tileB(uint32_t dst_base, const __half* src, int tid)
{
#pragma unroll
    for (int u = tid; u < 2048; u += 256) {
        int row = u >> 3, c = u & 7;
        uint32_t off = row * 128 + c * 16;
        CP_ASYNC16(dst_base + SW128(off), src + (size_t)row * D_MODEL + c * 8);
    }
}

__device__ __forceinline__ void gemm_mainloop(
    uint32_t sbase, int tid, int lane, int m0, int n0,
    const __half* pA, const __half* pB,
    float acc[4][8][4])
{
#pragma unroll
    for (int i = 0; i < 4; i++)
#pragma unroll
        for (int j = 0; j < 8; j++)
#pragma unroll
            for (int r = 0; r < 4; r++) acc[i][j][r] = 0.f;

    const int ra = lane & 15;
    const int ca = lane >> 4;
    const int qb = lane >> 3;
    const int l7 = lane & 7;

    cp_tileA(sbase, pA, tid);
    cp_tileB(sbase + TILE_A, pB, tid);
    CP_COMMIT();

    for (int ch = 0; ch < NCHUNK; ch++) {
        const int buf = ch & 1;
        if (ch + 1 < NCHUNK) {
            const uint32_t nb = sbase + (buf ^ 1) * BUF_B;
            const int kc = (ch + 1) * KC;
            cp_tileA(nb, pA + kc, tid);
            cp_tileB(nb + TILE_A, pB + kc, tid);
            CP_COMMIT();
            CP_WAIT(1);
        } else {
            CP_WAIT(0);
        }
        __syncthreads();

        const uint32_t aS = sbase + buf * BUF_B;
        const uint32_t bS = aS + TILE_A;

#pragma unroll
        for (int ks = 0; ks < 4; ks++) {
            uint32_t ah[16];
#pragma unroll
            for (int i = 0; i < 4; i++) {
                uint32_t off = (uint32_t)(m0 + i * 16 + ra) * 128 + (ks * 2 + ca) * 16;
                uint32_t sw = SW128(off);
                LDSM_X4(ah[4 * i], ah[4 * i + 1], ah[4 * i + 2], ah[4 * i + 3], aS + sw);
            }
            uint32_t bh[16];
#pragma unroll
            for (int jj = 0; jj < 4; jj++) {
                uint32_t off = (uint32_t)((n0 + (jj * 2 + (qb >> 1)) * 8 + l7) * 128
                                          + (ks * 2 + (qb & 1)) * 16);
                uint32_t sw = SW128(off);
                LDSM_X4(bh[4 * jj], bh[4 * jj + 1], bh[4 * jj + 2], bh[4 * jj + 3], bS + sw);
            }
#pragma unroll
            for (int i = 0; i < 4; i++)
#pragma unroll
                for (int j = 0; j < 8; j++)
                    MMA_F16(acc[i][j], &ah[4 * i], &bh[2 * j]);
        }
        __syncthreads();
    }
}

// ---------------------------------------------------------------------------
// QKV projections, one launch (grid.z = 0:Q, 1:K, 2:V). CTA tile 128x256.
// Epilogue writes attention-ready fp16 layouts (Q hi/lo, K hi, V hi/lo).
// ---------------------------------------------------------------------------
__global__ __launch_bounds__(256, 1)
void gemm_qkv(const __half* __restrict__ A, const __half* __restrict__ Whi,
              __half* __restrict__ qh, __half* __restrict__ ql,
              __half* __restrict__ kh,
              __half* __restrict__ vth, __half* __restrict__ vtl)
{
    extern __shared__ char smem[];
    const uint32_t sbase = smem_to_u32(smem);
    const int tid = threadIdx.x;
    const int wid = tid >> 5, lane = tid & 31;
    const int bm = blockIdx.y * 128;
    const int bn = blockIdx.x * 256;
    const int z  = blockIdx.z;
    const int m0 = (wid & 1) * 64;
    const int n0 = (wid >> 1) * 64;

    float acc[4][8][4];
    gemm_mainloop(sbase, tid, lane, m0, n0,
                  A + (size_t)bm * D_MODEL,
                  Whi + (size_t)z * D_MODEL * D_MODEL + (size_t)bn * D_MODEL,
                  acc);

    const int g = lane >> 2, t = lane & 3;

    if (z == 2) {
#pragma unroll
        for (int i = 0; i < 4; i++) {
#pragma unroll
            for (int j = 0; j < 8; j++) {
                const int c  = bn + n0 + j * 8 + 2 * t;
                const int hh = c >> 6, d0 = c & 63;
#pragma unroll
                for (int rr = 0; rr < 4; rr++) {
                    const int row = bm + m0 + i * 16 + g + ((rr >> 1) * 8);
                    const int b = row >> 11, s = row & (SEQ - 1);
                    const int d = d0 + (rr & 1);
                    float v = acc[i][j][rr];
                    __half hv = __float2half_rn(v);
                    __half lv = __float2half_rn(v - __half2float(hv));
                    const size_t dst = ((size_t)((b * NHEAD + hh) * DK + d)) * SEQ + s;
                    vth[dst] = hv;
                    vtl[dst] = lv;
                }
            }
        }
    } else if (z == 0) {
#pragma unroll
        for (int i = 0; i < 4; i++) {
#pragma unroll
            for (int j = 0; j < 8; j++) {
                const int c  = bn + n0 + j * 8 + 2 * t;
                const int hh = c >> 6, d = c & 63;
                const int row0 = bm + m0 + i * 16 + g;
                uint32_t hv, lv;
                {
                    const int b = row0 >> 11, s = row0 & (SEQ - 1);
                    split2h(acc[i][j][0] * 0.125f, acc[i][j][1] * 0.125f, hv, lv);
                    const size_t dst = ((size_t)((b * NHEAD + hh) * SEQ + s)) * DK + d;
                    *(uint32_t*)(qh + dst) = hv;
                    *(uint32_t*)(ql + dst) = lv;
                }
                {
                    const int row1 = row0 + 8;
                    const int b = row1 >> 11, s = row1 & (SEQ - 1);
                    split2h(acc[i][j][2] * 0.125f, acc[i][j][3] * 0.125f, hv, lv);
                    const size_t dst = ((size_t)((b * NHEAD + hh) * SEQ + s)) * DK + d;
                    *(uint32_t*)(qh + dst) = hv;
                    *(uint32_t*)(ql + dst) = lv;
                }
            }
        }
    } else {
#pragma unroll
        for (int i = 0; i < 4; i++) {
#pragma unroll
            for (int j = 0; j < 8; j++) {
                const int c  = bn + n0 + j * 8 + 2 * t;
                const int hh = c >> 6, d = c & 63;
                const int row0 = bm + m0 + i * 16 + g;
                {
                    const int b = row0 >> 11, s = row0 & (SEQ - 1);
                    const size_t dst = ((size_t)((b * NHEAD + hh) * SEQ + s)) * DK + d;
                    *(uint32_t*)(kh + dst) = pack_h2(acc[i][j][0], acc[i][j][1]);
                }
                {
                    const int row1 = row0 + 8;
                    const int b = row1 >> 11, s = row1 & (SEQ - 1);
                    const size_t dst = ((size_t)((b * NHEAD + hh) * SEQ + s)) * DK + d;
                    *(uint32_t*)(kh + dst) = pack_h2(acc[i][j][2], acc[i][j][3]);
                }
            }
        }
    }
}

// ---------------------------------------------------------------------------
// Output projection GEMM (fp32 result to d_out). CTA tile 128x256.
// ---------------------------------------------------------------------------
__global__ __launch_bounds__(256, 1)
void gemm_mma(const __half* __restrict__ A, const __half* __restrict__ B,
              float* __restrict__ C)
{
    extern __shared__ char smem[];
    const uint32_t sbase = smem_to_u32(smem);
    const int tid = threadIdx.x;
    const int wid = tid >> 5, lane = tid & 31;
    const int bm = blockIdx.y * 128;
    const int bn = blockIdx.x * 256;
    const int m0 = (wid & 1) * 64;
    const int n0 = (wid >> 1) * 64;

    float acc[4][8][4];
    gemm_mainloop(sbase, tid, lane, m0, n0,
                  A + (size_t)bm * D_MODEL,
                  B + (size_t)bn * D_MODEL,
                  acc);

    const int g = lane >> 2, t = lane & 3;
#pragma unroll
    for (int i = 0; i < 4; i++) {
#pragma unroll
        for (int j = 0; j < 8; j++) {
            float* cp0 = C + (size_t)(bm + m0 + i * 16 + g) * D_MODEL + bn + n0 + j * 8 + 2 * t;
            float* cp1 = cp0 + 8 * D_MODEL;
            *(float2*)cp0 = make_float2(acc[i][j][0], acc[i][j][1]);
            *(float2*)cp1 = make_float2(acc[i][j][2], acc[i][j][3]);
        }
    }
}

// ---------------------------------------------------------------------------
// Tensor-core causal flash attention — fp16 2-pass, double-buffered KV,
// up to 3 CTAs/SM (validated R15/R16). Output written as plain fp16.
// ---------------------------------------------------------------------------
#define ATT_NT    128
#define KV_B      24576
#define ATT_SMEM  (16384 + 2 * KV_B)   // 65536

__global__ __launch_bounds__(ATT_NT, 3)
void attn_mma(const __half* __restrict__ Qh, const __half* __restrict__ Ql,
              const __half* __restrict__ Kh,
              const __half* __restrict__ Vh, const __half* __restrict__ Vl,
              __half* __restrict__ Ohi)
{
    extern __shared__ char smem[];
    const uint32_t sb = smem_to_u32(smem);
    const int tid = threadIdx.x, wid = tid >> 5, lane = tid & 31;
    const int qblk = gridDim.x - 1 - blockIdx.x;   // heavy CTAs first
    const int bh = blockIdx.y;
    const int b = bh >> 4, h = bh & 15;
    const int qr0 = qblk * 64 + wid * 16;
    const int g = lane >> 2, t = lane & 3;
    const int qb2 = lane >> 3, l7 = lane & 7;
    const int ra = lane & 15, ca = lane >> 4;

    const uint32_t QH = sb, QL = sb + 8192;
    const uint32_t KVB = sb + 16384;   // per buffer: KH +0, VH +8192, VL +16384

    const int nkb = qblk + 1;

    auto load_kv = [&](uint32_t dbuf, int k0) {
#pragma unroll
        for (int u = tid; u < 512; u += ATT_NT) {
            int r = u >> 3, c = u & 7;
            uint32_t sw = SW128((uint32_t)(r * 128 + c * 16));
            const size_t kg = ((size_t)bh * SEQ + k0 + r) * DK + c * 8;
            CP_ASYNC16(dbuf + sw, Kh + kg);
            const size_t vg = ((size_t)bh * DK + r) * SEQ + k0 + c * 8;
            CP_ASYNC16(dbuf + 8192 + sw,  Vh + vg);
            CP_ASYNC16(dbuf + 16384 + sw, Vl + vg);
        }
    };

    {
        const __half* qh_g = Qh + ((size_t)bh * SEQ + qblk * 64) * DK;
        const __half* ql_g = Ql + ((size_t)bh * SEQ + qblk * 64) * DK;
#pragma unroll
        for (int u = tid; u < 512; u += ATT_NT) {
            int row = u >> 3, c = u & 7;
            uint32_t sw = SW128((uint32_t)(row * 128 + c * 16));
            CP_ASYNC16(QH + sw, qh_g + (size_t)row * DK + c * 8);
            CP_ASYNC16(QL + sw, ql_g + (size_t)row * DK + c * 8);
        }
        CP_COMMIT();
    }
    load_kv(KVB, 0);
    CP_COMMIT();
    CP_WAIT(1);
    __syncthreads();

    uint32_t qhf[16], qlf[16];
#pragma unroll
    for (int ks = 0; ks < 4; ks++) {
        uint32_t sw = SW128((uint32_t)((wid * 16 + ra) * 128 + (ks * 2 + ca) * 16));
        LDSM_X4(qhf[4 * ks], qhf[4 * ks + 1], qhf[4 * ks + 2], qhf[4 * ks + 3], QH + sw);
        LDSM_X4(qlf[4 * ks], qlf[4 * ks + 1], qlf[4 * ks + 2], qlf[4 * ks + 3], QL + sw);
    }

    float o[8][4];
#pragma unroll
    for (int j = 0; j < 8; j++)
#pragma unroll
        for (int r = 0; r < 4; r++) o[j][r] = 0.f;
    float m0 = NEG_INF, m1 = NEG_INF, l0 = 0.f, l1 = 0.f;

    for (int kb = 0; kb < nkb; kb++) {
        const int buf = kb & 1;
        const int k0 = kb * 64;

        if (kb + 1 < nkb) {
            load_kv(KVB + (buf ^ 1) * KV_B, (kb + 1) * 64);
            CP_COMMIT();
            CP_WAIT(1);
        } else {
            CP_WAIT(0);
        }
        __syncthreads();

        const uint32_t KHs = KVB + buf * KV_B;
        const uint32_t VHs = KHs + 8192;
        const uint32_t VLs = KHs + 16384;

        float sf[8][4];
#pragma unroll
        for (int j = 0; j < 8; j++)
#pragma unroll
            for (int r = 0; r < 4; r++) sf[j][r] = 0.f;

#pragma unroll
        for (int ks = 0; ks < 4; ks++) {
            uint32_t bhf[16];
#pragma unroll
            for (int jj = 0; jj < 4; jj++) {
                uint32_t sw = SW128((uint32_t)(((jj * 2 + (qb2 >> 1)) * 8 + l7) * 128
                                               + (ks * 2 + (qb2 & 1)) * 16));
                LDSM_X4(bhf[4 * jj], bhf[4 * jj + 1], bhf[4 * jj + 2], bhf[4 * jj + 3], KHs + sw);
            }
#pragma unroll
            for (int j = 0; j < 8; j++) {
                MMA_F16(sf[j], &qhf[4 * ks], &bhf[2 * j]);
                MMA_F16(sf[j], &qlf[4 * ks], &bhf[2 * j]);
            }
        }

        if (k0 + 63 > qr0) {
            const int row0 = qr0 + g, row1 = row0 + 8;
#pragma unroll
            for (int j = 0; j < 8; j++) {
                const int key = k0 + 8 * j + 2 * t;
                if (key     > row0) sf[j][0] = NEG_INF;
                if (key + 1 > row0) sf[j][1] = NEG_INF;
                if (key     > row1) sf[j][2] = NEG_INF;
                if (key + 1 > row1) sf[j][3] = NEG_INF;
            }
        }

        float mx0 = NEG_INF, mx1 = NEG_INF;
#pragma unroll
        for (int j = 0; j < 8; j++) {
            mx0 = fmaxf(mx0, fmaxf(sf[j][0], sf[j][1]));
            mx1 = fmaxf(mx1, fmaxf(sf[j][2], sf[j][3]));
        }
        mx0 = fmaxf(mx0, __shfl_xor_sync(0xffffffffu, mx0, 1));
        mx0 = fmaxf(mx0, __shfl_xor_sync(0xffffffffu, mx0, 2));
        mx1 = fmaxf(mx1, __shfl_xor_sync(0xffffffffu, mx1, 1));
        mx1 = fmaxf(mx1, __shfl_xor_sync(0xffffffffu, mx1, 2));
        const float mn0 = fmaxf(m0, mx0), mn1 = fmaxf(m1, mx1);
        const float a0 = __expf(m0 - mn0), a1 = __expf(m1 - mn1);
        m0 = mn0; m1 = mn1;

        float rs0 = 0.f, rs1 = 0.f;
        uint32_t ph[16];
#pragma unroll
        for (int j = 0; j < 8; j++) {
            float p0 = __expf(sf[j][0] - mn0);
            float p1 = __expf(sf[j][1] - mn0);
            float p2 = __expf(sf[j][2] - mn1);
            float p3 = __expf(sf[j][3] - mn1);
            rs0 += p0 + p1;
            rs1 += p2 + p3;
            const int ks2 = j >> 1, hf = j & 1;
            ph[4 * ks2 + 2 * hf]     = pack_h2(p0, p1);
            ph[4 * ks2 + 2 * hf + 1] = pack_h2(p2, p3);
        }
        rs0 += __shfl_xor_sync(0xffffffffu, rs0, 1);
        rs0 += __shfl_xor_sync(0xffffffffu, rs0, 2);
        rs1 += __shfl_xor_sync(0xffffffffu, rs1, 1);
        rs1 += __shfl_xor_sync(0xffffffffu, rs1, 2);
        l0 = l0 * a0 + rs0;
        l1 = l1 * a1 + rs1;

#pragma unroll
        for (int j = 0; j < 8; j++) {
            o[j][0] *= a0; o[j][1] *= a0;
            o[j][2] *= a1; o[j][3] *= a1;
        }

#pragma unroll
        for (int ks = 0; ks < 4; ks++) {
            uint32_t vhf[16], vlf[16];
#pragma unroll
            for (int jj = 0; jj < 4; jj++) {
                uint32_t sw = SW128((uint32_t)(((jj * 2 + (qb2 >> 1)) * 8 + l7) * 128
                                               + (ks * 2 + (qb2 & 1)) * 16));
                LDSM_X4(vhf[4 * jj], vhf[4 * jj + 1], vhf[4 * jj + 2], vhf[4 * jj + 3], VHs + sw);
                LDSM_X4(vlf[4 * jj], vlf[4 * jj + 1], vlf[4 * jj + 2], vlf[4 * jj + 3], VLs + sw);
            }
#pragma unroll
            for (int j = 0; j < 8; j++) {
                MMA_F16(o[j], &ph[4 * ks], &vhf[2 * j]);
                MMA_F16(o[j], &ph[4 * ks], &vlf[2 * j]);
            }
        }

        __syncthreads();
    }

    const float il0 = 1.f / l0, il1 = 1.f / l1;
    const size_t r0 = (size_t)(b * SEQ + qr0 + g) * D_MODEL + h * DK;
    const size_t r1 = r0 + (size_t)8 * D_MODEL;
#pragma unroll
    for (int j = 0; j < 8; j++) {
        const int c = 8 * j + 2 * t;
        *(uint32_t*)(Ohi + r0 + c) = pack_h2(o[j][0] * il0, o[j][1] * il0);
        *(uint32_t*)(Ohi + r1 + c) = pack_h2(o[j][2] * il1, o[j][3] * il1);
    }
}

// ---------------------------------------------------------------------------
extern "C" void kernel_launch(void* const* d_in, const int* in_sizes, int n_in,
                              void* d_out, int out_size)
{
    (void)in_sizes; (void)n_in; (void)out_size;
    const float* x  = (const float*)d_in[0];
    const float* Wq = (const float*)d_in[1];
    const float* Wk = (const float*)d_in[2];
    const float* Wv = (const float*)d_in[3];
    const float* Wo = (const float*)d_in[4];
    float* out = (float*)d_out;

    __half *xhi, *ohi, *whi;
    cudaGetSymbolAddress((void**)&xhi, g_x_hi);
    cudaGetSymbolAddress((void**)&ohi, g_o_hi);
    cudaGetSymbolAddress((void**)&whi, g_w_hi);
    __half *qh, *ql, *kh, *vth, *vtl;
    cudaGetSymbolAddress((void**)&qh,  g_qh);
    cudaGetSymbolAddress((void**)&ql,  g_ql);
    cudaGetSymbolAddress((void**)&kh,  g_kh);
    cudaGetSymbolAddress((void**)&vth, g_vth);
    cudaGetSymbolAddress((void**)&vtl, g_vtl);

    cudaFuncSetAttribute(gemm_qkv, cudaFuncAttributeMaxDynamicSharedMemorySize, GEMM_SMEM);
    cudaFuncSetAttribute(gemm_mma, cudaFuncAttributeMaxDynamicSharedMemorySize, GEMM_SMEM);
    cudaFuncSetAttribute(attn_mma, cudaFuncAttributeMaxDynamicSharedMemorySize, ATT_SMEM);

    const int NW4 = D_MODEL * D_MODEL / 4;   // 262,144
    const int WSZ = D_MODEL * D_MODEL;

    cvt_all<<<dim3(NW4 / 256, 8), 256>>>(x, Wq, Wk, Wv, Wo, xhi, whi);

    gemm_qkv<<<dim3(D_MODEL / 256, MTOT / 128, 3), 256, GEMM_SMEM>>>(
        xhi, whi, qh, ql, kh, vth, vtl);

    attn_mma<<<dim3(SEQ / 64, BH), ATT_NT, ATT_SMEM>>>(qh, ql, kh, vth, vtl, ohi);

    gemm_mma<<<dim3(D_MODEL / 256, MTOT / 128), 256, GEMM_SMEM>>>(
        ohi, whi + 3 * WSZ, out);
}